// round 3
// baseline (speedup 1.0000x reference)
#include <cuda_runtime.h>
#include <cuda_bf16.h>
#include <math.h>

#define NN 20000
#define NE 320000
#define NHEADS 4
#define NREL 40
#define FIN 768
#define HID 128
#define NCLS 9

// ---------------- scratch (static device globals; no allocs allowed) -------
__device__ __align__(16) float g_h[NN * NHEADS * HID];     // GEMM out [N,H,O]
__device__ __align__(16) float g_tmp[NN * NHEADS * HID];   // agg out  [N,H,O]
__device__ __align__(16) float g_x[NN * HID];              // running x
__device__ __align__(16) float g_hin[NN * HID];            // bn/lrelu output (residual)
__device__ __align__(16) float g_es[NN * NHEADS];
__device__ __align__(16) float g_ed[NN * NHEADS];
__device__ __align__(16) float g_eetab[NREL * NHEADS];
__device__ __align__(16) float g_W[FIN * NHEADS * HID];    // reordered weights [F, H*O]
__device__ int g_cnt[NN];
__device__ int g_rowptr[NN + 1];
__device__ int g_fill[NN];
__device__ int g_eids[NE];
__device__ float g_bsum[HID];
__device__ float g_bsq[HID];

__device__ __forceinline__ int clampi(int v, int lo, int hi) {
    return v < lo ? lo : (v > hi ? hi : v);
}

// ---------------- CSR build ------------------------------------------------
__global__ void zero_i_k(int* p, int n) {
    int i = blockIdx.x * blockDim.x + threadIdx.x;
    if (i < n) p[i] = 0;
}

__global__ void count_k(const int* __restrict__ dst, int* __restrict__ cnt) {
    int e = blockIdx.x * blockDim.x + threadIdx.x;
    if (e < NE) atomicAdd(&cnt[clampi(dst[e], 0, NN - 1)], 1);
}

__global__ void scan_k(const int* __restrict__ cnt, int* __restrict__ rowptr,
                       int* __restrict__ fill) {
    __shared__ int sh[1024];
    int tid = threadIdx.x;
    int carry = 0;
    if (tid == 0) rowptr[0] = 0;
    for (int base = 0; base < NN; base += 1024) {
        int i = base + tid;
        int v = (i < NN) ? cnt[i] : 0;
        sh[tid] = v;
        __syncthreads();
        for (int off = 1; off < 1024; off <<= 1) {
            int t = (tid >= off) ? sh[tid - off] : 0;
            __syncthreads();
            sh[tid] += t;
            __syncthreads();
        }
        int incl = sh[tid];
        if (i < NN) {
            rowptr[i + 1] = carry + incl;
            fill[i] = carry + incl - v;
        }
        carry += sh[1023];
        __syncthreads();
    }
}

__global__ void scatter_k(const int* __restrict__ dst, int* __restrict__ fill,
                          int* __restrict__ eids) {
    int e = blockIdx.x * blockDim.x + threadIdx.x;
    if (e < NE) {
        int d = clampi(dst[e], 0, NN - 1);
        int pos = atomicAdd(&fill[d], 1);
        if (pos >= 0 && pos < NE) eids[pos] = e;
    }
}

// ---------------- weight reorder [H,F,O] -> [F, H*O] -----------------------
__global__ void reorder_k(const float* __restrict__ W, float* __restrict__ out,
                          int K, int O) {
    int idx = blockIdx.x * blockDim.x + threadIdx.x;
    int tot = NHEADS * K * O;
    if (idx >= tot) return;
    int o = idx % O;
    int f = (idx / O) % K;
    int h = idx / (O * K);
    out[f * (NHEADS * O) + h * O + o] = W[idx];
}

// ---------------- SGEMM 128x128x8, 8x8 per thread --------------------------
#define BM 128
#define BN 128
#define BK 8
__global__ __launch_bounds__(256)
void sgemm_k(const float* __restrict__ A, const float* __restrict__ B,
             float* __restrict__ C, int M, int N, int K) {
    __shared__ float As[BK][BM];
    __shared__ float Bs[BK][BN];
    int tid = threadIdx.x;
    int row0 = blockIdx.y * BM;
    int col0 = blockIdx.x * BN;

    int aRow = tid >> 1;            // 0..127
    int aCol = (tid & 1) * 4;       // 0 or 4
    int bRow = tid >> 5;            // 0..7
    int bCol = (tid & 31) * 4;      // 0..124

    int ty = tid >> 4;              // 0..15
    int tx = tid & 15;              // 0..15

    float acc[8][8];
#pragma unroll
    for (int i = 0; i < 8; i++)
#pragma unroll
        for (int j = 0; j < 8; j++) acc[i][j] = 0.f;

    for (int k0 = 0; k0 < K; k0 += BK) {
        float4 av = make_float4(0.f, 0.f, 0.f, 0.f);
        int gr = row0 + aRow;
        if (gr < M) av = *(const float4*)(A + (size_t)gr * K + k0 + aCol);
        As[aCol + 0][aRow] = av.x;
        As[aCol + 1][aRow] = av.y;
        As[aCol + 2][aRow] = av.z;
        As[aCol + 3][aRow] = av.w;

        float4 bv = make_float4(0.f, 0.f, 0.f, 0.f);
        int gc = col0 + bCol;
        if (gc + 3 < N) bv = *(const float4*)(B + (size_t)(k0 + bRow) * N + gc);
        Bs[bRow][bCol + 0] = bv.x;
        Bs[bRow][bCol + 1] = bv.y;
        Bs[bRow][bCol + 2] = bv.z;
        Bs[bRow][bCol + 3] = bv.w;
        __syncthreads();

#pragma unroll
        for (int k = 0; k < BK; k++) {
            float ra[8], rb[8];
#pragma unroll
            for (int i = 0; i < 8; i++) ra[i] = As[k][ty * 8 + i];
#pragma unroll
            for (int j = 0; j < 8; j++) rb[j] = Bs[k][tx * 8 + j];
#pragma unroll
            for (int i = 0; i < 8; i++)
#pragma unroll
                for (int j = 0; j < 8; j++) acc[i][j] += ra[i] * rb[j];
        }
        __syncthreads();
    }

#pragma unroll
    for (int i = 0; i < 8; i++) {
        int r = row0 + ty * 8 + i;
        if (r >= M) continue;
#pragma unroll
        for (int j = 0; j < 8; j++) {
            int c = col0 + tx * 8 + j;
            if (c < N) C[(size_t)r * N + c] = acc[i][j];
        }
    }
}

// ---------------- es/ed per (node, head) -----------------------------------
template <int O>
__global__ void esed_k(const float* __restrict__ h, const float* __restrict__ a_s,
                       const float* __restrict__ a_d, float* __restrict__ es,
                       float* __restrict__ ed) {
    int w = (blockIdx.x * blockDim.x + threadIdx.x) >> 5;
    int lane = threadIdx.x & 31;
    if (w >= NN * NHEADS) return;
    int hd = w % NHEADS;
    const float* hp = h + (size_t)w * O;
    float s = 0.f, d = 0.f;
    for (int k = lane; k < O; k += 32) {
        float v = hp[k];
        s += v * a_s[hd * O + k];
        d += v * a_d[hd * O + k];
    }
#pragma unroll
    for (int off = 16; off; off >>= 1) {
        s += __shfl_xor_sync(0xffffffffu, s, off);
        d += __shfl_xor_sync(0xffffffffu, d, off);
    }
    if (lane == 0) { es[w] = s; ed[w] = d; }
}

__global__ void eetab_k(const float* __restrict__ rel, const float* __restrict__ ae,
                        float* __restrict__ tab) {
    int i = threadIdx.x;
    if (i < NREL * NHEADS) {
        int r = i >> 2, hd = i & 3;
        tab[i] = rel[r * 2] * ae[hd * 2] + rel[r * 2 + 1] * ae[hd * 2 + 1];
    }
}

// ---------------- attention aggregation: warp per (node, head) -------------
__device__ __forceinline__ float lrelu02(float v) { return v > 0.f ? v : 0.2f * v; }

template <int O>
__global__ void agg_k(const float* __restrict__ h, const float* __restrict__ es,
                      const float* __restrict__ ed, const float* __restrict__ eetab,
                      const int* __restrict__ src,
                      const int* __restrict__ etype,
                      const int* __restrict__ edist,
                      const int* __restrict__ rowptr, const int* __restrict__ eids,
                      float* __restrict__ out) {
    int w = (blockIdx.x * blockDim.x + threadIdx.x) >> 5;
    int lane = threadIdx.x & 31;
    if (w >= NN * NHEADS) return;
    int n = w / NHEADS;
    int hd = w % NHEADS;
    int beg = rowptr[n], end = rowptr[n + 1];
    float edn = ed[n * NHEADS + hd];

    // pass 1: segment max (lane strided)
    float m = -3.4e38f;
    for (int i = beg + lane; i < end; i += 32) {
        int e = eids[i];
        int s = clampi(src[e], 0, NN - 1);
        int t = clampi(etype[e], 0, NREL - 1);
        float lg = lrelu02(es[s * NHEADS + hd] + edn + eetab[t * NHEADS + hd]);
        m = fmaxf(m, lg);
    }
#pragma unroll
    for (int off = 16; off; off >>= 1) m = fmaxf(m, __shfl_xor_sync(0xffffffffu, m, off));

    // pass 2: den + weighted gather
    const int ACCN = (O + 31) / 32;
    float acc[(O + 31) / 32];
#pragma unroll
    for (int k = 0; k < ACCN; k++) acc[k] = 0.f;
    float den = 0.f;

    for (int i = beg; i < end; i++) {
        int e = eids[i];
        int s = clampi(src[e], 0, NN - 1);
        int t = clampi(etype[e], 0, NREL - 1);
        float lg = lrelu02(es[s * NHEADS + hd] + edn + eetab[t * NHEADS + hd]);
        float ex = __expf(lg - m);
        den += ex;
        float wgt = ex / (1.0f + (float)edist[e]);
        const float* hs = h + ((size_t)s * NHEADS + hd) * O;
#pragma unroll
        for (int k = 0; k < ACCN; k++) {
            int o = lane + 32 * k;
            if (o < O) acc[k] += wgt * hs[o];
        }
    }
    float inv = 1.0f / (den + 1e-16f);
    float* op = out + ((size_t)n * NHEADS + hd) * O;
#pragma unroll
    for (int k = 0; k < ACCN; k++) {
        int o = lane + 32 * k;
        if (o < O) op[o] = acc[k] * inv;
    }
}

// ---------------- combine (mean over heads + bias [+ residual]) ------------
__global__ void combine128_k(const float* __restrict__ tmp, const float* __restrict__ b,
                             const float* __restrict__ resid, float* __restrict__ out) {
    int i = blockIdx.x * blockDim.x + threadIdx.x;
    if (i >= NN * HID) return;
    int n = i >> 7, o = i & 127;
    const float* t = tmp + (size_t)n * NHEADS * HID + o;
    float v = 0.25f * (t[0] + t[HID] + t[2 * HID] + t[3 * HID]) + b[o];
    if (resid) v += resid[i];
    out[i] = v;
}

__global__ void combine9_k(const float* __restrict__ tmp, const float* __restrict__ b,
                           float* __restrict__ out) {
    int i = blockIdx.x * blockDim.x + threadIdx.x;
    if (i >= NN * NCLS) return;
    int n = i / NCLS, c = i % NCLS;
    const float* t = tmp + (size_t)n * NHEADS * NCLS + c;
    float v = 0.25f * (t[0] + t[NCLS] + t[2 * NCLS] + t[3 * NCLS]) + b[c];
    out[i] = v > 0.f ? v : 0.1f * v;
}

// ---------------- batch norm -----------------------------------------------
__global__ void bn_zero_k(float* s, float* q) {
    int t = threadIdx.x;
    if (t < HID) { s[t] = 0.f; q[t] = 0.f; }
}

__global__ void bn_stats_k(const float* __restrict__ x, float* __restrict__ sum,
                           float* __restrict__ sumsq) {
    int t = threadIdx.x;  // 0..127
    int rows_per = (NN + gridDim.x - 1) / gridDim.x;
    int r0 = blockIdx.x * rows_per;
    int r1 = min(r0 + rows_per, NN);
    float s = 0.f, q = 0.f;
    for (int r = r0; r < r1; r++) {
        float v = x[(size_t)r * HID + t];
        s += v;
        q += v * v;
    }
    atomicAdd(&sum[t], s);
    atomicAdd(&sumsq[t], q);
}

__global__ void bn_apply_k(const float* __restrict__ x, const float* __restrict__ sum,
                           const float* __restrict__ sumsq, const float* __restrict__ g,
                           const float* __restrict__ b, float* __restrict__ out) {
    int i = blockIdx.x * blockDim.x + threadIdx.x;
    if (i >= NN * HID) return;
    int o = i & 127;
    float mu = sum[o] * (1.0f / NN);
    float var = sumsq[o] * (1.0f / NN) - mu * mu;
    float v = (x[i] - mu) * rsqrtf(var + 1e-5f) * g[o] + b[o];
    out[i] = v > 0.f ? v : 0.1f * v;
}

// ---------------- host orchestration ---------------------------------------
static void run_conv(const float* X, int K, int O, const float* W,
                     const float* a_s, const float* a_d, const float* a_e,
                     const float* rel, const int* src, const int* etype,
                     const int* edist, float* h_buf, float* tmp_buf, float* es,
                     float* ed, float* eetab, int* rowptr, int* eids, float* Wb) {
    int tot = NHEADS * K * O;
    reorder_k<<<(tot + 255) / 256, 256>>>(W, Wb, K, O);
    int Ncols = NHEADS * O;
    dim3 grid((Ncols + BN - 1) / BN, (NN + BM - 1) / BM);
    sgemm_k<<<grid, 256>>>(X, Wb, h_buf, NN, Ncols, K);
    int warps = NN * NHEADS;
    int blocks = (warps * 32 + 255) / 256;
    if (O == HID)
        esed_k<HID><<<blocks, 256>>>(h_buf, a_s, a_d, es, ed);
    else
        esed_k<NCLS><<<blocks, 256>>>(h_buf, a_s, a_d, es, ed);
    eetab_k<<<1, 256>>>(rel, a_e, eetab);
    if (O == HID)
        agg_k<HID><<<blocks, 256>>>(h_buf, es, ed, eetab, src, etype, edist, rowptr,
                                    eids, tmp_buf);
    else
        agg_k<NCLS><<<blocks, 256>>>(h_buf, es, ed, eetab, src, etype, edist, rowptr,
                                     eids, tmp_buf);
}

extern "C" void kernel_launch(void* const* d_in, const int* in_sizes, int n_in,
                              void* d_out, int out_size) {
    const float* x = (const float*)d_in[0];
    const int* ei = (const int*)d_in[1];       // int32! (JAX x64 disabled)
    const int* etype = (const int*)d_in[2];    // int32!
    const int* edist = (const int*)d_in[3];
    const float* W0 = (const float*)d_in[4];
    const float* asrc0 = (const float*)d_in[5];
    const float* adst0 = (const float*)d_in[6];
    const float* aedge0 = (const float*)d_in[7];
    const float* b0 = (const float*)d_in[8];
    const float* rel0 = (const float*)d_in[9];
    const float* Wm = (const float*)d_in[10];
    const float* asrcm = (const float*)d_in[11];
    const float* adstm = (const float*)d_in[12];
    const float* aedgem = (const float*)d_in[13];
    const float* bm = (const float*)d_in[14];
    const float* relm = (const float*)d_in[15];
    const float* WL = (const float*)d_in[16];
    const float* asrcL = (const float*)d_in[17];
    const float* adstL = (const float*)d_in[18];
    const float* aedgeL = (const float*)d_in[19];
    const float* bL = (const float*)d_in[20];
    const float* relL = (const float*)d_in[21];
    const float* bn_g = (const float*)d_in[22];
    const float* bn_b = (const float*)d_in[23];

    float *h_buf, *tmp, *xb, *hin, *es, *ed, *eetab, *Wb, *bsum, *bsq;
    int *cnt, *rowptr, *fill, *eids;
    cudaGetSymbolAddress((void**)&h_buf, g_h);
    cudaGetSymbolAddress((void**)&tmp, g_tmp);
    cudaGetSymbolAddress((void**)&xb, g_x);
    cudaGetSymbolAddress((void**)&hin, g_hin);
    cudaGetSymbolAddress((void**)&es, g_es);
    cudaGetSymbolAddress((void**)&ed, g_ed);
    cudaGetSymbolAddress((void**)&eetab, g_eetab);
    cudaGetSymbolAddress((void**)&Wb, g_W);
    cudaGetSymbolAddress((void**)&bsum, g_bsum);
    cudaGetSymbolAddress((void**)&bsq, g_bsq);
    cudaGetSymbolAddress((void**)&cnt, g_cnt);
    cudaGetSymbolAddress((void**)&rowptr, g_rowptr);
    cudaGetSymbolAddress((void**)&fill, g_fill);
    cudaGetSymbolAddress((void**)&eids, g_eids);

    const int* src = ei;
    const int* dst = ei + NE;

    // CSR build
    zero_i_k<<<(NN + 255) / 256, 256>>>(cnt, NN);
    count_k<<<(NE + 255) / 256, 256>>>(dst, cnt);
    scan_k<<<1, 1024>>>(cnt, rowptr, fill);
    scatter_k<<<(NE + 255) / 256, 256>>>(dst, fill, eids);

    int nb128 = (NN * HID + 255) / 256;

    // layer 0
    run_conv(x, FIN, HID, W0, asrc0, adst0, aedge0, rel0, src, etype, edist, h_buf,
             tmp, es, ed, eetab, rowptr, eids, Wb);
    combine128_k<<<nb128, 256>>>(tmp, b0, nullptr, xb);

    // middle layers
    for (int i = 0; i < 3; i++) {
        bn_zero_k<<<1, 128>>>(bsum, bsq);
        bn_stats_k<<<200, 128>>>(xb, bsum, bsq);
        bn_apply_k<<<nb128, 256>>>(xb, bsum, bsq, bn_g + i * HID, bn_b + i * HID, hin);
        run_conv(hin, HID, HID, Wm + (size_t)i * NHEADS * HID * HID,
                 asrcm + i * NHEADS * HID, adstm + i * NHEADS * HID,
                 aedgem + i * NHEADS * 2, relm + i * NREL * 2, src, etype, edist,
                 h_buf, tmp, es, ed, eetab, rowptr, eids, Wb);
        combine128_k<<<nb128, 256>>>(tmp, bm + i * HID, hin, xb);
    }

    // final layer
    bn_zero_k<<<1, 128>>>(bsum, bsq);
    bn_stats_k<<<200, 128>>>(xb, bsum, bsq);
    bn_apply_k<<<nb128, 256>>>(xb, bsum, bsq, bn_g + 3 * HID, bn_b + 3 * HID, hin);
    run_conv(hin, HID, NCLS, WL, asrcL, adstL, aedgeL, relL, src, etype, edist,
             h_buf, tmp, es, ed, eetab, rowptr, eids, Wb);
    combine9_k<<<(NN * NCLS + 255) / 256, 256>>>(tmp, bL, (float*)d_out);
}

// round 5
// speedup vs baseline: 1.0457x; 1.0457x over previous
#include <cuda_runtime.h>
#include <cuda_bf16.h>
#include <math.h>
#include <stdint.h>

#define NN 20000
#define NE 320000
#define NHEADS 4
#define NREL 40
#define FIN 768
#define HID 128
#define NCLS 9

// ---------------- scratch (static device globals; no allocs allowed) -------
__device__ __align__(16) float g_h[NN * NHEADS * HID];     // GEMM out [N, 512]
__device__ __align__(16) float g_tmp[NN * NHEADS * HID];   // agg out  [N,H,O]
__device__ __align__(16) float g_x[NN * HID];              // running x
__device__ __align__(16) float g_hin[NN * HID];            // bn/lrelu output (residual)
__device__ __align__(16) float g_es[NN * NHEADS];
__device__ __align__(16) float g_ed[NN * NHEADS];
__device__ __align__(16) float g_eetab[NREL * NHEADS];
__device__ __align__(16) float g_W[FIN * NHEADS * HID];    // reordered weights (final layer SIMT)
__device__ __align__(16) __nv_bfloat16 g_A2[NN * 2 * FIN];            // [M, 2K] hi|lo
__device__ __align__(16) __nv_bfloat16 g_B2[(NHEADS * HID) * 2 * FIN]; // [512, 2K] hi|lo
__device__ int g_cnt[NN];
__device__ int g_rowptr[NN + 1];
__device__ int g_fill[NN];
__device__ int g_eids[NE];
__device__ float g_bsum[HID];
__device__ float g_bsq[HID];

__device__ __forceinline__ int clampi(int v, int lo, int hi) {
    return v < lo ? lo : (v > hi ? hi : v);
}

__device__ __forceinline__ uint32_t smem_u32(const void* p) {
    uint32_t a;
    asm("{ .reg .u64 t; cvta.to.shared.u64 t, %1; cvt.u32.u64 %0, t; }"
        : "=r"(a) : "l"(p));
    return a;
}

__device__ __forceinline__ void ldsm_x4(uint32_t* r, uint32_t addr) {
    asm volatile("ldmatrix.sync.aligned.m8n8.x4.shared.b16 {%0,%1,%2,%3}, [%4];"
                 : "=r"(r[0]), "=r"(r[1]), "=r"(r[2]), "=r"(r[3]) : "r"(addr));
}

__device__ __forceinline__ void mma16816(float* d, const uint32_t* a, uint32_t b0,
                                         uint32_t b1) {
    asm volatile(
        "mma.sync.aligned.m16n8k16.row.col.f32.bf16.bf16.f32 "
        "{%0,%1,%2,%3}, {%4,%5,%6,%7}, {%8,%9}, {%0,%1,%2,%3};"
        : "+f"(d[0]), "+f"(d[1]), "+f"(d[2]), "+f"(d[3])
        : "r"(a[0]), "r"(a[1]), "r"(a[2]), "r"(a[3]), "r"(b0), "r"(b1));
}

// ---------------- bf16x3-split tensor-core GEMM ----------------------------
// C[M,512] = A[M,K] x Bt[512,K]^T using phases: AhBh + AhBl + AlBh
// A2: [M, 2K] (cols [0,K)=hi, [K,2K)=lo), B2: [512, 2K] same.
#define SMS 40  // smem row stride (bf16 elems); 80B -> conflict-free ldmatrix
__global__ __launch_bounds__(256)
void mma_gemm_k(const __nv_bfloat16* __restrict__ A2,
                const __nv_bfloat16* __restrict__ B2,
                float* __restrict__ C, int M, int K) {
    __shared__ __align__(16) __nv_bfloat16 Asm[128 * SMS];
    __shared__ __align__(16) __nv_bfloat16 Bsm[128 * SMS];
    int tid = threadIdx.x;
    int wid = tid >> 5;
    int lane = tid & 31;
    int warp_m = wid & 3;   // 4 warps over M (32 rows each)
    int warp_n = wid >> 2;  // 2 warps over N (64 cols each)
    int row0 = blockIdx.y * 128;
    int col0 = blockIdx.x * 128;

    float acc[2][8][4];
#pragma unroll
    for (int i = 0; i < 2; i++)
#pragma unroll
        for (int j = 0; j < 8; j++)
#pragma unroll
            for (int q = 0; q < 4; q++) acc[i][j][q] = 0.f;

    uint32_t As_base = smem_u32(Asm);
    uint32_t Bs_base = smem_u32(Bsm);
    int ksz = K / 32;
    int nst = 3 * ksz;
    int lr = tid >> 1;           // 0..127 (row for loads)
    int lq = (tid & 1) * 16;     // 0 or 16 (col chunk)

    for (int st = 0; st < nst; st++) {
        int phase = st / ksz;
        int kb = (st - phase * ksz) * 32;
        int akb = (phase == 2) ? K + kb : kb;
        int bkb = (phase == 1) ? K + kb : kb;

        // load A tile 128x32
        {
            uint4 v0 = make_uint4(0, 0, 0, 0), v1 = make_uint4(0, 0, 0, 0);
            int gr = row0 + lr;
            if (gr < M) {
                const __nv_bfloat16* p = A2 + (size_t)gr * (2 * K) + akb + lq;
                v0 = *(const uint4*)p;
                v1 = *(const uint4*)(p + 8);
            }
            __nv_bfloat16* s = Asm + lr * SMS + lq;
            *(uint4*)s = v0;
            *(uint4*)(s + 8) = v1;
        }
        // load B tile 128x32 (rows col0..col0+127 of 512; always valid)
        {
            const __nv_bfloat16* p = B2 + (size_t)(col0 + lr) * (2 * K) + bkb + lq;
            uint4 v0 = *(const uint4*)p;
            uint4 v1 = *(const uint4*)(p + 8);
            __nv_bfloat16* s = Bsm + lr * SMS + lq;
            *(uint4*)s = v0;
            *(uint4*)(s + 8) = v1;
        }
        __syncthreads();

#pragma unroll
        for (int k16 = 0; k16 < 32; k16 += 16) {
            uint32_t af[2][4];
#pragma unroll
            for (int mf = 0; mf < 2; mf++) {
                int m = warp_m * 32 + mf * 16 + (lane & 15);
                uint32_t addr = As_base + (uint32_t)((m * SMS + k16 + ((lane >> 4) << 3)) * 2);
                ldsm_x4(af[mf], addr);
            }
            uint32_t bf[4][4];
#pragma unroll
            for (int jp = 0; jp < 4; jp++) {
                int n = warp_n * 64 + jp * 16 + (lane & 15);
                uint32_t addr = Bs_base + (uint32_t)((n * SMS + k16 + ((lane >> 4) << 3)) * 2);
                ldsm_x4(bf[jp], addr);
            }
#pragma unroll
            for (int mf = 0; mf < 2; mf++)
#pragma unroll
                for (int jp = 0; jp < 4; jp++) {
                    mma16816(acc[mf][jp * 2 + 0], af[mf], bf[jp][0], bf[jp][2]);
                    mma16816(acc[mf][jp * 2 + 1], af[mf], bf[jp][1], bf[jp][3]);
                }
        }
        __syncthreads();
    }

    // epilogue
    int g = lane >> 2, t = lane & 3;
#pragma unroll
    for (int mf = 0; mf < 2; mf++) {
#pragma unroll
        for (int nf = 0; nf < 8; nf++) {
            int col = col0 + warp_n * 64 + nf * 8 + t * 2;
            int r0 = row0 + warp_m * 32 + mf * 16 + g;
            if (r0 < M) {
                float2 v = make_float2(acc[mf][nf][0], acc[mf][nf][1]);
                *(float2*)(C + (size_t)r0 * 512 + col) = v;
            }
            int r1 = r0 + 8;
            if (r1 < M) {
                float2 v = make_float2(acc[mf][nf][2], acc[mf][nf][3]);
                *(float2*)(C + (size_t)r1 * 512 + col) = v;
            }
        }
    }
}

// ---------------- fp32 -> bf16 hi/lo split ---------------------------------
__global__ void convA_k(const float* __restrict__ X, __nv_bfloat16* __restrict__ A2,
                        int M, int K) {
    int i = blockIdx.x * blockDim.x + threadIdx.x;
    if (i >= M * K) return;
    int r = i / K, k = i - r * K;
    float v = X[i];
    __nv_bfloat16 h = __float2bfloat16(v);
    __nv_bfloat16 l = __float2bfloat16(v - __bfloat162float(h));
    size_t base = (size_t)r * 2 * K;
    A2[base + k] = h;
    A2[base + K + k] = l;
}

// W [H, K, O] -> B2 [(h*O+o), 2K] hi|lo
__global__ void convB_k(const float* __restrict__ W, __nv_bfloat16* __restrict__ B2,
                        int K, int O) {
    int idx = blockIdx.x * blockDim.x + threadIdx.x;
    int tot = NHEADS * K * O;
    if (idx >= tot) return;
    int o = idx % O;
    int f = (idx / O) % K;
    int h = idx / (O * K);
    float v = W[idx];
    __nv_bfloat16 vh = __float2bfloat16(v);
    __nv_bfloat16 vl = __float2bfloat16(v - __bfloat162float(vh));
    size_t base = (size_t)(h * O + o) * 2 * K;
    B2[base + f] = vh;
    B2[base + K + f] = vl;
}

// ---------------- CSR build ------------------------------------------------
__global__ void zero_i_k(int* p, int n) {
    int i = blockIdx.x * blockDim.x + threadIdx.x;
    if (i < n) p[i] = 0;
}

__global__ void count_k(const int* __restrict__ dst, int* __restrict__ cnt) {
    int e = blockIdx.x * blockDim.x + threadIdx.x;
    if (e < NE) atomicAdd(&cnt[clampi(dst[e], 0, NN - 1)], 1);
}

__global__ void scan_k(const int* __restrict__ cnt, int* __restrict__ rowptr,
                       int* __restrict__ fill) {
    __shared__ int sh[1024];
    int tid = threadIdx.x;
    int carry = 0;
    if (tid == 0) rowptr[0] = 0;
    for (int base = 0; base < NN; base += 1024) {
        int i = base + tid;
        int v = (i < NN) ? cnt[i] : 0;
        sh[tid] = v;
        __syncthreads();
        for (int off = 1; off < 1024; off <<= 1) {
            int t = (tid >= off) ? sh[tid - off] : 0;
            __syncthreads();
            sh[tid] += t;
            __syncthreads();
        }
        int incl = sh[tid];
        if (i < NN) {
            rowptr[i + 1] = carry + incl;
            fill[i] = carry + incl - v;
        }
        carry += sh[1023];
        __syncthreads();
    }
}

__global__ void scatter_k(const int* __restrict__ dst, int* __restrict__ fill,
                          int* __restrict__ eids) {
    int e = blockIdx.x * blockDim.x + threadIdx.x;
    if (e < NE) {
        int d = clampi(dst[e], 0, NN - 1);
        int pos = atomicAdd(&fill[d], 1);
        if (pos >= 0 && pos < NE) eids[pos] = e;
    }
}

// ---------------- weight reorder [H,F,O] -> [F, H*O] (final layer) ---------
__global__ void reorder_k(const float* __restrict__ W, float* __restrict__ out,
                          int K, int O) {
    int idx = blockIdx.x * blockDim.x + threadIdx.x;
    int tot = NHEADS * K * O;
    if (idx >= tot) return;
    int o = idx % O;
    int f = (idx / O) % K;
    int h = idx / (O * K);
    out[f * (NHEADS * O) + h * O + o] = W[idx];
}

// ---------------- SIMT SGEMM (final small layer only) ----------------------
#define BM 128
#define BN 128
#define BK 8
__global__ __launch_bounds__(256)
void sgemm_k(const float* __restrict__ A, const float* __restrict__ B,
             float* __restrict__ C, int M, int N, int K) {
    __shared__ float As[BK][BM];
    __shared__ float Bs[BK][BN];
    int tid = threadIdx.x;
    int row0 = blockIdx.y * BM;
    int col0 = blockIdx.x * BN;

    int aRow = tid >> 1;
    int aCol = (tid & 1) * 4;
    int bRow = tid >> 5;
    int bCol = (tid & 31) * 4;
    int ty = tid >> 4;
    int tx = tid & 15;

    float acc[8][8];
#pragma unroll
    for (int i = 0; i < 8; i++)
#pragma unroll
        for (int j = 0; j < 8; j++) acc[i][j] = 0.f;

    for (int k0 = 0; k0 < K; k0 += BK) {
        float4 av = make_float4(0.f, 0.f, 0.f, 0.f);
        int gr = row0 + aRow;
        if (gr < M) av = *(const float4*)(A + (size_t)gr * K + k0 + aCol);
        As[aCol + 0][aRow] = av.x;
        As[aCol + 1][aRow] = av.y;
        As[aCol + 2][aRow] = av.z;
        As[aCol + 3][aRow] = av.w;

        float4 bv = make_float4(0.f, 0.f, 0.f, 0.f);
        int gc = col0 + bCol;
        if (gc + 3 < N) bv = *(const float4*)(B + (size_t)(k0 + bRow) * N + gc);
        Bs[bRow][bCol + 0] = bv.x;
        Bs[bRow][bCol + 1] = bv.y;
        Bs[bRow][bCol + 2] = bv.z;
        Bs[bRow][bCol + 3] = bv.w;
        __syncthreads();

#pragma unroll
        for (int k = 0; k < BK; k++) {
            float ra[8], rb[8];
#pragma unroll
            for (int i = 0; i < 8; i++) ra[i] = As[k][ty * 8 + i];
#pragma unroll
            for (int j = 0; j < 8; j++) rb[j] = Bs[k][tx * 8 + j];
#pragma unroll
            for (int i = 0; i < 8; i++)
#pragma unroll
                for (int j = 0; j < 8; j++) acc[i][j] += ra[i] * rb[j];
        }
        __syncthreads();
    }

#pragma unroll
    for (int i = 0; i < 8; i++) {
        int r = row0 + ty * 8 + i;
        if (r >= M) continue;
#pragma unroll
        for (int j = 0; j < 8; j++) {
            int c = col0 + tx * 8 + j;
            if (c < N) C[(size_t)r * N + c] = acc[i][j];
        }
    }
}

// ---------------- es/ed per (node, head) -----------------------------------
template <int O>
__global__ void esed_k(const float* __restrict__ h, const float* __restrict__ a_s,
                       const float* __restrict__ a_d, float* __restrict__ es,
                       float* __restrict__ ed) {
    int w = (blockIdx.x * blockDim.x + threadIdx.x) >> 5;
    int lane = threadIdx.x & 31;
    if (w >= NN * NHEADS) return;
    int hd = w % NHEADS;
    const float* hp = h + (size_t)w * O;
    float s = 0.f, d = 0.f;
    for (int k = lane; k < O; k += 32) {
        float v = hp[k];
        s += v * a_s[hd * O + k];
        d += v * a_d[hd * O + k];
    }
#pragma unroll
    for (int off = 16; off; off >>= 1) {
        s += __shfl_xor_sync(0xffffffffu, s, off);
        d += __shfl_xor_sync(0xffffffffu, d, off);
    }
    if (lane == 0) { es[w] = s; ed[w] = d; }
}

__global__ void eetab_k(const float* __restrict__ rel, const float* __restrict__ ae,
                        float* __restrict__ tab) {
    int i = threadIdx.x;
    if (i < NREL * NHEADS) {
        int r = i >> 2, hd = i & 3;
        tab[i] = rel[r * 2] * ae[hd * 2] + rel[r * 2 + 1] * ae[hd * 2 + 1];
    }
}

// ---------------- attention aggregation: warp per (node, head) -------------
__device__ __forceinline__ float lrelu02(float v) { return v > 0.f ? v : 0.2f * v; }

template <int O>
__global__ void agg_k(const float* __restrict__ h, const float* __restrict__ es,
                      const float* __restrict__ ed, const float* __restrict__ eetab,
                      const int* __restrict__ src,
                      const int* __restrict__ etype,
                      const int* __restrict__ edist,
                      const int* __restrict__ rowptr, const int* __restrict__ eids,
                      float* __restrict__ out) {
    int w = (blockIdx.x * blockDim.x + threadIdx.x) >> 5;
    int lane = threadIdx.x & 31;
    if (w >= NN * NHEADS) return;
    int n = w / NHEADS;
    int hd = w % NHEADS;
    int beg = rowptr[n], end = rowptr[n + 1];
    float edn = ed[n * NHEADS + hd];

    float m = -3.4e38f;
    for (int i = beg + lane; i < end; i += 32) {
        int e = eids[i];
        int s = clampi(src[e], 0, NN - 1);
        int t = clampi(etype[e], 0, NREL - 1);
        float lg = lrelu02(es[s * NHEADS + hd] + edn + eetab[t * NHEADS + hd]);
        m = fmaxf(m, lg);
    }
#pragma unroll
    for (int off = 16; off; off >>= 1) m = fmaxf(m, __shfl_xor_sync(0xffffffffu, m, off));

    const int ACCN = (O + 31) / 32;
    float acc[(O + 31) / 32];
#pragma unroll
    for (int k = 0; k < ACCN; k++) acc[k] = 0.f;
    float den = 0.f;

    for (int i = beg; i < end; i++) {
        int e = eids[i];
        int s = clampi(src[e], 0, NN - 1);
        int t = clampi(etype[e], 0, NREL - 1);
        float lg = lrelu02(es[s * NHEADS + hd] + edn + eetab[t * NHEADS + hd]);
        float ex = __expf(lg - m);
        den += ex;
        float wgt = ex / (1.0f + (float)edist[e]);
        const float* hs = h + ((size_t)s * NHEADS + hd) * O;
#pragma unroll
        for (int k = 0; k < ACCN; k++) {
            int o = lane + 32 * k;
            if (o < O) acc[k] += wgt * hs[o];
        }
    }
    float inv = 1.0f / (den + 1e-16f);
    float* op = out + ((size_t)n * NHEADS + hd) * O;
#pragma unroll
    for (int k = 0; k < ACCN; k++) {
        int o = lane + 32 * k;
        if (o < O) op[o] = acc[k] * inv;
    }
}

// ---------------- combine (mean over heads + bias [+ residual]) ------------
__global__ void combine128_k(const float* __restrict__ tmp, const float* __restrict__ b,
                             const float* __restrict__ resid, float* __restrict__ out) {
    int i = blockIdx.x * blockDim.x + threadIdx.x;
    if (i >= NN * HID) return;
    int n = i >> 7, o = i & 127;
    const float* t = tmp + (size_t)n * NHEADS * HID + o;
    float v = 0.25f * (t[0] + t[HID] + t[2 * HID] + t[3 * HID]) + b[o];
    if (resid) v += resid[i];
    out[i] = v;
}

__global__ void combine9_k(const float* __restrict__ tmp, const float* __restrict__ b,
                           float* __restrict__ out) {
    int i = blockIdx.x * blockDim.x + threadIdx.x;
    if (i >= NN * NCLS) return;
    int n = i / NCLS, c = i % NCLS;
    const float* t = tmp + (size_t)n * NHEADS * NCLS + c;
    float v = 0.25f * (t[0] + t[NCLS] + t[2 * NCLS] + t[3 * NCLS]) + b[c];
    out[i] = v > 0.f ? v : 0.1f * v;
}

// ---------------- batch norm -----------------------------------------------
__global__ void bn_zero_k(float* s, float* q) {
    int t = threadIdx.x;
    if (t < HID) { s[t] = 0.f; q[t] = 0.f; }
}

__global__ void bn_stats_k(const float* __restrict__ x, float* __restrict__ sum,
                           float* __restrict__ sumsq) {
    int t = threadIdx.x;
    int rows_per = (NN + gridDim.x - 1) / gridDim.x;
    int r0 = blockIdx.x * rows_per;
    int r1 = min(r0 + rows_per, NN);
    float s = 0.f, q = 0.f;
    for (int r = r0; r < r1; r++) {
        float v = x[(size_t)r * HID + t];
        s += v;
        q += v * v;
    }
    atomicAdd(&sum[t], s);
    atomicAdd(&sumsq[t], q);
}

__global__ void bn_apply_k(const float* __restrict__ x, const float* __restrict__ sum,
                           const float* __restrict__ sumsq, const float* __restrict__ g,
                           const float* __restrict__ b, float* __restrict__ out) {
    int i = blockIdx.x * blockDim.x + threadIdx.x;
    if (i >= NN * HID) return;
    int o = i & 127;
    float mu = sum[o] * (1.0f / NN);
    float var = sumsq[o] * (1.0f / NN) - mu * mu;
    float v = (x[i] - mu) * rsqrtf(var + 1e-5f) * g[o] + b[o];
    out[i] = v > 0.f ? v : 0.1f * v;
}

// ---------------- host orchestration ---------------------------------------
static void run_conv_tc(const float* X, int K, const float* W,
                        const float* a_s, const float* a_d, const float* a_e,
                        const float* rel, const int* src, const int* etype,
                        const int* edist, float* h_buf, float* tmp_buf, float* es,
                        float* ed, float* eetab, int* rowptr, int* eids,
                        __nv_bfloat16* A2, __nv_bfloat16* B2) {
    int na = NN * K;
    convA_k<<<(na + 255) / 256, 256>>>(X, A2, NN, K);
    int nb = NHEADS * K * HID;
    convB_k<<<(nb + 255) / 256, 256>>>(W, B2, K, HID);
    dim3 grid(4, (NN + 127) / 128);
    mma_gemm_k<<<grid, 256>>>(A2, B2, h_buf, NN, K);
    int warps = NN * NHEADS;
    int blocks = (warps * 32 + 255) / 256;
    esed_k<HID><<<blocks, 256>>>(h_buf, a_s, a_d, es, ed);
    eetab_k<<<1, 256>>>(rel, a_e, eetab);
    agg_k<HID><<<blocks, 256>>>(h_buf, es, ed, eetab, src, etype, edist, rowptr,
                                eids, tmp_buf);
}

extern "C" void kernel_launch(void* const* d_in, const int* in_sizes, int n_in,
                              void* d_out, int out_size) {
    const float* x = (const float*)d_in[0];
    const int* ei = (const int*)d_in[1];
    const int* etype = (const int*)d_in[2];
    const int* edist = (const int*)d_in[3];
    const float* W0 = (const float*)d_in[4];
    const float* asrc0 = (const float*)d_in[5];
    const float* adst0 = (const float*)d_in[6];
    const float* aedge0 = (const float*)d_in[7];
    const float* b0 = (const float*)d_in[8];
    const float* rel0 = (const float*)d_in[9];
    const float* Wm = (const float*)d_in[10];
    const float* asrcm = (const float*)d_in[11];
    const float* adstm = (const float*)d_in[12];
    const float* aedgem = (const float*)d_in[13];
    const float* bm = (const float*)d_in[14];
    const float* relm = (const float*)d_in[15];
    const float* WL = (const float*)d_in[16];
    const float* asrcL = (const float*)d_in[17];
    const float* adstL = (const float*)d_in[18];
    const float* aedgeL = (const float*)d_in[19];
    const float* bL = (const float*)d_in[20];
    const float* relL = (const float*)d_in[21];
    const float* bn_g = (const float*)d_in[22];
    const float* bn_b = (const float*)d_in[23];

    float *h_buf, *tmp, *xb, *hin, *es, *ed, *eetab, *Wb, *bsum, *bsq;
    __nv_bfloat16 *A2, *B2;
    int *cnt, *rowptr, *fill, *eids;
    cudaGetSymbolAddress((void**)&h_buf, g_h);
    cudaGetSymbolAddress((void**)&tmp, g_tmp);
    cudaGetSymbolAddress((void**)&xb, g_x);
    cudaGetSymbolAddress((void**)&hin, g_hin);
    cudaGetSymbolAddress((void**)&es, g_es);
    cudaGetSymbolAddress((void**)&ed, g_ed);
    cudaGetSymbolAddress((void**)&eetab, g_eetab);
    cudaGetSymbolAddress((void**)&Wb, g_W);
    cudaGetSymbolAddress((void**)&bsum, g_bsum);
    cudaGetSymbolAddress((void**)&bsq, g_bsq);
    cudaGetSymbolAddress((void**)&A2, g_A2);
    cudaGetSymbolAddress((void**)&B2, g_B2);
    cudaGetSymbolAddress((void**)&cnt, g_cnt);
    cudaGetSymbolAddress((void**)&rowptr, g_rowptr);
    cudaGetSymbolAddress((void**)&fill, g_fill);
    cudaGetSymbolAddress((void**)&eids, g_eids);

    const int* src = ei;
    const int* dst = ei + NE;

    // CSR build
    zero_i_k<<<(NN + 255) / 256, 256>>>(cnt, NN);
    count_k<<<(NE + 255) / 256, 256>>>(dst, cnt);
    scan_k<<<1, 1024>>>(cnt, rowptr, fill);
    scatter_k<<<(NE + 255) / 256, 256>>>(dst, fill, eids);

    int nb128 = (NN * HID + 255) / 256;

    // layer 0 (tensor-core GEMM, K=768)
    run_conv_tc(x, FIN, W0, asrc0, adst0, aedge0, rel0, src, etype, edist, h_buf,
                tmp, es, ed, eetab, rowptr, eids, A2, B2);
    combine128_k<<<nb128, 256>>>(tmp, b0, nullptr, xb);

    // middle layers (K=128)
    for (int i = 0; i < 3; i++) {
        bn_zero_k<<<1, 128>>>(bsum, bsq);
        bn_stats_k<<<200, 128>>>(xb, bsum, bsq);
        bn_apply_k<<<nb128, 256>>>(xb, bsum, bsq, bn_g + i * HID, bn_b + i * HID, hin);
        run_conv_tc(hin, HID, Wm + (size_t)i * NHEADS * HID * HID,
                    asrcm + i * NHEADS * HID, adstm + i * NHEADS * HID,
                    aedgem + i * NHEADS * 2, relm + i * NREL * 2, src, etype, edist,
                    h_buf, tmp, es, ed, eetab, rowptr, eids, A2, B2);
        combine128_k<<<nb128, 256>>>(tmp, bm + i * HID, hin, xb);
    }

    // final layer (SIMT, tiny)
    bn_zero_k<<<1, 128>>>(bsum, bsq);
    bn_stats_k<<<200, 128>>>(xb, bsum, bsq);
    bn_apply_k<<<nb128, 256>>>(xb, bsum, bsq, bn_g + 3 * HID, bn_b + 3 * HID, hin);
    {
        int tot = NHEADS * HID * NCLS;
        reorder_k<<<(tot + 255) / 256, 256>>>(WL, Wb, HID, NCLS);
        int Ncols = NHEADS * NCLS;
        dim3 grid((Ncols + BN - 1) / BN, (NN + BM - 1) / BM);
        sgemm_k<<<grid, 256>>>(hin, Wb, h_buf, NN, Ncols, HID);
        int warps = NN * NHEADS;
        int blocks = (warps * 32 + 255) / 256;
        esed_k<NCLS><<<blocks, 256>>>(h_buf, asrcL, adstL, es, ed);
        eetab_k<<<1, 256>>>(relL, aedgeL, eetab);
        agg_k<NCLS><<<blocks, 256>>>(h_buf, es, ed, eetab, src, etype, edist, rowptr,
                                     eids, tmp);
    }
    combine9_k<<<(NN * NCLS + 255) / 256, 256>>>(tmp, bL, (float*)d_out);
}

// round 6
// speedup vs baseline: 1.3391x; 1.2805x over previous
#include <cuda_runtime.h>
#include <cuda_bf16.h>
#include <math.h>
#include <stdint.h>

#define NN 20000
#define NE 320000
#define NHEADS 4
#define NREL 40
#define FIN 768
#define HID 128
#define NCLS 9

// ---------------- scratch (static device globals; no allocs allowed) -------
__device__ __align__(16) float g_h[NN * NHEADS * HID];     // GEMM out [N, 512]
__device__ __align__(16) float g_tmp[NN * NHEADS * HID];   // logit/alpha buf + final-layer agg out
__device__ __align__(16) float g_x[NN * HID];              // running x
__device__ __align__(16) float g_hin[NN * HID];            // bn/lrelu output (residual)
__device__ __align__(16) float g_es[NN * NHEADS];
__device__ __align__(16) float g_ed[NN * NHEADS];
__device__ __align__(16) float g_eetab[NREL * NHEADS];
__device__ __align__(16) float g_W[FIN * NHEADS * HID];    // reordered weights (final layer SIMT)
__device__ __align__(16) __nv_bfloat16 g_A2[NN * 2 * FIN];             // [M, 2K] hi|lo
__device__ __align__(16) __nv_bfloat16 g_B2[(NHEADS * HID) * 2 * FIN]; // [512, 2K] hi|lo
__device__ int g_cnt[NN];
__device__ int g_rowptr[NN + 1];
__device__ int g_fill[NN];
__device__ int g_eids[NE];
__device__ float g_bsum[HID];
__device__ float g_bsq[HID];

__device__ __forceinline__ int clampi(int v, int lo, int hi) {
    return v < lo ? lo : (v > hi ? hi : v);
}

__device__ __forceinline__ uint32_t smem_u32(const void* p) {
    uint32_t a;
    asm("{ .reg .u64 t; cvta.to.shared.u64 t, %1; cvt.u32.u64 %0, t; }"
        : "=r"(a) : "l"(p));
    return a;
}

__device__ __forceinline__ void ldsm_x4(uint32_t* r, uint32_t addr) {
    asm volatile("ldmatrix.sync.aligned.m8n8.x4.shared.b16 {%0,%1,%2,%3}, [%4];"
                 : "=r"(r[0]), "=r"(r[1]), "=r"(r[2]), "=r"(r[3]) : "r"(addr));
}

__device__ __forceinline__ void mma16816(float* d, const uint32_t* a, uint32_t b0,
                                         uint32_t b1) {
    asm volatile(
        "mma.sync.aligned.m16n8k16.row.col.f32.bf16.bf16.f32 "
        "{%0,%1,%2,%3}, {%4,%5,%6,%7}, {%8,%9}, {%0,%1,%2,%3};"
        : "+f"(d[0]), "+f"(d[1]), "+f"(d[2]), "+f"(d[3])
        : "r"(a[0]), "r"(a[1]), "r"(a[2]), "r"(a[3]), "r"(b0), "r"(b1));
}

__device__ __forceinline__ void cp16(uint32_t saddr, const void* g, bool pred) {
    int sz = pred ? 16 : 0;
    asm volatile("cp.async.cg.shared.global [%0], [%1], 16, %2;"
                 :: "r"(saddr), "l"(g), "r"(sz));
}
#define CP_COMMIT() asm volatile("cp.async.commit_group;" ::: "memory")
#define CP_WAIT1() asm volatile("cp.async.wait_group 1;" ::: "memory")
#define CP_WAIT0() asm volatile("cp.async.wait_group 0;" ::: "memory")

// ---------------- bf16x3-split tensor-core GEMM (cp.async 2-stage) ---------
// C[M,512] = A[M,K] x Bt[512,K]^T using phases: AhBh + AhBl + AlBh
#define SMS 40  // smem row stride (bf16); 80B -> conflict-free ldmatrix
#define TILE_B (128 * SMS)  // elems per buffer
__global__ __launch_bounds__(256)
void mma_gemm_k(const __nv_bfloat16* __restrict__ A2,
                const __nv_bfloat16* __restrict__ B2,
                float* __restrict__ C, int M, int K) {
    __shared__ __align__(16) __nv_bfloat16 Asm[2][TILE_B];
    __shared__ __align__(16) __nv_bfloat16 Bsm[2][TILE_B];
    int tid = threadIdx.x;
    int wid = tid >> 5;
    int lane = tid & 31;
    int warp_m = wid & 3;
    int warp_n = wid >> 2;
    int row0 = blockIdx.y * 128;
    int col0 = blockIdx.x * 128;

    float acc[2][8][4];
#pragma unroll
    for (int i = 0; i < 2; i++)
#pragma unroll
        for (int j = 0; j < 8; j++)
#pragma unroll
            for (int q = 0; q < 4; q++) acc[i][j][q] = 0.f;

    uint32_t As0 = smem_u32(&Asm[0][0]);
    uint32_t Bs0 = smem_u32(&Bsm[0][0]);
    int ksz = K / 32;
    int nst = 3 * ksz;
    int lr = tid >> 1;
    int lq = (tid & 1) * 16;
    int gr = row0 + lr;
    bool aval = gr < M;
    const __nv_bfloat16* Abase = A2 + (size_t)(aval ? gr : 0) * (2 * K);
    const __nv_bfloat16* Bbase = B2 + (size_t)(col0 + lr) * (2 * K);
    uint32_t sA = (uint32_t)((lr * SMS + lq) * 2);

    // stage-issue helper (macro to keep addresses simple)
#define ISSUE_STAGE(st) do {                                            \
        int _ph = (st) / ksz;                                           \
        int _kb = ((st) - _ph * ksz) * 32;                              \
        int _akb = (_ph == 2) ? K + _kb : _kb;                          \
        int _bkb = (_ph == 1) ? K + _kb : _kb;                          \
        int _buf = (st) & 1;                                            \
        uint32_t _sa = As0 + _buf * (TILE_B * 2) + sA;                  \
        const __nv_bfloat16* _ga = Abase + _akb + lq;                   \
        cp16(_sa, _ga, aval);                                           \
        cp16(_sa + 16, _ga + 8, aval);                                  \
        uint32_t _sb = Bs0 + _buf * (TILE_B * 2) + sA;                  \
        const __nv_bfloat16* _gb = Bbase + _bkb + lq;                   \
        cp16(_sb, _gb, true);                                           \
        cp16(_sb + 16, _gb + 8, true);                                  \
        CP_COMMIT();                                                    \
    } while (0)

    ISSUE_STAGE(0);
    for (int st = 0; st < nst; st++) {
        if (st + 1 < nst) {
            ISSUE_STAGE(st + 1);
            CP_WAIT1();
        } else {
            CP_WAIT0();
        }
        __syncthreads();
        uint32_t Ab = As0 + (st & 1) * (TILE_B * 2);
        uint32_t Bb = Bs0 + (st & 1) * (TILE_B * 2);
#pragma unroll
        for (int k16 = 0; k16 < 32; k16 += 16) {
            uint32_t af[2][4];
#pragma unroll
            for (int mf = 0; mf < 2; mf++) {
                int m = warp_m * 32 + mf * 16 + (lane & 15);
                uint32_t addr = Ab + (uint32_t)((m * SMS + k16 + ((lane >> 4) << 3)) * 2);
                ldsm_x4(af[mf], addr);
            }
            uint32_t bf[4][4];
#pragma unroll
            for (int jp = 0; jp < 4; jp++) {
                int n = warp_n * 64 + jp * 16 + (lane & 15);
                uint32_t addr = Bb + (uint32_t)((n * SMS + k16 + ((lane >> 4) << 3)) * 2);
                ldsm_x4(bf[jp], addr);
            }
#pragma unroll
            for (int mf = 0; mf < 2; mf++)
#pragma unroll
                for (int jp = 0; jp < 4; jp++) {
                    mma16816(acc[mf][jp * 2 + 0], af[mf], bf[jp][0], bf[jp][2]);
                    mma16816(acc[mf][jp * 2 + 1], af[mf], bf[jp][1], bf[jp][3]);
                }
        }
        __syncthreads();
    }
#undef ISSUE_STAGE

    int g = lane >> 2, t = lane & 3;
#pragma unroll
    for (int mf = 0; mf < 2; mf++) {
#pragma unroll
        for (int nf = 0; nf < 8; nf++) {
            int col = col0 + warp_n * 64 + nf * 8 + t * 2;
            int r0 = row0 + warp_m * 32 + mf * 16 + g;
            if (r0 < M) {
                float2 v = make_float2(acc[mf][nf][0], acc[mf][nf][1]);
                *(float2*)(C + (size_t)r0 * 512 + col) = v;
            }
            int r1 = r0 + 8;
            if (r1 < M) {
                float2 v = make_float2(acc[mf][nf][2], acc[mf][nf][3]);
                *(float2*)(C + (size_t)r1 * 512 + col) = v;
            }
        }
    }
}

// ---------------- fp32 -> bf16 hi/lo split ---------------------------------
__global__ void convA_k(const float* __restrict__ X, __nv_bfloat16* __restrict__ A2,
                        int M, int K) {
    int i = blockIdx.x * blockDim.x + threadIdx.x;
    if (i >= M * K) return;
    int r = i / K, k = i - r * K;
    float v = X[i];
    __nv_bfloat16 h = __float2bfloat16(v);
    __nv_bfloat16 l = __float2bfloat16(v - __bfloat162float(h));
    size_t base = (size_t)r * 2 * K;
    A2[base + k] = h;
    A2[base + K + k] = l;
}

__global__ void convB_k(const float* __restrict__ W, __nv_bfloat16* __restrict__ B2,
                        int K, int O) {
    int idx = blockIdx.x * blockDim.x + threadIdx.x;
    int tot = NHEADS * K * O;
    if (idx >= tot) return;
    int o = idx % O;
    int f = (idx / O) % K;
    int h = idx / (O * K);
    float v = W[idx];
    __nv_bfloat16 vh = __float2bfloat16(v);
    __nv_bfloat16 vl = __float2bfloat16(v - __bfloat162float(vh));
    size_t base = (size_t)(h * O + o) * 2 * K;
    B2[base + f] = vh;
    B2[base + K + f] = vl;
}

// ---------------- CSR build ------------------------------------------------
__global__ void zero_i_k(int* p, int n) {
    int i = blockIdx.x * blockDim.x + threadIdx.x;
    if (i < n) p[i] = 0;
}

__global__ void count_k(const int* __restrict__ dst, int* __restrict__ cnt) {
    int e = blockIdx.x * blockDim.x + threadIdx.x;
    if (e < NE) atomicAdd(&cnt[clampi(dst[e], 0, NN - 1)], 1);
}

__global__ void scan_k(const int* __restrict__ cnt, int* __restrict__ rowptr,
                       int* __restrict__ fill) {
    __shared__ int sh[1024];
    int tid = threadIdx.x;
    int carry = 0;
    if (tid == 0) rowptr[0] = 0;
    for (int base = 0; base < NN; base += 1024) {
        int i = base + tid;
        int v = (i < NN) ? cnt[i] : 0;
        sh[tid] = v;
        __syncthreads();
        for (int off = 1; off < 1024; off <<= 1) {
            int t = (tid >= off) ? sh[tid - off] : 0;
            __syncthreads();
            sh[tid] += t;
            __syncthreads();
        }
        int incl = sh[tid];
        if (i < NN) {
            rowptr[i + 1] = carry + incl;
            fill[i] = carry + incl - v;
        }
        carry += sh[1023];
        __syncthreads();
    }
}

__global__ void scatter_k(const int* __restrict__ dst, int* __restrict__ fill,
                          int* __restrict__ eids) {
    int e = blockIdx.x * blockDim.x + threadIdx.x;
    if (e < NE) {
        int d = clampi(dst[e], 0, NN - 1);
        int pos = atomicAdd(&fill[d], 1);
        if (pos >= 0 && pos < NE) eids[pos] = e;
    }
}

// ---------------- weight reorder [H,F,O] -> [F, H*O] (final layer) ---------
__global__ void reorder_k(const float* __restrict__ W, float* __restrict__ out,
                          int K, int O) {
    int idx = blockIdx.x * blockDim.x + threadIdx.x;
    int tot = NHEADS * K * O;
    if (idx >= tot) return;
    int o = idx % O;
    int f = (idx / O) % K;
    int h = idx / (O * K);
    out[f * (NHEADS * O) + h * O + o] = W[idx];
}

// ---------------- SIMT SGEMM (final small layer only) ----------------------
#define BM 128
#define BN 128
#define BK 8
__global__ __launch_bounds__(256)
void sgemm_k(const float* __restrict__ A, const float* __restrict__ B,
             float* __restrict__ C, int M, int N, int K) {
    __shared__ float As[BK][BM];
    __shared__ float Bs[BK][BN];
    int tid = threadIdx.x;
    int row0 = blockIdx.y * BM;
    int col0 = blockIdx.x * BN;

    int aRow = tid >> 1;
    int aCol = (tid & 1) * 4;
    int bRow = tid >> 5;
    int bCol = (tid & 31) * 4;
    int ty = tid >> 4;
    int tx = tid & 15;

    float acc[8][8];
#pragma unroll
    for (int i = 0; i < 8; i++)
#pragma unroll
        for (int j = 0; j < 8; j++) acc[i][j] = 0.f;

    for (int k0 = 0; k0 < K; k0 += BK) {
        float4 av = make_float4(0.f, 0.f, 0.f, 0.f);
        int gr = row0 + aRow;
        if (gr < M) av = *(const float4*)(A + (size_t)gr * K + k0 + aCol);
        As[aCol + 0][aRow] = av.x;
        As[aCol + 1][aRow] = av.y;
        As[aCol + 2][aRow] = av.z;
        As[aCol + 3][aRow] = av.w;

        float4 bv = make_float4(0.f, 0.f, 0.f, 0.f);
        int gc = col0 + bCol;
        if (gc + 3 < N) bv = *(const float4*)(B + (size_t)(k0 + bRow) * N + gc);
        Bs[bRow][bCol + 0] = bv.x;
        Bs[bRow][bCol + 1] = bv.y;
        Bs[bRow][bCol + 2] = bv.z;
        Bs[bRow][bCol + 3] = bv.w;
        __syncthreads();

#pragma unroll
        for (int k = 0; k < BK; k++) {
            float ra[8], rb[8];
#pragma unroll
            for (int i = 0; i < 8; i++) ra[i] = As[k][ty * 8 + i];
#pragma unroll
            for (int j = 0; j < 8; j++) rb[j] = Bs[k][tx * 8 + j];
#pragma unroll
            for (int i = 0; i < 8; i++)
#pragma unroll
                for (int j = 0; j < 8; j++) acc[i][j] += ra[i] * rb[j];
        }
        __syncthreads();
    }

#pragma unroll
    for (int i = 0; i < 8; i++) {
        int r = row0 + ty * 8 + i;
        if (r >= M) continue;
#pragma unroll
        for (int j = 0; j < 8; j++) {
            int c = col0 + tx * 8 + j;
            if (c < N) C[(size_t)r * N + c] = acc[i][j];
        }
    }
}

// ---------------- es/ed per (node, head) -----------------------------------
template <int O>
__global__ void esed_k(const float* __restrict__ h, const float* __restrict__ a_s,
                       const float* __restrict__ a_d, float* __restrict__ es,
                       float* __restrict__ ed) {
    int w = (blockIdx.x * blockDim.x + threadIdx.x) >> 5;
    int lane = threadIdx.x & 31;
    if (w >= NN * NHEADS) return;
    int hd = w % NHEADS;
    const float* hp = h + (size_t)w * O;
    float s = 0.f, d = 0.f;
    for (int k = lane; k < O; k += 32) {
        float v = hp[k];
        s += v * a_s[hd * O + k];
        d += v * a_d[hd * O + k];
    }
#pragma unroll
    for (int off = 16; off; off >>= 1) {
        s += __shfl_xor_sync(0xffffffffu, s, off);
        d += __shfl_xor_sync(0xffffffffu, d, off);
    }
    if (lane == 0) { es[w] = s; ed[w] = d; }
}

__global__ void eetab_k(const float* __restrict__ rel, const float* __restrict__ ae,
                        float* __restrict__ tab) {
    int i = threadIdx.x;
    if (i < NREL * NHEADS) {
        int r = i >> 2, hd = i & 3;
        tab[i] = rel[r * 2] * ae[hd * 2] + rel[r * 2 + 1] * ae[hd * 2 + 1];
    }
}

__device__ __forceinline__ float lrelu02(float v) { return v > 0.f ? v : 0.2f * v; }

// ---------------- agg stage A: edge-parallel logits (all heads) ------------
__global__ void logit_k(const float* __restrict__ es, const float* __restrict__ ed,
                        const float* __restrict__ eetab, const int* __restrict__ src,
                        const int* __restrict__ dst, const int* __restrict__ etype,
                        const int* __restrict__ eids, float4* __restrict__ lg4) {
    int i = blockIdx.x * blockDim.x + threadIdx.x;
    if (i >= NE) return;
    int e = eids[i];
    int s = clampi(src[e], 0, NN - 1);
    int d = clampi(dst[e], 0, NN - 1);
    int t = clampi(etype[e], 0, NREL - 1);
    float4 a = *(const float4*)(es + s * 4);
    float4 b = *(const float4*)(ed + d * 4);
    float4 c = *(const float4*)(eetab + t * 4);
    float4 r;
    r.x = lrelu02(a.x + b.x + c.x);
    r.y = lrelu02(a.y + b.y + c.y);
    r.z = lrelu02(a.z + b.z + c.z);
    r.w = lrelu02(a.w + b.w + c.w);
    lg4[i] = r;
}

// ---------------- agg stage B: warp-per-node softmax -> alpha (in place) ---
__global__ void softmax_k(float4* __restrict__ lg4, const int* __restrict__ edist,
                          const int* __restrict__ eids, const int* __restrict__ rowptr) {
    int n = (blockIdx.x * blockDim.x + threadIdx.x) >> 5;
    int lane = threadIdx.x & 31;
    if (n >= NN) return;
    int beg = rowptr[n], end = rowptr[n + 1];
    float4 m = make_float4(-3.4e38f, -3.4e38f, -3.4e38f, -3.4e38f);
    for (int i = beg + lane; i < end; i += 32) {
        float4 v = lg4[i];
        m.x = fmaxf(m.x, v.x); m.y = fmaxf(m.y, v.y);
        m.z = fmaxf(m.z, v.z); m.w = fmaxf(m.w, v.w);
    }
#pragma unroll
    for (int off = 16; off; off >>= 1) {
        m.x = fmaxf(m.x, __shfl_xor_sync(0xffffffffu, m.x, off));
        m.y = fmaxf(m.y, __shfl_xor_sync(0xffffffffu, m.y, off));
        m.z = fmaxf(m.z, __shfl_xor_sync(0xffffffffu, m.z, off));
        m.w = fmaxf(m.w, __shfl_xor_sync(0xffffffffu, m.w, off));
    }
    float4 den = make_float4(0.f, 0.f, 0.f, 0.f);
    for (int i = beg + lane; i < end; i += 32) {
        float4 v = lg4[i];
        den.x += __expf(v.x - m.x); den.y += __expf(v.y - m.y);
        den.z += __expf(v.z - m.z); den.w += __expf(v.w - m.w);
    }
#pragma unroll
    for (int off = 16; off; off >>= 1) {
        den.x += __shfl_xor_sync(0xffffffffu, den.x, off);
        den.y += __shfl_xor_sync(0xffffffffu, den.y, off);
        den.z += __shfl_xor_sync(0xffffffffu, den.z, off);
        den.w += __shfl_xor_sync(0xffffffffu, den.w, off);
    }
    float4 inv;
    inv.x = 1.0f / (den.x + 1e-16f); inv.y = 1.0f / (den.y + 1e-16f);
    inv.z = 1.0f / (den.z + 1e-16f); inv.w = 1.0f / (den.w + 1e-16f);
    for (int i = beg + lane; i < end; i += 32) {
        float4 v = lg4[i];
        float w = 1.0f / (1.0f + (float)edist[eids[i]]);
        float4 a;
        a.x = __expf(v.x - m.x) * inv.x * w;
        a.y = __expf(v.y - m.y) * inv.y * w;
        a.z = __expf(v.z - m.z) * inv.z * w;
        a.w = __expf(v.w - m.w) * inv.w * w;
        lg4[i] = a;
    }
}

// ---------------- agg stage C: warp-per-node gather (all heads) + combine --
__global__ void aggC_k(const float* __restrict__ h, const float4* __restrict__ alpha4,
                       const int* __restrict__ src, const int* __restrict__ eids,
                       const int* __restrict__ rowptr, const float* __restrict__ b,
                       const float* __restrict__ resid, float* __restrict__ out) {
    int n = (blockIdx.x * blockDim.x + threadIdx.x) >> 5;
    int lane = threadIdx.x & 31;
    if (n >= NN) return;
    int beg = rowptr[n], end = rowptr[n + 1];
    float acc[NHEADS][4];
#pragma unroll
    for (int q = 0; q < NHEADS; q++)
#pragma unroll
        for (int j = 0; j < 4; j++) acc[q][j] = 0.f;

    for (int i = beg; i < end; i++) {
        int e = eids[i];
        int s = clampi(src[e], 0, NN - 1);
        float4 a = alpha4[i];
        const float* hs = h + (size_t)s * 512;
        float aw[4] = {a.x, a.y, a.z, a.w};
#pragma unroll
        for (int q = 0; q < NHEADS; q++)
#pragma unroll
            for (int j = 0; j < 4; j++)
                acc[q][j] += aw[q] * hs[q * 128 + lane + 32 * j];
    }
#pragma unroll
    for (int j = 0; j < 4; j++) {
        int o = lane + 32 * j;
        float v = 0.25f * (acc[0][j] + acc[1][j] + acc[2][j] + acc[3][j]) + b[o];
        if (resid) v += resid[(size_t)n * 128 + o];
        out[(size_t)n * 128 + o] = v;
    }
}

// ---------------- final-layer agg (O=9, old style) + combine ---------------
template <int O>
__global__ void agg_k(const float* __restrict__ h, const float* __restrict__ es,
                      const float* __restrict__ ed, const float* __restrict__ eetab,
                      const int* __restrict__ src,
                      const int* __restrict__ etype,
                      const int* __restrict__ edist,
                      const int* __restrict__ rowptr, const int* __restrict__ eids,
                      float* __restrict__ out) {
    int w = (blockIdx.x * blockDim.x + threadIdx.x) >> 5;
    int lane = threadIdx.x & 31;
    if (w >= NN * NHEADS) return;
    int n = w / NHEADS;
    int hd = w % NHEADS;
    int beg = rowptr[n], end = rowptr[n + 1];
    float edn = ed[n * NHEADS + hd];

    float m = -3.4e38f;
    for (int i = beg + lane; i < end; i += 32) {
        int e = eids[i];
        int s = clampi(src[e], 0, NN - 1);
        int t = clampi(etype[e], 0, NREL - 1);
        float lg = lrelu02(es[s * NHEADS + hd] + edn + eetab[t * NHEADS + hd]);
        m = fmaxf(m, lg);
    }
#pragma unroll
    for (int off = 16; off; off >>= 1) m = fmaxf(m, __shfl_xor_sync(0xffffffffu, m, off));

    const int ACCN = (O + 31) / 32;
    float acc[(O + 31) / 32];
#pragma unroll
    for (int k = 0; k < ACCN; k++) acc[k] = 0.f;
    float den = 0.f;

    for (int i = beg; i < end; i++) {
        int e = eids[i];
        int s = clampi(src[e], 0, NN - 1);
        int t = clampi(etype[e], 0, NREL - 1);
        float lg = lrelu02(es[s * NHEADS + hd] + edn + eetab[t * NHEADS + hd]);
        float ex = __expf(lg - m);
        den += ex;
        float wgt = ex / (1.0f + (float)edist[e]);
        const float* hs = h + ((size_t)s * NHEADS + hd) * O;
#pragma unroll
        for (int k = 0; k < ACCN; k++) {
            int o = lane + 32 * k;
            if (o < O) acc[k] += wgt * hs[o];
        }
    }
    float inv = 1.0f / (den + 1e-16f);
    float* op = out + ((size_t)n * NHEADS + hd) * O;
#pragma unroll
    for (int k = 0; k < ACCN; k++) {
        int o = lane + 32 * k;
        if (o < O) op[o] = acc[k] * inv;
    }
}

__global__ void combine9_k(const float* __restrict__ tmp, const float* __restrict__ b,
                           float* __restrict__ out) {
    int i = blockIdx.x * blockDim.x + threadIdx.x;
    if (i >= NN * NCLS) return;
    int n = i / NCLS, c = i % NCLS;
    const float* t = tmp + (size_t)n * NHEADS * NCLS + c;
    float v = 0.25f * (t[0] + t[NCLS] + t[2 * NCLS] + t[3 * NCLS]) + b[c];
    out[i] = v > 0.f ? v : 0.1f * v;
}

// ---------------- batch norm -----------------------------------------------
__global__ void bn_zero_k(float* s, float* q) {
    int t = threadIdx.x;
    if (t < HID) { s[t] = 0.f; q[t] = 0.f; }
}

__global__ void bn_stats_k(const float* __restrict__ x, float* __restrict__ sum,
                           float* __restrict__ sumsq) {
    int t = threadIdx.x;
    int rows_per = (NN + gridDim.x - 1) / gridDim.x;
    int r0 = blockIdx.x * rows_per;
    int r1 = min(r0 + rows_per, NN);
    float s = 0.f, q = 0.f;
    for (int r = r0; r < r1; r++) {
        float v = x[(size_t)r * HID + t];
        s += v;
        q += v * v;
    }
    atomicAdd(&sum[t], s);
    atomicAdd(&sumsq[t], q);
}

__global__ void bn_apply_k(const float* __restrict__ x, const float* __restrict__ sum,
                           const float* __restrict__ sumsq, const float* __restrict__ g,
                           const float* __restrict__ b, float* __restrict__ out) {
    int i = blockIdx.x * blockDim.x + threadIdx.x;
    if (i >= NN * HID) return;
    int o = i & 127;
    float mu = sum[o] * (1.0f / NN);
    float var = sumsq[o] * (1.0f / NN) - mu * mu;
    float v = (x[i] - mu) * rsqrtf(var + 1e-5f) * g[o] + b[o];
    out[i] = v > 0.f ? v : 0.1f * v;
}

// ---------------- host orchestration ---------------------------------------
struct Bufs {
    float *h_buf, *tmp, *xb, *hin, *es, *ed, *eetab, *Wb, *bsum, *bsq;
    __nv_bfloat16 *A2, *B2;
    int *cnt, *rowptr, *fill, *eids;
};

static void run_gemm(const float* X, int K, const float* W, Bufs& B) {
    int na = NN * K;
    convA_k<<<(na + 255) / 256, 256>>>(X, B.A2, NN, K);
    int nb = NHEADS * K * HID;
    convB_k<<<(nb + 255) / 256, 256>>>(W, B.B2, K, HID);
    dim3 grid(4, (NN + 127) / 128);
    mma_gemm_k<<<grid, 256>>>(B.A2, B.B2, B.h_buf, NN, K);
}

static void run_attn(const float* a_s, const float* a_d, const float* a_e,
                     const float* rel, const int* src, const int* dst,
                     const int* etype, const int* edist, const float* bias,
                     const float* resid, float* out, Bufs& B) {
    int warps = NN * NHEADS;
    int blocks = (warps * 32 + 255) / 256;
    esed_k<HID><<<blocks, 256>>>(B.h_buf, a_s, a_d, B.es, B.ed);
    eetab_k<<<1, 256>>>(rel, a_e, B.eetab);
    float4* lg4 = (float4*)B.tmp;
    logit_k<<<(NE + 255) / 256, 256>>>(B.es, B.ed, B.eetab, src, dst, etype,
                                       B.eids, lg4);
    softmax_k<<<(NN * 32 + 255) / 256, 256>>>(lg4, edist, B.eids, B.rowptr);
    aggC_k<<<(NN * 32 + 255) / 256, 256>>>(B.h_buf, lg4, src, B.eids, B.rowptr,
                                           bias, resid, out);
}

extern "C" void kernel_launch(void* const* d_in, const int* in_sizes, int n_in,
                              void* d_out, int out_size) {
    const float* x = (const float*)d_in[0];
    const int* ei = (const int*)d_in[1];
    const int* etype = (const int*)d_in[2];
    const int* edist = (const int*)d_in[3];
    const float* W0 = (const float*)d_in[4];
    const float* asrc0 = (const float*)d_in[5];
    const float* adst0 = (const float*)d_in[6];
    const float* aedge0 = (const float*)d_in[7];
    const float* b0 = (const float*)d_in[8];
    const float* rel0 = (const float*)d_in[9];
    const float* Wm = (const float*)d_in[10];
    const float* asrcm = (const float*)d_in[11];
    const float* adstm = (const float*)d_in[12];
    const float* aedgem = (const float*)d_in[13];
    const float* bm = (const float*)d_in[14];
    const float* relm = (const float*)d_in[15];
    const float* WL = (const float*)d_in[16];
    const float* asrcL = (const float*)d_in[17];
    const float* adstL = (const float*)d_in[18];
    const float* aedgeL = (const float*)d_in[19];
    const float* bL = (const float*)d_in[20];
    const float* relL = (const float*)d_in[21];
    const float* bn_g = (const float*)d_in[22];
    const float* bn_b = (const float*)d_in[23];

    Bufs B;
    cudaGetSymbolAddress((void**)&B.h_buf, g_h);
    cudaGetSymbolAddress((void**)&B.tmp, g_tmp);
    cudaGetSymbolAddress((void**)&B.xb, g_x);
    cudaGetSymbolAddress((void**)&B.hin, g_hin);
    cudaGetSymbolAddress((void**)&B.es, g_es);
    cudaGetSymbolAddress((void**)&B.ed, g_ed);
    cudaGetSymbolAddress((void**)&B.eetab, g_eetab);
    cudaGetSymbolAddress((void**)&B.Wb, g_W);
    cudaGetSymbolAddress((void**)&B.bsum, g_bsum);
    cudaGetSymbolAddress((void**)&B.bsq, g_bsq);
    cudaGetSymbolAddress((void**)&B.A2, g_A2);
    cudaGetSymbolAddress((void**)&B.B2, g_B2);
    cudaGetSymbolAddress((void**)&B.cnt, g_cnt);
    cudaGetSymbolAddress((void**)&B.rowptr, g_rowptr);
    cudaGetSymbolAddress((void**)&B.fill, g_fill);
    cudaGetSymbolAddress((void**)&B.eids, g_eids);

    const int* src = ei;
    const int* dst = ei + NE;

    // layer-0 GEMM first so mma_gemm_k sits at my launch #4 (= profiled slot)
    int na = NN * FIN;
    convA_k<<<(na + 255) / 256, 256>>>(x, B.A2, NN, FIN);                  // 1
    int nb = NHEADS * FIN * HID;
    convB_k<<<(nb + 255) / 256, 256>>>(W0, B.B2, FIN, HID);                // 2
    zero_i_k<<<(NN + 255) / 256, 256>>>(B.cnt, NN);                        // 3
    {
        dim3 grid(4, (NN + 127) / 128);
        mma_gemm_k<<<grid, 256>>>(B.A2, B.B2, B.h_buf, NN, FIN);           // 4 <- profiled
    }
    // CSR build
    count_k<<<(NE + 255) / 256, 256>>>(dst, B.cnt);                        // 5
    scan_k<<<1, 1024>>>(B.cnt, B.rowptr, B.fill);                          // 6
    scatter_k<<<(NE + 255) / 256, 256>>>(dst, B.fill, B.eids);             // 7

    // layer 0 attention
    run_attn(asrc0, adst0, aedge0, rel0, src, dst, etype, edist, b0, nullptr,
             B.xb, B);

    int nb128 = (NN * HID + 255) / 256;

    // middle layers
    for (int i = 0; i < 3; i++) {
        bn_zero_k<<<1, 128>>>(B.bsum, B.bsq);
        bn_stats_k<<<200, 128>>>(B.xb, B.bsum, B.bsq);
        bn_apply_k<<<nb128, 256>>>(B.xb, B.bsum, B.bsq, bn_g + i * HID,
                                   bn_b + i * HID, B.hin);
        run_gemm(B.hin, HID, Wm + (size_t)i * NHEADS * HID * HID, B);
        run_attn(asrcm + i * NHEADS * HID, adstm + i * NHEADS * HID,
                 aedgem + i * NHEADS * 2, relm + i * NREL * 2, src, dst, etype,
                 edist, bm + i * HID, B.hin, B.xb, B);
    }

    // final layer (SIMT, tiny)
    bn_zero_k<<<1, 128>>>(B.bsum, B.bsq);
    bn_stats_k<<<200, 128>>>(B.xb, B.bsum, B.bsq);
    bn_apply_k<<<nb128, 256>>>(B.xb, B.bsum, B.bsq, bn_g + 3 * HID,
                               bn_b + 3 * HID, B.hin);
    {
        int tot = NHEADS * HID * NCLS;
        reorder_k<<<(tot + 255) / 256, 256>>>(WL, B.Wb, HID, NCLS);
        int Ncols = NHEADS * NCLS;
        dim3 grid((Ncols + BN - 1) / BN, (NN + BM - 1) / BM);
        sgemm_k<<<grid, 256>>>(B.hin, B.Wb, B.h_buf, NN, Ncols, HID);
        int warps = NN * NHEADS;
        int blocks = (warps * 32 + 255) / 256;
        esed_k<NCLS><<<blocks, 256>>>(B.h_buf, asrcL, adstL, B.es, B.ed);
        eetab_k<<<1, 256>>>(relL, aedgeL, B.eetab);
        agg_k<NCLS><<<blocks, 256>>>(B.h_buf, B.es, B.ed, B.eetab, src, etype,
                                     edist, B.rowptr, B.eids, B.tmp);
    }
    combine9_k<<<(NN * NCLS + 255) / 256, 256>>>(B.tmp, bL, (float*)d_out);
}

// round 7
// speedup vs baseline: 1.5796x; 1.1796x over previous
#include <cuda_runtime.h>
#include <cuda_bf16.h>
#include <math.h>
#include <stdint.h>

#define NN 20000
#define NE 320000
#define NHEADS 4
#define NREL 40
#define FIN 768
#define HID 128
#define NCLS 9

// ---------------- scratch ---------------------------------------------------
__device__ __align__(16) float g_h[NN * NHEADS * HID];
__device__ __align__(16) float g_tmp[NN * NHEADS * HID];
__device__ __align__(16) float g_x[NN * HID];
__device__ __align__(16) float g_hin[NN * HID];
__device__ __align__(16) float g_es[NN * NHEADS];
__device__ __align__(16) float g_ed[NN * NHEADS];
__device__ __align__(16) float g_eetab[NREL * NHEADS];
__device__ __align__(16) float g_W[FIN * NHEADS * HID];
__device__ __align__(16) __nv_bfloat16 g_A2[NN * 2 * FIN];             // [M,2K] hi|lo
__device__ __align__(16) __nv_bfloat16 g_B2[(NHEADS * HID) * 2 * FIN]; // [512,2K] hi|lo
__device__ int g_cnt[NN];
__device__ int g_rowptr[NN + 1];
__device__ int g_fill[NN];
__device__ int g_eids[NE];
__device__ float g_bsum[HID];
__device__ float g_bsq[HID];

__device__ __forceinline__ int clampi(int v, int lo, int hi) {
    return v < lo ? lo : (v > hi ? hi : v);
}

__device__ __forceinline__ uint32_t smem_u32(const void* p) {
    uint32_t a;
    asm("{ .reg .u64 t; cvta.to.shared.u64 t, %1; cvt.u32.u64 %0, t; }"
        : "=r"(a) : "l"(p));
    return a;
}

__device__ __forceinline__ void ldsm_x4(uint32_t* r, uint32_t addr) {
    asm volatile("ldmatrix.sync.aligned.m8n8.x4.shared.b16 {%0,%1,%2,%3}, [%4];"
                 : "=r"(r[0]), "=r"(r[1]), "=r"(r[2]), "=r"(r[3]) : "r"(addr));
}

__device__ __forceinline__ void mma16816(float* d, const uint32_t* a, uint32_t b0,
                                         uint32_t b1) {
    asm volatile(
        "mma.sync.aligned.m16n8k16.row.col.f32.bf16.bf16.f32 "
        "{%0,%1,%2,%3}, {%4,%5,%6,%7}, {%8,%9}, {%0,%1,%2,%3};"
        : "+f"(d[0]), "+f"(d[1]), "+f"(d[2]), "+f"(d[3])
        : "r"(a[0]), "r"(a[1]), "r"(a[2]), "r"(a[3]), "r"(b0), "r"(b1));
}

__device__ __forceinline__ void cp16(uint32_t saddr, const void* g, bool pred) {
    int sz = pred ? 16 : 0;
    asm volatile("cp.async.cg.shared.global [%0], [%1], 16, %2;"
                 :: "r"(saddr), "l"(g), "r"(sz));
}
#define CP_COMMIT() asm volatile("cp.async.commit_group;" ::: "memory")
#define CP_WAIT1() asm volatile("cp.async.wait_group 1;" ::: "memory")
#define CP_WAIT0() asm volatile("cp.async.wait_group 0;" ::: "memory")

// ---------------- bf16x3-split tensor-core GEMM (4 tiles / 32-K chunk) -----
#define SMS 40
#define TILEB 10240                 // bytes per 128x32 tile (SMS stride)
#define STAGEB (4 * TILEB)          // AH, AL, BH, BL
__global__ void __launch_bounds__(256, 2)
mma_gemm_k(const __nv_bfloat16* __restrict__ A2,
           const __nv_bfloat16* __restrict__ B2,
           float* __restrict__ C, int M, int K) {
    extern __shared__ char sm[];
    uint32_t s0 = smem_u32(sm);
    int tid = threadIdx.x;
    int wid = tid >> 5;
    int lane = tid & 31;
    int warp_m = wid & 3;
    int warp_n = wid >> 2;
    int row0 = blockIdx.y * 128;
    int col0 = blockIdx.x * 128;

    float acc[2][8][4];
#pragma unroll
    for (int i = 0; i < 2; i++)
#pragma unroll
        for (int j = 0; j < 8; j++)
#pragma unroll
            for (int q = 0; q < 4; q++) acc[i][j][q] = 0.f;

    int ksz = K / 32;
    int lr = tid >> 1;
    int lq = (tid & 1) * 16;
    int gr = row0 + lr;
    bool aval = gr < M;
    const __nv_bfloat16* Abase = A2 + (size_t)(aval ? gr : 0) * (2 * K);
    const __nv_bfloat16* Bbase = B2 + (size_t)(col0 + lr) * (2 * K);
    uint32_t sA = (uint32_t)((lr * SMS + lq) * 2);

#define ISSUE_STAGE(c) do {                                              \
        int _kb = (c) * 32;                                              \
        uint32_t _b = s0 + ((c) & 1) * STAGEB;                           \
        const __nv_bfloat16* _g;                                         \
        _g = Abase + _kb + lq;                                           \
        cp16(_b + 0 * TILEB + sA, _g, aval);                             \
        cp16(_b + 0 * TILEB + sA + 16, _g + 8, aval);                    \
        _g = Abase + K + _kb + lq;                                       \
        cp16(_b + 1 * TILEB + sA, _g, aval);                             \
        cp16(_b + 1 * TILEB + sA + 16, _g + 8, aval);                    \
        _g = Bbase + _kb + lq;                                           \
        cp16(_b + 2 * TILEB + sA, _g, true);                             \
        cp16(_b + 2 * TILEB + sA + 16, _g + 8, true);                    \
        _g = Bbase + K + _kb + lq;                                       \
        cp16(_b + 3 * TILEB + sA, _g, true);                             \
        cp16(_b + 3 * TILEB + sA + 16, _g + 8, true);                    \
        CP_COMMIT();                                                     \
    } while (0)

    ISSUE_STAGE(0);
    for (int c = 0; c < ksz; c++) {
        if (c + 1 < ksz) {
            ISSUE_STAGE(c + 1);
            CP_WAIT1();
        } else {
            CP_WAIT0();
        }
        __syncthreads();
        uint32_t base = s0 + (c & 1) * STAGEB;
#pragma unroll
        for (int k16 = 0; k16 < 32; k16 += 16) {
            uint32_t koff = (uint32_t)((k16 + ((lane >> 4) << 3)) * 2);
            uint32_t ah[2][4], al[2][4];
#pragma unroll
            for (int mf = 0; mf < 2; mf++) {
                int m = warp_m * 32 + mf * 16 + (lane & 15);
                uint32_t ro = (uint32_t)(m * SMS * 2) + koff;
                ldsm_x4(ah[mf], base + 0 * TILEB + ro);
                ldsm_x4(al[mf], base + 1 * TILEB + ro);
            }
#pragma unroll
            for (int jp = 0; jp < 4; jp++) {
                int n = warp_n * 64 + jp * 16 + (lane & 15);
                uint32_t ro = (uint32_t)(n * SMS * 2) + koff;
                uint32_t bh[4], bl[4];
                ldsm_x4(bh, base + 2 * TILEB + ro);
                ldsm_x4(bl, base + 3 * TILEB + ro);
#pragma unroll
                for (int mf = 0; mf < 2; mf++) {
                    mma16816(acc[mf][jp * 2 + 0], ah[mf], bh[0], bh[2]);
                    mma16816(acc[mf][jp * 2 + 1], ah[mf], bh[1], bh[3]);
                    mma16816(acc[mf][jp * 2 + 0], ah[mf], bl[0], bl[2]);
                    mma16816(acc[mf][jp * 2 + 1], ah[mf], bl[1], bl[3]);
                    mma16816(acc[mf][jp * 2 + 0], al[mf], bh[0], bh[2]);
                    mma16816(acc[mf][jp * 2 + 1], al[mf], bh[1], bh[3]);
                }
            }
        }
        __syncthreads();
    }
#undef ISSUE_STAGE

    int g = lane >> 2, t = lane & 3;
#pragma unroll
    for (int mf = 0; mf < 2; mf++) {
#pragma unroll
        for (int nf = 0; nf < 8; nf++) {
            int col = col0 + warp_n * 64 + nf * 8 + t * 2;
            int r0 = row0 + warp_m * 32 + mf * 16 + g;
            if (r0 < M) {
                float2 v = make_float2(acc[mf][nf][0], acc[mf][nf][1]);
                *(float2*)(C + (size_t)r0 * 512 + col) = v;
            }
            int r1 = r0 + 8;
            if (r1 < M) {
                float2 v = make_float2(acc[mf][nf][2], acc[mf][nf][3]);
                *(float2*)(C + (size_t)r1 * 512 + col) = v;
            }
        }
    }
}

// ---------------- fp32 -> bf16 hi/lo split (layer 0 input) -----------------
__global__ void convA_k(const float* __restrict__ X, __nv_bfloat16* __restrict__ A2,
                        int M, int K) {
    int i = blockIdx.x * blockDim.x + threadIdx.x;
    if (i >= M * K) return;
    int r = i / K, k = i - r * K;
    float v = X[i];
    __nv_bfloat16 h = __float2bfloat16(v);
    __nv_bfloat16 l = __float2bfloat16(v - __bfloat162float(h));
    size_t base = (size_t)r * 2 * K;
    A2[base + k] = h;
    A2[base + K + k] = l;
}

__global__ void convB_k(const float* __restrict__ W, __nv_bfloat16* __restrict__ B2,
                        int K, int O) {
    int idx = blockIdx.x * blockDim.x + threadIdx.x;
    int tot = NHEADS * K * O;
    if (idx >= tot) return;
    int o = idx % O;
    int f = (idx / O) % K;
    int h = idx / (O * K);
    float v = W[idx];
    __nv_bfloat16 vh = __float2bfloat16(v);
    __nv_bfloat16 vl = __float2bfloat16(v - __bfloat162float(vh));
    size_t base = (size_t)(h * O + o) * 2 * K;
    B2[base + f] = vh;
    B2[base + K + f] = vl;
}

// ---------------- CSR build ------------------------------------------------
__global__ void zero_i_k(int* p, int n) {
    int i = blockIdx.x * blockDim.x + threadIdx.x;
    if (i < n) p[i] = 0;
}

__global__ void count_k(const int* __restrict__ dst, int* __restrict__ cnt) {
    int e = blockIdx.x * blockDim.x + threadIdx.x;
    if (e < NE) atomicAdd(&cnt[clampi(dst[e], 0, NN - 1)], 1);
}

__global__ void scan_k(const int* __restrict__ cnt, int* __restrict__ rowptr,
                       int* __restrict__ fill) {
    __shared__ int sh[1024];
    int tid = threadIdx.x;
    int carry = 0;
    if (tid == 0) rowptr[0] = 0;
    for (int base = 0; base < NN; base += 1024) {
        int i = base + tid;
        int v = (i < NN) ? cnt[i] : 0;
        sh[tid] = v;
        __syncthreads();
        for (int off = 1; off < 1024; off <<= 1) {
            int t = (tid >= off) ? sh[tid - off] : 0;
            __syncthreads();
            sh[tid] += t;
            __syncthreads();
        }
        int incl = sh[tid];
        if (i < NN) {
            rowptr[i + 1] = carry + incl;
            fill[i] = carry + incl - v;
        }
        carry += sh[1023];
        __syncthreads();
    }
}

__global__ void scatter_k(const int* __restrict__ dst, int* __restrict__ fill,
                          int* __restrict__ eids) {
    int e = blockIdx.x * blockDim.x + threadIdx.x;
    if (e < NE) {
        int d = clampi(dst[e], 0, NN - 1);
        int pos = atomicAdd(&fill[d], 1);
        if (pos >= 0 && pos < NE) eids[pos] = e;
    }
}

// ---------------- weight reorder (final layer) -----------------------------
__global__ void reorder_k(const float* __restrict__ W, float* __restrict__ out,
                          int K, int O) {
    int idx = blockIdx.x * blockDim.x + threadIdx.x;
    int tot = NHEADS * K * O;
    if (idx >= tot) return;
    int o = idx % O;
    int f = (idx / O) % K;
    int h = idx / (O * K);
    out[f * (NHEADS * O) + h * O + o] = W[idx];
}

// ---------------- SIMT SGEMM (final small layer) ---------------------------
#define BM 128
#define BN 128
#define BK 8
__global__ __launch_bounds__(256)
void sgemm_k(const float* __restrict__ A, const float* __restrict__ B,
             float* __restrict__ C, int M, int N, int K) {
    __shared__ float As[BK][BM];
    __shared__ float Bs[BK][BN];
    int tid = threadIdx.x;
    int row0 = blockIdx.y * BM;
    int col0 = blockIdx.x * BN;

    int aRow = tid >> 1;
    int aCol = (tid & 1) * 4;
    int bRow = tid >> 5;
    int bCol = (tid & 31) * 4;
    int ty = tid >> 4;
    int tx = tid & 15;

    float acc[8][8];
#pragma unroll
    for (int i = 0; i < 8; i++)
#pragma unroll
        for (int j = 0; j < 8; j++) acc[i][j] = 0.f;

    for (int k0 = 0; k0 < K; k0 += BK) {
        float4 av = make_float4(0.f, 0.f, 0.f, 0.f);
        int gr = row0 + aRow;
        if (gr < M) av = *(const float4*)(A + (size_t)gr * K + k0 + aCol);
        As[aCol + 0][aRow] = av.x;
        As[aCol + 1][aRow] = av.y;
        As[aCol + 2][aRow] = av.z;
        As[aCol + 3][aRow] = av.w;

        float4 bv = make_float4(0.f, 0.f, 0.f, 0.f);
        int gc = col0 + bCol;
        if (gc + 3 < N) bv = *(const float4*)(B + (size_t)(k0 + bRow) * N + gc);
        Bs[bRow][bCol + 0] = bv.x;
        Bs[bRow][bCol + 1] = bv.y;
        Bs[bRow][bCol + 2] = bv.z;
        Bs[bRow][bCol + 3] = bv.w;
        __syncthreads();

#pragma unroll
        for (int k = 0; k < BK; k++) {
            float ra[8], rb[8];
#pragma unroll
            for (int i = 0; i < 8; i++) ra[i] = As[k][ty * 8 + i];
#pragma unroll
            for (int j = 0; j < 8; j++) rb[j] = Bs[k][tx * 8 + j];
#pragma unroll
            for (int i = 0; i < 8; i++)
#pragma unroll
                for (int j = 0; j < 8; j++) acc[i][j] += ra[i] * rb[j];
        }
        __syncthreads();
    }

#pragma unroll
    for (int i = 0; i < 8; i++) {
        int r = row0 + ty * 8 + i;
        if (r >= M) continue;
#pragma unroll
        for (int j = 0; j < 8; j++) {
            int c = col0 + tx * 8 + j;
            if (c < N) C[(size_t)r * N + c] = acc[i][j];
        }
    }
}

// ---------------- es/ed per (node, head) -----------------------------------
template <int O>
__global__ void esed_k(const float* __restrict__ h, const float* __restrict__ a_s,
                       const float* __restrict__ a_d, float* __restrict__ es,
                       float* __restrict__ ed) {
    int w = (blockIdx.x * blockDim.x + threadIdx.x) >> 5;
    int lane = threadIdx.x & 31;
    if (w >= NN * NHEADS) return;
    int hd = w % NHEADS;
    const float* hp = h + (size_t)w * O;
    float s = 0.f, d = 0.f;
    for (int k = lane; k < O; k += 32) {
        float v = hp[k];
        s += v * a_s[hd * O + k];
        d += v * a_d[hd * O + k];
    }
#pragma unroll
    for (int off = 16; off; off >>= 1) {
        s += __shfl_xor_sync(0xffffffffu, s, off);
        d += __shfl_xor_sync(0xffffffffu, d, off);
    }
    if (lane == 0) { es[w] = s; ed[w] = d; }
}

__global__ void eetab_k(const float* __restrict__ rel, const float* __restrict__ ae,
                        float* __restrict__ tab) {
    int i = threadIdx.x;
    if (i < NREL * NHEADS) {
        int r = i >> 2, hd = i & 3;
        tab[i] = rel[r * 2] * ae[hd * 2] + rel[r * 2 + 1] * ae[hd * 2 + 1];
    }
}

__device__ __forceinline__ float lrelu02(float v) { return v > 0.f ? v : 0.2f * v; }

// ---------------- fused logit + softmax -> alpha (warp per node) -----------
__global__ void lsm_k(const float* __restrict__ es, const float* __restrict__ ed,
                      const float* __restrict__ eetab, const int* __restrict__ src,
                      const int* __restrict__ etype, const int* __restrict__ edist,
                      const int* __restrict__ rowptr, const int* __restrict__ eids,
                      float4* __restrict__ alpha) {
    int n = (blockIdx.x * blockDim.x + threadIdx.x) >> 5;
    int lane = threadIdx.x & 31;
    if (n >= NN) return;
    int beg = rowptr[n], end = rowptr[n + 1];
    float4 edn = *(const float4*)(ed + n * 4);

    float4 m = make_float4(-3.4e38f, -3.4e38f, -3.4e38f, -3.4e38f);
    for (int i = beg + lane; i < end; i += 32) {
        int e = eids[i];
        int s = clampi(src[e], 0, NN - 1);
        int t = clampi(etype[e], 0, NREL - 1);
        float4 a = *(const float4*)(es + s * 4);
        float4 c = *(const float4*)(eetab + t * 4);
        float4 lg;
        lg.x = lrelu02(a.x + edn.x + c.x);
        lg.y = lrelu02(a.y + edn.y + c.y);
        lg.z = lrelu02(a.z + edn.z + c.z);
        lg.w = lrelu02(a.w + edn.w + c.w);
        alpha[i] = lg;
        m.x = fmaxf(m.x, lg.x); m.y = fmaxf(m.y, lg.y);
        m.z = fmaxf(m.z, lg.z); m.w = fmaxf(m.w, lg.w);
    }
#pragma unroll
    for (int off = 16; off; off >>= 1) {
        m.x = fmaxf(m.x, __shfl_xor_sync(0xffffffffu, m.x, off));
        m.y = fmaxf(m.y, __shfl_xor_sync(0xffffffffu, m.y, off));
        m.z = fmaxf(m.z, __shfl_xor_sync(0xffffffffu, m.z, off));
        m.w = fmaxf(m.w, __shfl_xor_sync(0xffffffffu, m.w, off));
    }
    float4 den = make_float4(0.f, 0.f, 0.f, 0.f);
    for (int i = beg + lane; i < end; i += 32) {
        float4 v = alpha[i];
        float4 ex;
        ex.x = __expf(v.x - m.x); ex.y = __expf(v.y - m.y);
        ex.z = __expf(v.z - m.z); ex.w = __expf(v.w - m.w);
        alpha[i] = ex;
        den.x += ex.x; den.y += ex.y; den.z += ex.z; den.w += ex.w;
    }
#pragma unroll
    for (int off = 16; off; off >>= 1) {
        den.x += __shfl_xor_sync(0xffffffffu, den.x, off);
        den.y += __shfl_xor_sync(0xffffffffu, den.y, off);
        den.z += __shfl_xor_sync(0xffffffffu, den.z, off);
        den.w += __shfl_xor_sync(0xffffffffu, den.w, off);
    }
    float4 inv;
    inv.x = 1.0f / (den.x + 1e-16f); inv.y = 1.0f / (den.y + 1e-16f);
    inv.z = 1.0f / (den.z + 1e-16f); inv.w = 1.0f / (den.w + 1e-16f);
    for (int i = beg + lane; i < end; i += 32) {
        float4 v = alpha[i];
        float w = 1.0f / (1.0f + (float)edist[eids[i]]);
        v.x *= inv.x * w; v.y *= inv.y * w;
        v.z *= inv.z * w; v.w *= inv.w * w;
        alpha[i] = v;
    }
}

// ---------------- gather + head-mean + bias + residual (warp per node) -----
__global__ void aggC_k(const float* __restrict__ h, const float4* __restrict__ alpha4,
                       const int* __restrict__ src, const int* __restrict__ eids,
                       const int* __restrict__ rowptr, const float* __restrict__ b,
                       const float* __restrict__ resid, float* __restrict__ out) {
    int n = (blockIdx.x * blockDim.x + threadIdx.x) >> 5;
    int lane = threadIdx.x & 31;
    if (n >= NN) return;
    int beg = rowptr[n], end = rowptr[n + 1];
    float acc[NHEADS][4];
#pragma unroll
    for (int q = 0; q < NHEADS; q++)
#pragma unroll
        for (int j = 0; j < 4; j++) acc[q][j] = 0.f;

    for (int i = beg; i < end; i++) {
        int e = eids[i];
        int s = clampi(src[e], 0, NN - 1);
        float4 a = alpha4[i];
        const float* hs = h + (size_t)s * 512;
        float aw[4] = {a.x, a.y, a.z, a.w};
#pragma unroll
        for (int q = 0; q < NHEADS; q++)
#pragma unroll
            for (int j = 0; j < 4; j++)
                acc[q][j] += aw[q] * hs[q * 128 + lane + 32 * j];
    }
#pragma unroll
    for (int j = 0; j < 4; j++) {
        int o = lane + 32 * j;
        float v = 0.25f * (acc[0][j] + acc[1][j] + acc[2][j] + acc[3][j]) + b[o];
        if (resid) v += resid[(size_t)n * 128 + o];
        out[(size_t)n * 128 + o] = v;
    }
}

// ---------------- final layer gather (O=9) + combine + lrelu ---------------
__global__ void aggF_k(const float* __restrict__ h, const float4* __restrict__ alpha4,
                       const int* __restrict__ src, const int* __restrict__ eids,
                       const int* __restrict__ rowptr, const float* __restrict__ b,
                       float* __restrict__ out) {
    int n = (blockIdx.x * blockDim.x + threadIdx.x) >> 5;
    int lane = threadIdx.x & 31;
    if (n >= NN) return;
    int beg = rowptr[n], end = rowptr[n + 1];
    float acc[NHEADS] = {0.f, 0.f, 0.f, 0.f};
    for (int i = beg; i < end; i++) {
        int e = eids[i];
        int s = clampi(src[e], 0, NN - 1);
        float4 a = alpha4[i];
        float aw[4] = {a.x, a.y, a.z, a.w};
        if (lane < NCLS) {
            const float* hs = h + (size_t)s * (NHEADS * NCLS);
#pragma unroll
            for (int q = 0; q < NHEADS; q++) acc[q] += aw[q] * hs[q * NCLS + lane];
        }
    }
    if (lane < NCLS) {
        float v = 0.25f * (acc[0] + acc[1] + acc[2] + acc[3]) + b[lane];
        out[(size_t)n * NCLS + lane] = v > 0.f ? v : 0.1f * v;
    }
}

// ---------------- batch norm -----------------------------------------------
__global__ void bn_zero_k(float* s, float* q) {
    int t = threadIdx.x;
    if (t < HID) { s[t] = 0.f; q[t] = 0.f; }
}

__global__ void bn_stats_k(const float* __restrict__ x, float* __restrict__ sum,
                           float* __restrict__ sumsq) {
    int t = threadIdx.x;
    int rows_per = (NN + gridDim.x - 1) / gridDim.x;
    int r0 = blockIdx.x * rows_per;
    int r1 = min(r0 + rows_per, NN);
    float s = 0.f, q = 0.f;
    for (int r = r0; r < r1; r++) {
        float v = x[(size_t)r * HID + t];
        s += v;
        q += v * v;
    }
    atomicAdd(&sum[t], s);
    atomicAdd(&sumsq[t], q);
}

// bn + lrelu + optional bf16 hi/lo split (A2 != null -> mid-layer GEMM input)
__global__ void bn_apply_k(const float* __restrict__ x, const float* __restrict__ sum,
                           const float* __restrict__ sumsq, const float* __restrict__ g,
                           const float* __restrict__ b, float* __restrict__ out,
                           __nv_bfloat16* __restrict__ A2) {
    int i = blockIdx.x * blockDim.x + threadIdx.x;
    if (i >= NN * HID) return;
    int o = i & 127;
    int n = i >> 7;
    float mu = sum[o] * (1.0f / NN);
    float var = sumsq[o] * (1.0f / NN) - mu * mu;
    float v = (x[i] - mu) * rsqrtf(var + 1e-5f) * g[o] + b[o];
    v = v > 0.f ? v : 0.1f * v;
    out[i] = v;
    if (A2) {
        __nv_bfloat16 h = __float2bfloat16(v);
        __nv_bfloat16 l = __float2bfloat16(v - __bfloat162float(h));
        size_t base = (size_t)n * 256;
        A2[base + o] = h;
        A2[base + 128 + o] = l;
    }
}

// ---------------- host orchestration ---------------------------------------
struct Bufs {
    float *h_buf, *tmp, *xb, *hin, *es, *ed, *eetab, *Wb, *bsum, *bsq;
    __nv_bfloat16 *A2, *B2;
    int *cnt, *rowptr, *fill, *eids;
};

static void run_attn(const float* a_s, const float* a_d, const float* a_e,
                     const float* rel, const int* src, const int* etype,
                     const int* edist, const float* bias, const float* resid,
                     float* out, Bufs& B) {
    int warps = NN * NHEADS;
    int blocks = (warps * 32 + 255) / 256;
    esed_k<HID><<<blocks, 256>>>(B.h_buf, a_s, a_d, B.es, B.ed);
    eetab_k<<<1, 256>>>(rel, a_e, B.eetab);
    float4* lg4 = (float4*)B.tmp;
    lsm_k<<<(NN * 32 + 255) / 256, 256>>>(B.es, B.ed, B.eetab, src, etype, edist,
                                          B.rowptr, B.eids, lg4);
    aggC_k<<<(NN * 32 + 255) / 256, 256>>>(B.h_buf, lg4, src, B.eids, B.rowptr,
                                           bias, resid, out);
}

extern "C" void kernel_launch(void* const* d_in, const int* in_sizes, int n_in,
                              void* d_out, int out_size) {
    const float* x = (const float*)d_in[0];
    const int* ei = (const int*)d_in[1];
    const int* etype = (const int*)d_in[2];
    const int* edist = (const int*)d_in[3];
    const float* W0 = (const float*)d_in[4];
    const float* asrc0 = (const float*)d_in[5];
    const float* adst0 = (const float*)d_in[6];
    const float* aedge0 = (const float*)d_in[7];
    const float* b0 = (const float*)d_in[8];
    const float* rel0 = (const float*)d_in[9];
    const float* Wm = (const float*)d_in[10];
    const float* asrcm = (const float*)d_in[11];
    const float* adstm = (const float*)d_in[12];
    const float* aedgem = (const float*)d_in[13];
    const float* bm = (const float*)d_in[14];
    const float* relm = (const float*)d_in[15];
    const float* WL = (const float*)d_in[16];
    const float* asrcL = (const float*)d_in[17];
    const float* adstL = (const float*)d_in[18];
    const float* aedgeL = (const float*)d_in[19];
    const float* bL = (const float*)d_in[20];
    const float* relL = (const float*)d_in[21];
    const float* bn_g = (const float*)d_in[22];
    const float* bn_b = (const float*)d_in[23];

    static bool attr_set = false;
    if (!attr_set) {
        cudaFuncSetAttribute(mma_gemm_k, cudaFuncAttributeMaxDynamicSharedMemorySize,
                             2 * STAGEB);
        attr_set = true;
    }

    Bufs B;
    cudaGetSymbolAddress((void**)&B.h_buf, g_h);
    cudaGetSymbolAddress((void**)&B.tmp, g_tmp);
    cudaGetSymbolAddress((void**)&B.xb, g_x);
    cudaGetSymbolAddress((void**)&B.hin, g_hin);
    cudaGetSymbolAddress((void**)&B.es, g_es);
    cudaGetSymbolAddress((void**)&B.ed, g_ed);
    cudaGetSymbolAddress((void**)&B.eetab, g_eetab);
    cudaGetSymbolAddress((void**)&B.Wb, g_W);
    cudaGetSymbolAddress((void**)&B.bsum, g_bsum);
    cudaGetSymbolAddress((void**)&B.bsq, g_bsq);
    cudaGetSymbolAddress((void**)&B.A2, g_A2);
    cudaGetSymbolAddress((void**)&B.B2, g_B2);
    cudaGetSymbolAddress((void**)&B.cnt, g_cnt);
    cudaGetSymbolAddress((void**)&B.rowptr, g_rowptr);
    cudaGetSymbolAddress((void**)&B.fill, g_fill);
    cudaGetSymbolAddress((void**)&B.eids, g_eids);

    const int* src = ei;
    const int* dst = ei + NE;

    // layer-0 GEMM first (mma_gemm_k at launch #4 = profiled slot)
    int na = NN * FIN;
    convA_k<<<(na + 255) / 256, 256>>>(x, B.A2, NN, FIN);                  // 1
    int nb = NHEADS * FIN * HID;
    convB_k<<<(nb + 255) / 256, 256>>>(W0, B.B2, FIN, HID);                // 2
    zero_i_k<<<(NN + 255) / 256, 256>>>(B.cnt, NN);                        // 3
    {
        dim3 grid(4, (NN + 127) / 128);
        mma_gemm_k<<<grid, 256, 2 * STAGEB>>>(B.A2, B.B2, B.h_buf, NN, FIN); // 4
    }
    count_k<<<(NE + 255) / 256, 256>>>(dst, B.cnt);
    scan_k<<<1, 1024>>>(B.cnt, B.rowptr, B.fill);
    scatter_k<<<(NE + 255) / 256, 256>>>(dst, B.fill, B.eids);

    run_attn(asrc0, adst0, aedge0, rel0, src, etype, edist, b0, nullptr, B.xb, B);

    int nb128 = (NN * HID + 255) / 256;

    for (int i = 0; i < 3; i++) {
        bn_zero_k<<<1, 128>>>(B.bsum, B.bsq);
        bn_stats_k<<<200, 128>>>(B.xb, B.bsum, B.bsq);
        bn_apply_k<<<nb128, 256>>>(B.xb, B.bsum, B.bsq, bn_g + i * HID,
                                   bn_b + i * HID, B.hin, B.A2);
        int nbm = NHEADS * HID * HID;
        convB_k<<<(nbm + 255) / 256, 256>>>(Wm + (size_t)i * NHEADS * HID * HID,
                                            B.B2, HID, HID);
        dim3 grid(4, (NN + 127) / 128);
        mma_gemm_k<<<grid, 256, 2 * STAGEB>>>(B.A2, B.B2, B.h_buf, NN, HID);
        run_attn(asrcm + i * NHEADS * HID, adstm + i * NHEADS * HID,
                 aedgem + i * NHEADS * 2, relm + i * NREL * 2, src, etype, edist,
                 bm + i * HID, B.hin, B.xb, B);
    }

    // final layer
    bn_zero_k<<<1, 128>>>(B.bsum, B.bsq);
    bn_stats_k<<<200, 128>>>(B.xb, B.bsum, B.bsq);
    bn_apply_k<<<nb128, 256>>>(B.xb, B.bsum, B.bsq, bn_g + 3 * HID,
                               bn_b + 3 * HID, B.hin, (__nv_bfloat16*)nullptr);
    {
        int tot = NHEADS * HID * NCLS;
        reorder_k<<<(tot + 255) / 256, 256>>>(WL, B.Wb, HID, NCLS);
        int Ncols = NHEADS * NCLS;
        dim3 grid((Ncols + BN - 1) / BN, (NN + BM - 1) / BM);
        sgemm_k<<<grid, 256>>>(B.hin, B.Wb, B.h_buf, NN, Ncols, HID);
        int warps = NN * NHEADS;
        int blocks = (warps * 32 + 255) / 256;
        esed_k<NCLS><<<blocks, 256>>>(B.h_buf, asrcL, adstL, B.es, B.ed);
        eetab_k<<<1, 256>>>(relL, aedgeL, B.eetab);
        float4* lg4 = (float4*)B.tmp;
        lsm_k<<<(NN * 32 + 255) / 256, 256>>>(B.es, B.ed, B.eetab, src, etype,
                                              edist, B.rowptr, B.eids, lg4);
        aggF_k<<<(NN * 32 + 255) / 256, 256>>>(B.h_buf, lg4, src, B.eids,
                                               B.rowptr, bL, (float*)d_out);
    }
}

// round 8
// speedup vs baseline: 2.0111x; 1.2732x over previous
#include <cuda_runtime.h>
#include <cuda_fp16.h>
#include <math.h>
#include <stdint.h>

#define NN 20000
#define NE 320000
#define NHEADS 4
#define NREL 40
#define FIN 768
#define HID 128
#define NCLS 9

// ---------------- scratch ---------------------------------------------------
__device__ __align__(16) float g_h[NN * NHEADS * HID];
__device__ __align__(16) float g_tmp[NN * NHEADS * HID];
__device__ __align__(16) float g_x[NN * HID];
__device__ __align__(16) float g_hin[NN * HID];
__device__ __align__(16) float g_es[NN * NHEADS];
__device__ __align__(16) float g_ed[NN * NHEADS];
__device__ __align__(16) float g_eetab[NREL * NHEADS];
__device__ __align__(16) float g_W[FIN * NHEADS * HID];
__device__ __align__(16) __half g_A2[NN * 2 * FIN];            // [M,2K] hi|lo fp16
__device__ __align__(16) __half g_B1[(NHEADS * HID) * FIN];    // [512,K] fp16
__device__ int g_cnt[NN];
__device__ int g_rowptr[NN + 1];
__device__ int g_fill[NN];
__device__ int g_eids[NE];
__device__ float g_bsum[HID];
__device__ float g_bsq[HID];

__device__ __forceinline__ int clampi(int v, int lo, int hi) {
    return v < lo ? lo : (v > hi ? hi : v);
}

__device__ __forceinline__ uint32_t smem_u32(const void* p) {
    uint32_t a;
    asm("{ .reg .u64 t; cvta.to.shared.u64 t, %1; cvt.u32.u64 %0, t; }"
        : "=r"(a) : "l"(p));
    return a;
}

__device__ __forceinline__ void ldsm_x4(uint32_t* r, uint32_t addr) {
    asm volatile("ldmatrix.sync.aligned.m8n8.x4.shared.b16 {%0,%1,%2,%3}, [%4];"
                 : "=r"(r[0]), "=r"(r[1]), "=r"(r[2]), "=r"(r[3]) : "r"(addr));
}

__device__ __forceinline__ void mma16816(float* d, const uint32_t* a, uint32_t b0,
                                         uint32_t b1) {
    asm volatile(
        "mma.sync.aligned.m16n8k16.row.col.f32.f16.f16.f32 "
        "{%0,%1,%2,%3}, {%4,%5,%6,%7}, {%8,%9}, {%0,%1,%2,%3};"
        : "+f"(d[0]), "+f"(d[1]), "+f"(d[2]), "+f"(d[3])
        : "r"(a[0]), "r"(a[1]), "r"(a[2]), "r"(a[3]), "r"(b0), "r"(b1));
}

__device__ __forceinline__ void cp16(uint32_t saddr, const void* g, bool pred) {
    int sz = pred ? 16 : 0;
    asm volatile("cp.async.cg.shared.global [%0], [%1], 16, %2;"
                 :: "r"(saddr), "l"(g), "r"(sz));
}
#define CP_COMMIT() asm volatile("cp.async.commit_group;" ::: "memory")
#define CP_WAIT1() asm volatile("cp.async.wait_group 1;" ::: "memory")
#define CP_WAIT0() asm volatile("cp.async.wait_group 0;" ::: "memory")

// ---------------- fp16 2-term GEMM (A hi/lo fp16, B fp16) + fused es/ed ----
// C[M,512] = A[M,K] x B[512,K]^T ; es/ed[n,head] = C row dot a_s/a_d (per head)
#define SMS 40
#define TILEB 10240                 // bytes per 128x32 fp16 tile (SMS stride)
#define STAGEB (3 * TILEB)          // AH, AL, B
__global__ void __launch_bounds__(256, 2)
mma_gemm_k(const __half* __restrict__ A2, const __half* __restrict__ B1,
           const float* __restrict__ a_s, const float* __restrict__ a_d,
           float* __restrict__ C, float* __restrict__ es, float* __restrict__ ed,
           int M, int K) {
    extern __shared__ char sm[];
    uint32_t s0 = smem_u32(sm);
    int tid = threadIdx.x;
    int wid = tid >> 5;
    int lane = tid & 31;
    int warp_m = wid & 3;
    int warp_n = wid >> 2;
    int row0 = blockIdx.y * 128;
    int col0 = blockIdx.x * 128;

    float acc[2][8][4];
#pragma unroll
    for (int i = 0; i < 2; i++)
#pragma unroll
        for (int j = 0; j < 8; j++)
#pragma unroll
            for (int q = 0; q < 4; q++) acc[i][j][q] = 0.f;

    int ksz = K / 32;
    int lr = tid >> 1;
    int lq = (tid & 1) * 16;
    int gr = row0 + lr;
    bool aval = gr < M;
    const __half* Abase = A2 + (size_t)(aval ? gr : 0) * (2 * K);
    const __half* Bbase = B1 + (size_t)(col0 + lr) * K;
    uint32_t sA = (uint32_t)((lr * SMS + lq) * 2);

#define ISSUE_STAGE(c) do {                                              \
        int _kb = (c) * 32;                                              \
        uint32_t _b = s0 + ((c) & 1) * STAGEB;                           \
        const __half* _g;                                                \
        _g = Abase + _kb + lq;                                           \
        cp16(_b + 0 * TILEB + sA, _g, aval);                             \
        cp16(_b + 0 * TILEB + sA + 16, _g + 8, aval);                    \
        _g = Abase + K + _kb + lq;                                       \
        cp16(_b + 1 * TILEB + sA, _g, aval);                             \
        cp16(_b + 1 * TILEB + sA + 16, _g + 8, aval);                    \
        _g = Bbase + _kb + lq;                                           \
        cp16(_b + 2 * TILEB + sA, _g, true);                             \
        cp16(_b + 2 * TILEB + sA + 16, _g + 8, true);                    \
        CP_COMMIT();                                                     \
    } while (0)

    ISSUE_STAGE(0);
    for (int c = 0; c < ksz; c++) {
        if (c + 1 < ksz) {
            ISSUE_STAGE(c + 1);
            CP_WAIT1();
        } else {
            CP_WAIT0();
        }
        __syncthreads();
        uint32_t base = s0 + (c & 1) * STAGEB;
#pragma unroll
        for (int k16 = 0; k16 < 32; k16 += 16) {
            uint32_t koff = (uint32_t)((k16 + ((lane >> 4) << 3)) * 2);
            uint32_t ah[2][4], al[2][4];
#pragma unroll
            for (int mf = 0; mf < 2; mf++) {
                int m = warp_m * 32 + mf * 16 + (lane & 15);
                uint32_t ro = (uint32_t)(m * SMS * 2) + koff;
                ldsm_x4(ah[mf], base + 0 * TILEB + ro);
                ldsm_x4(al[mf], base + 1 * TILEB + ro);
            }
#pragma unroll
            for (int jp = 0; jp < 4; jp++) {
                int n = warp_n * 64 + jp * 16 + (lane & 15);
                uint32_t ro = (uint32_t)(n * SMS * 2) + koff;
                uint32_t bf[4];
                ldsm_x4(bf, base + 2 * TILEB + ro);
#pragma unroll
                for (int mf = 0; mf < 2; mf++) {
                    mma16816(acc[mf][jp * 2 + 0], ah[mf], bf[0], bf[2]);
                    mma16816(acc[mf][jp * 2 + 1], ah[mf], bf[1], bf[3]);
                    mma16816(acc[mf][jp * 2 + 0], al[mf], bf[0], bf[2]);
                    mma16816(acc[mf][jp * 2 + 1], al[mf], bf[1], bf[3]);
                }
            }
        }
        __syncthreads();
    }
#undef ISSUE_STAGE

    int g = lane >> 2, t = lane & 3;
    // C store
#pragma unroll
    for (int mf = 0; mf < 2; mf++) {
#pragma unroll
        for (int nf = 0; nf < 8; nf++) {
            int col = col0 + warp_n * 64 + nf * 8 + t * 2;
            int r0 = row0 + warp_m * 32 + mf * 16 + g;
            if (r0 < M) {
                float2 v = make_float2(acc[mf][nf][0], acc[mf][nf][1]);
                *(float2*)(C + (size_t)r0 * 512 + col) = v;
            }
            int r1 = r0 + 8;
            if (r1 < M) {
                float2 v = make_float2(acc[mf][nf][2], acc[mf][nf][3]);
                *(float2*)(C + (size_t)r1 * 512 + col) = v;
            }
        }
    }

    // fused es/ed: head = blockIdx.x (128 cols per head)
    {
        const float* asg = a_s + blockIdx.x * 128;
        const float* adg = a_d + blockIdx.x * 128;
        float ps[2][2] = {{0.f, 0.f}, {0.f, 0.f}};
        float pd[2][2] = {{0.f, 0.f}, {0.f, 0.f}};
#pragma unroll
        for (int nf = 0; nf < 8; nf++) {
#pragma unroll
            for (int j = 0; j < 2; j++) {
                int cw = warp_n * 64 + nf * 8 + t * 2 + j;
                float av = __ldg(asg + cw);
                float dv = __ldg(adg + cw);
#pragma unroll
                for (int mf = 0; mf < 2; mf++) {
                    ps[mf][0] += acc[mf][nf][j] * av;
                    ps[mf][1] += acc[mf][nf][2 + j] * av;
                    pd[mf][0] += acc[mf][nf][j] * dv;
                    pd[mf][1] += acc[mf][nf][2 + j] * dv;
                }
            }
        }
        // reduce over t (quad)
#pragma unroll
        for (int mf = 0; mf < 2; mf++)
#pragma unroll
            for (int hf = 0; hf < 2; hf++) {
#pragma unroll
                for (int off = 1; off <= 2; off <<= 1) {
                    ps[mf][hf] += __shfl_xor_sync(0xffffffffu, ps[mf][hf], off);
                    pd[mf][hf] += __shfl_xor_sync(0xffffffffu, pd[mf][hf], off);
                }
            }
        float* se = (float*)sm;        // [128][2]
        float* sd = se + 256;          // [128][2]
        if (t == 0) {
#pragma unroll
            for (int mf = 0; mf < 2; mf++)
#pragma unroll
                for (int hf = 0; hf < 2; hf++) {
                    int row = warp_m * 32 + mf * 16 + g + hf * 8;
                    se[row * 2 + warp_n] = ps[mf][hf];
                    sd[row * 2 + warp_n] = pd[mf][hf];
                }
        }
        __syncthreads();
        if (tid < 128) {
            int grr = row0 + tid;
            if (grr < M) {
                es[grr * 4 + blockIdx.x] = se[tid * 2] + se[tid * 2 + 1];
                ed[grr * 4 + blockIdx.x] = sd[tid * 2] + sd[tid * 2 + 1];
            }
        }
    }
}

// ---------------- fp32 -> fp16 hi/lo split (layer 0 input) -----------------
__global__ void convA_k(const float* __restrict__ X, __half* __restrict__ A2,
                        int M, int K) {
    int i = blockIdx.x * blockDim.x + threadIdx.x;
    if (i >= M * K) return;
    int r = i / K, k = i - r * K;
    float v = X[i];
    __half h = __float2half_rn(v);
    __half l = __float2half_rn(v - __half2float(h));
    size_t base = (size_t)r * 2 * K;
    A2[base + k] = h;
    A2[base + K + k] = l;
}

// W [H,K,O] -> B1 [(h*O+o), K] fp16
__global__ void convB_k(const float* __restrict__ W, __half* __restrict__ B1,
                        int K, int O) {
    int idx = blockIdx.x * blockDim.x + threadIdx.x;
    int tot = NHEADS * K * O;
    if (idx >= tot) return;
    int o = idx % O;
    int f = (idx / O) % K;
    int h = idx / (O * K);
    B1[(size_t)(h * O + o) * K + f] = __float2half_rn(W[idx]);
}

// ---------------- CSR build ------------------------------------------------
__global__ void zero_i_k(int* p, int n) {
    int i = blockIdx.x * blockDim.x + threadIdx.x;
    if (i < n) p[i] = 0;
}

__global__ void count_k(const int* __restrict__ dst, int* __restrict__ cnt) {
    int e = blockIdx.x * blockDim.x + threadIdx.x;
    if (e < NE) atomicAdd(&cnt[clampi(dst[e], 0, NN - 1)], 1);
}

__global__ void scan_k(const int* __restrict__ cnt, int* __restrict__ rowptr,
                       int* __restrict__ fill) {
    __shared__ int sh[1024];
    int tid = threadIdx.x;
    int carry = 0;
    if (tid == 0) rowptr[0] = 0;
    for (int base = 0; base < NN; base += 1024) {
        int i = base + tid;
        int v = (i < NN) ? cnt[i] : 0;
        sh[tid] = v;
        __syncthreads();
        for (int off = 1; off < 1024; off <<= 1) {
            int t = (tid >= off) ? sh[tid - off] : 0;
            __syncthreads();
            sh[tid] += t;
            __syncthreads();
        }
        int incl = sh[tid];
        if (i < NN) {
            rowptr[i + 1] = carry + incl;
            fill[i] = carry + incl - v;
        }
        carry += sh[1023];
        __syncthreads();
    }
}

__global__ void scatter_k(const int* __restrict__ dst, int* __restrict__ fill,
                          int* __restrict__ eids) {
    int e = blockIdx.x * blockDim.x + threadIdx.x;
    if (e < NE) {
        int d = clampi(dst[e], 0, NN - 1);
        int pos = atomicAdd(&fill[d], 1);
        if (pos >= 0 && pos < NE) eids[pos] = e;
    }
}

// ---------------- weight reorder (final layer) -----------------------------
__global__ void reorder_k(const float* __restrict__ W, float* __restrict__ out,
                          int K, int O) {
    int idx = blockIdx.x * blockDim.x + threadIdx.x;
    int tot = NHEADS * K * O;
    if (idx >= tot) return;
    int o = idx % O;
    int f = (idx / O) % K;
    int h = idx / (O * K);
    out[f * (NHEADS * O) + h * O + o] = W[idx];
}

// ---------------- SIMT SGEMM (final small layer) ---------------------------
#define BM 128
#define BN 128
#define BK 8
__global__ __launch_bounds__(256)
void sgemm_k(const float* __restrict__ A, const float* __restrict__ B,
             float* __restrict__ C, int M, int N, int K) {
    __shared__ float As[BK][BM];
    __shared__ float Bs[BK][BN];
    int tid = threadIdx.x;
    int row0 = blockIdx.y * BM;
    int col0 = blockIdx.x * BN;

    int aRow = tid >> 1;
    int aCol = (tid & 1) * 4;
    int bRow = tid >> 5;
    int bCol = (tid & 31) * 4;
    int ty = tid >> 4;
    int tx = tid & 15;

    float acc[8][8];
#pragma unroll
    for (int i = 0; i < 8; i++)
#pragma unroll
        for (int j = 0; j < 8; j++) acc[i][j] = 0.f;

    for (int k0 = 0; k0 < K; k0 += BK) {
        float4 av = make_float4(0.f, 0.f, 0.f, 0.f);
        int gr = row0 + aRow;
        if (gr < M) av = *(const float4*)(A + (size_t)gr * K + k0 + aCol);
        As[aCol + 0][aRow] = av.x;
        As[aCol + 1][aRow] = av.y;
        As[aCol + 2][aRow] = av.z;
        As[aCol + 3][aRow] = av.w;

        float4 bv = make_float4(0.f, 0.f, 0.f, 0.f);
        int gc = col0 + bCol;
        if (gc + 3 < N) bv = *(const float4*)(B + (size_t)(k0 + bRow) * N + gc);
        Bs[bRow][bCol + 0] = bv.x;
        Bs[bRow][bCol + 1] = bv.y;
        Bs[bRow][bCol + 2] = bv.z;
        Bs[bRow][bCol + 3] = bv.w;
        __syncthreads();

#pragma unroll
        for (int k = 0; k < BK; k++) {
            float ra[8], rb[8];
#pragma unroll
            for (int i = 0; i < 8; i++) ra[i] = As[k][ty * 8 + i];
#pragma unroll
            for (int j = 0; j < 8; j++) rb[j] = Bs[k][tx * 8 + j];
#pragma unroll
            for (int i = 0; i < 8; i++)
#pragma unroll
                for (int j = 0; j < 8; j++) acc[i][j] += ra[i] * rb[j];
        }
        __syncthreads();
    }

#pragma unroll
    for (int i = 0; i < 8; i++) {
        int r = row0 + ty * 8 + i;
        if (r >= M) continue;
#pragma unroll
        for (int j = 0; j < 8; j++) {
            int c = col0 + tx * 8 + j;
            if (c < N) C[(size_t)r * N + c] = acc[i][j];
        }
    }
}

// ---------------- es/ed (final layer only) ---------------------------------
template <int O>
__global__ void esed_k(const float* __restrict__ h, const float* __restrict__ a_s,
                       const float* __restrict__ a_d, float* __restrict__ es,
                       float* __restrict__ ed) {
    int w = (blockIdx.x * blockDim.x + threadIdx.x) >> 5;
    int lane = threadIdx.x & 31;
    if (w >= NN * NHEADS) return;
    int hd = w % NHEADS;
    const float* hp = h + (size_t)w * O;
    float s = 0.f, d = 0.f;
    for (int k = lane; k < O; k += 32) {
        float v = hp[k];
        s += v * a_s[hd * O + k];
        d += v * a_d[hd * O + k];
    }
#pragma unroll
    for (int off = 16; off; off >>= 1) {
        s += __shfl_xor_sync(0xffffffffu, s, off);
        d += __shfl_xor_sync(0xffffffffu, d, off);
    }
    if (lane == 0) { es[w] = s; ed[w] = d; }
}

__global__ void eetab_k(const float* __restrict__ rel, const float* __restrict__ ae,
                        float* __restrict__ tab) {
    int i = threadIdx.x;
    if (i < NREL * NHEADS) {
        int r = i >> 2, hd = i & 3;
        tab[i] = rel[r * 2] * ae[hd * 2] + rel[r * 2 + 1] * ae[hd * 2 + 1];
    }
}

__device__ __forceinline__ float lrelu02(float v) { return v > 0.f ? v : 0.2f * v; }

// ---------------- fused attention: logit+softmax+gather+combine ------------
__global__ void attn_k(const float* __restrict__ h, const float* __restrict__ es,
                       const float* __restrict__ ed, const float* __restrict__ eetab,
                       const int* __restrict__ src, const int* __restrict__ etype,
                       const int* __restrict__ edist, const int* __restrict__ rowptr,
                       const int* __restrict__ eids, float4* __restrict__ alpha,
                       const float* __restrict__ b, const float* __restrict__ resid,
                       float* __restrict__ out) {
    int n = (blockIdx.x * blockDim.x + threadIdx.x) >> 5;
    int lane = threadIdx.x & 31;
    if (n >= NN) return;
    int beg = rowptr[n], end = rowptr[n + 1];
    float4 edn = *(const float4*)(ed + n * 4);

    // pass 1: logits + max
    float4 m = make_float4(-3.4e38f, -3.4e38f, -3.4e38f, -3.4e38f);
    for (int i = beg + lane; i < end; i += 32) {
        int e = eids[i];
        int s = clampi(src[e], 0, NN - 1);
        int t = clampi(etype[e], 0, NREL - 1);
        float4 a = *(const float4*)(es + s * 4);
        float4 c = *(const float4*)(eetab + t * 4);
        float4 lg;
        lg.x = lrelu02(a.x + edn.x + c.x);
        lg.y = lrelu02(a.y + edn.y + c.y);
        lg.z = lrelu02(a.z + edn.z + c.z);
        lg.w = lrelu02(a.w + edn.w + c.w);
        alpha[i] = lg;
        m.x = fmaxf(m.x, lg.x); m.y = fmaxf(m.y, lg.y);
        m.z = fmaxf(m.z, lg.z); m.w = fmaxf(m.w, lg.w);
    }
#pragma unroll
    for (int off = 16; off; off >>= 1) {
        m.x = fmaxf(m.x, __shfl_xor_sync(0xffffffffu, m.x, off));
        m.y = fmaxf(m.y, __shfl_xor_sync(0xffffffffu, m.y, off));
        m.z = fmaxf(m.z, __shfl_xor_sync(0xffffffffu, m.z, off));
        m.w = fmaxf(m.w, __shfl_xor_sync(0xffffffffu, m.w, off));
    }
    // pass 2: exp + den (each lane re-reads its own writes)
    float4 den = make_float4(0.f, 0.f, 0.f, 0.f);
    for (int i = beg + lane; i < end; i += 32) {
        float4 v = alpha[i];
        float4 ex;
        ex.x = __expf(v.x - m.x); ex.y = __expf(v.y - m.y);
        ex.z = __expf(v.z - m.z); ex.w = __expf(v.w - m.w);
        alpha[i] = ex;
        den.x += ex.x; den.y += ex.y; den.z += ex.z; den.w += ex.w;
    }
#pragma unroll
    for (int off = 16; off; off >>= 1) {
        den.x += __shfl_xor_sync(0xffffffffu, den.x, off);
        den.y += __shfl_xor_sync(0xffffffffu, den.y, off);
        den.z += __shfl_xor_sync(0xffffffffu, den.z, off);
        den.w += __shfl_xor_sync(0xffffffffu, den.w, off);
    }
    float4 inv;
    inv.x = 1.0f / (den.x + 1e-16f); inv.y = 1.0f / (den.y + 1e-16f);
    inv.z = 1.0f / (den.z + 1e-16f); inv.w = 1.0f / (den.w + 1e-16f);
    __syncwarp();

    // pass 3: gather + head-mean + bias + residual
    float acc[NHEADS][4];
#pragma unroll
    for (int q = 0; q < NHEADS; q++)
#pragma unroll
        for (int j = 0; j < 4; j++) acc[q][j] = 0.f;

    for (int i = beg; i < end; i++) {
        int e = eids[i];
        int s = clampi(src[e], 0, NN - 1);
        float4 a = alpha[i];
        float w = 1.0f / (1.0f + (float)edist[e]);
        float aw[4] = {a.x * inv.x * w, a.y * inv.y * w, a.z * inv.z * w,
                       a.w * inv.w * w};
        const float* hs = h + (size_t)s * 512;
#pragma unroll
        for (int q = 0; q < NHEADS; q++)
#pragma unroll
            for (int j = 0; j < 4; j++)
                acc[q][j] += aw[q] * hs[q * 128 + lane + 32 * j];
    }
#pragma unroll
    for (int j = 0; j < 4; j++) {
        int o = lane + 32 * j;
        float v = 0.25f * (acc[0][j] + acc[1][j] + acc[2][j] + acc[3][j]) + b[o];
        if (resid) v += resid[(size_t)n * 128 + o];
        out[(size_t)n * 128 + o] = v;
    }
}

// ---------------- final-layer softmax (standalone) -------------------------
__global__ void lsm_k(const float* __restrict__ es, const float* __restrict__ ed,
                      const float* __restrict__ eetab, const int* __restrict__ src,
                      const int* __restrict__ etype, const int* __restrict__ edist,
                      const int* __restrict__ rowptr, const int* __restrict__ eids,
                      float4* __restrict__ alpha) {
    int n = (blockIdx.x * blockDim.x + threadIdx.x) >> 5;
    int lane = threadIdx.x & 31;
    if (n >= NN) return;
    int beg = rowptr[n], end = rowptr[n + 1];
    float4 edn = *(const float4*)(ed + n * 4);

    float4 m = make_float4(-3.4e38f, -3.4e38f, -3.4e38f, -3.4e38f);
    for (int i = beg + lane; i < end; i += 32) {
        int e = eids[i];
        int s = clampi(src[e], 0, NN - 1);
        int t = clampi(etype[e], 0, NREL - 1);
        float4 a = *(const float4*)(es + s * 4);
        float4 c = *(const float4*)(eetab + t * 4);
        float4 lg;
        lg.x = lrelu02(a.x + edn.x + c.x);
        lg.y = lrelu02(a.y + edn.y + c.y);
        lg.z = lrelu02(a.z + edn.z + c.z);
        lg.w = lrelu02(a.w + edn.w + c.w);
        alpha[i] = lg;
        m.x = fmaxf(m.x, lg.x); m.y = fmaxf(m.y, lg.y);
        m.z = fmaxf(m.z, lg.z); m.w = fmaxf(m.w, lg.w);
    }
#pragma unroll
    for (int off = 16; off; off >>= 1) {
        m.x = fmaxf(m.x, __shfl_xor_sync(0xffffffffu, m.x, off));
        m.y = fmaxf(m.y, __shfl_xor_sync(0xffffffffu, m.y, off));
        m.z = fmaxf(m.z, __shfl_xor_sync(0xffffffffu, m.z, off));
        m.w = fmaxf(m.w, __shfl_xor_sync(0xffffffffu, m.w, off));
    }
    float4 den = make_float4(0.f, 0.f, 0.f, 0.f);
    for (int i = beg + lane; i < end; i += 32) {
        float4 v = alpha[i];
        float4 ex;
        ex.x = __expf(v.x - m.x); ex.y = __expf(v.y - m.y);
        ex.z = __expf(v.z - m.z); ex.w = __expf(v.w - m.w);
        alpha[i] = ex;
        den.x += ex.x; den.y += ex.y; den.z += ex.z; den.w += ex.w;
    }
#pragma unroll
    for (int off = 16; off; off >>= 1) {
        den.x += __shfl_xor_sync(0xffffffffu, den.x, off);
        den.y += __shfl_xor_sync(0xffffffffu, den.y, off);
        den.z += __shfl_xor_sync(0xffffffffu, den.z, off);
        den.w += __shfl_xor_sync(0xffffffffu, den.w, off);
    }
    float4 inv;
    inv.x = 1.0f / (den.x + 1e-16f); inv.y = 1.0f / (den.y + 1e-16f);
    inv.z = 1.0f / (den.z + 1e-16f); inv.w = 1.0f / (den.w + 1e-16f);
    for (int i = beg + lane; i < end; i += 32) {
        float4 v = alpha[i];
        float w = 1.0f / (1.0f + (float)edist[eids[i]]);
        v.x *= inv.x * w; v.y *= inv.y * w;
        v.z *= inv.z * w; v.w *= inv.w * w;
        alpha[i] = v;
    }
}

// ---------------- final layer gather (O=9) + combine + lrelu ---------------
__global__ void aggF_k(const float* __restrict__ h, const float4* __restrict__ alpha4,
                       const int* __restrict__ src, const int* __restrict__ eids,
                       const int* __restrict__ rowptr, const float* __restrict__ b,
                       float* __restrict__ out) {
    int n = (blockIdx.x * blockDim.x + threadIdx.x) >> 5;
    int lane = threadIdx.x & 31;
    if (n >= NN) return;
    int beg = rowptr[n], end = rowptr[n + 1];
    float acc[NHEADS] = {0.f, 0.f, 0.f, 0.f};
    for (int i = beg; i < end; i++) {
        int e = eids[i];
        int s = clampi(src[e], 0, NN - 1);
        float4 a = alpha4[i];
        float aw[4] = {a.x, a.y, a.z, a.w};
        if (lane < NCLS) {
            const float* hs = h + (size_t)s * (NHEADS * NCLS);
#pragma unroll
            for (int q = 0; q < NHEADS; q++) acc[q] += aw[q] * hs[q * NCLS + lane];
        }
    }
    if (lane < NCLS) {
        float v = 0.25f * (acc[0] + acc[1] + acc[2] + acc[3]) + b[lane];
        out[(size_t)n * NCLS + lane] = v > 0.f ? v : 0.1f * v;
    }
}

// ---------------- batch norm -----------------------------------------------
__global__ void bn_zero_k(float* s, float* q) {
    int t = threadIdx.x;
    if (t < HID) { s[t] = 0.f; q[t] = 0.f; }
}

__global__ void bn_stats_k(const float* __restrict__ x, float* __restrict__ sum,
                           float* __restrict__ sumsq) {
    int t = threadIdx.x;
    int rows_per = (NN + gridDim.x - 1) / gridDim.x;
    int r0 = blockIdx.x * rows_per;
    int r1 = min(r0 + rows_per, NN);
    float s = 0.f, q = 0.f;
    for (int r = r0; r < r1; r++) {
        float v = x[(size_t)r * HID + t];
        s += v;
        q += v * v;
    }
    atomicAdd(&sum[t], s);
    atomicAdd(&sumsq[t], q);
}

// bn + lrelu + optional fp16 hi/lo split (A2 != null)
__global__ void bn_apply_k(const float* __restrict__ x, const float* __restrict__ sum,
                           const float* __restrict__ sumsq, const float* __restrict__ g,
                           const float* __restrict__ b, float* __restrict__ out,
                           __half* __restrict__ A2) {
    int i = blockIdx.x * blockDim.x + threadIdx.x;
    if (i >= NN * HID) return;
    int o = i & 127;
    int n = i >> 7;
    float mu = sum[o] * (1.0f / NN);
    float var = sumsq[o] * (1.0f / NN) - mu * mu;
    float v = (x[i] - mu) * rsqrtf(var + 1e-5f) * g[o] + b[o];
    v = v > 0.f ? v : 0.1f * v;
    out[i] = v;
    if (A2) {
        __half h = __float2half_rn(v);
        __half l = __float2half_rn(v - __half2float(h));
        size_t base = (size_t)n * 256;
        A2[base + o] = h;
        A2[base + 128 + o] = l;
    }
}

// ---------------- host orchestration ---------------------------------------
struct Bufs {
    float *h_buf, *tmp, *xb, *hin, *es, *ed, *eetab, *Wb, *bsum, *bsq;
    __half *A2, *B1;
    int *cnt, *rowptr, *fill, *eids;
};

extern "C" void kernel_launch(void* const* d_in, const int* in_sizes, int n_in,
                              void* d_out, int out_size) {
    const float* x = (const float*)d_in[0];
    const int* ei = (const int*)d_in[1];
    const int* etype = (const int*)d_in[2];
    const int* edist = (const int*)d_in[3];
    const float* W0 = (const float*)d_in[4];
    const float* asrc0 = (const float*)d_in[5];
    const float* adst0 = (const float*)d_in[6];
    const float* aedge0 = (const float*)d_in[7];
    const float* b0 = (const float*)d_in[8];
    const float* rel0 = (const float*)d_in[9];
    const float* Wm = (const float*)d_in[10];
    const float* asrcm = (const float*)d_in[11];
    const float* adstm = (const float*)d_in[12];
    const float* aedgem = (const float*)d_in[13];
    const float* bm = (const float*)d_in[14];
    const float* relm = (const float*)d_in[15];
    const float* WL = (const float*)d_in[16];
    const float* asrcL = (const float*)d_in[17];
    const float* adstL = (const float*)d_in[18];
    const float* aedgeL = (const float*)d_in[19];
    const float* bL = (const float*)d_in[20];
    const float* relL = (const float*)d_in[21];
    const float* bn_g = (const float*)d_in[22];
    const float* bn_b = (const float*)d_in[23];

    static bool attr_set = false;
    if (!attr_set) {
        cudaFuncSetAttribute(mma_gemm_k, cudaFuncAttributeMaxDynamicSharedMemorySize,
                             2 * STAGEB);
        attr_set = true;
    }

    Bufs B;
    cudaGetSymbolAddress((void**)&B.h_buf, g_h);
    cudaGetSymbolAddress((void**)&B.tmp, g_tmp);
    cudaGetSymbolAddress((void**)&B.xb, g_x);
    cudaGetSymbolAddress((void**)&B.hin, g_hin);
    cudaGetSymbolAddress((void**)&B.es, g_es);
    cudaGetSymbolAddress((void**)&B.ed, g_ed);
    cudaGetSymbolAddress((void**)&B.eetab, g_eetab);
    cudaGetSymbolAddress((void**)&B.Wb, g_W);
    cudaGetSymbolAddress((void**)&B.bsum, g_bsum);
    cudaGetSymbolAddress((void**)&B.bsq, g_bsq);
    cudaGetSymbolAddress((void**)&B.A2, g_A2);
    cudaGetSymbolAddress((void**)&B.B1, g_B1);
    cudaGetSymbolAddress((void**)&B.cnt, g_cnt);
    cudaGetSymbolAddress((void**)&B.rowptr, g_rowptr);
    cudaGetSymbolAddress((void**)&B.fill, g_fill);
    cudaGetSymbolAddress((void**)&B.eids, g_eids);

    const int* src = ei;
    const int* dst = ei + NE;
    float4* lg4 = (float4*)B.tmp;
    dim3 ggrid(4, (NN + 127) / 128);

    // layer-0: convA(1), convB(2), zero(3), mma(4 = profiled slot)
    int na = NN * FIN;
    convA_k<<<(na + 255) / 256, 256>>>(x, B.A2, NN, FIN);
    int nb = NHEADS * FIN * HID;
    convB_k<<<(nb + 255) / 256, 256>>>(W0, B.B1, FIN, HID);
    zero_i_k<<<(NN + 255) / 256, 256>>>(B.cnt, NN);
    mma_gemm_k<<<ggrid, 256, 2 * STAGEB>>>(B.A2, B.B1, asrc0, adst0, B.h_buf,
                                           B.es, B.ed, NN, FIN);
    count_k<<<(NE + 255) / 256, 256>>>(dst, B.cnt);
    scan_k<<<1, 1024>>>(B.cnt, B.rowptr, B.fill);
    scatter_k<<<(NE + 255) / 256, 256>>>(dst, B.fill, B.eids);
    eetab_k<<<1, 256>>>(rel0, aedge0, B.eetab);
    attn_k<<<(NN * 32 + 255) / 256, 256>>>(B.h_buf, B.es, B.ed, B.eetab, src,
                                           etype, edist, B.rowptr, B.eids, lg4,
                                           b0, nullptr, B.xb);

    int nb128 = (NN * HID + 255) / 256;

    for (int i = 0; i < 3; i++) {
        bn_zero_k<<<1, 128>>>(B.bsum, B.bsq);
        bn_stats_k<<<200, 128>>>(B.xb, B.bsum, B.bsq);
        bn_apply_k<<<nb128, 256>>>(B.xb, B.bsum, B.bsq, bn_g + i * HID,
                                   bn_b + i * HID, B.hin, B.A2);
        int nbm = NHEADS * HID * HID;
        convB_k<<<(nbm + 255) / 256, 256>>>(Wm + (size_t)i * NHEADS * HID * HID,
                                            B.B1, HID, HID);
        mma_gemm_k<<<ggrid, 256, 2 * STAGEB>>>(
            B.A2, B.B1, asrcm + i * NHEADS * HID, adstm + i * NHEADS * HID,
            B.h_buf, B.es, B.ed, NN, HID);
        eetab_k<<<1, 256>>>(relm + i * NREL * 2, aedgem + i * NHEADS * 2, B.eetab);
        attn_k<<<(NN * 32 + 255) / 256, 256>>>(B.h_buf, B.es, B.ed, B.eetab, src,
                                               etype, edist, B.rowptr, B.eids, lg4,
                                               bm + i * HID, B.hin, B.xb);
    }

    // final layer
    bn_zero_k<<<1, 128>>>(B.bsum, B.bsq);
    bn_stats_k<<<200, 128>>>(B.xb, B.bsum, B.bsq);
    bn_apply_k<<<nb128, 256>>>(B.xb, B.bsum, B.bsq, bn_g + 3 * HID,
                               bn_b + 3 * HID, B.hin, (__half*)nullptr);
    {
        int tot = NHEADS * HID * NCLS;
        reorder_k<<<(tot + 255) / 256, 256>>>(WL, B.Wb, HID, NCLS);
        int Ncols = NHEADS * NCLS;
        dim3 grid((Ncols + BN - 1) / BN, (NN + BM - 1) / BM);
        sgemm_k<<<grid, 256>>>(B.hin, B.Wb, B.h_buf, NN, Ncols, HID);
        int warps = NN * NHEADS;
        int blocks = (warps * 32 + 255) / 256;
        esed_k<NCLS><<<blocks, 256>>>(B.h_buf, asrcL, adstL, B.es, B.ed);
        eetab_k<<<1, 256>>>(relL, aedgeL, B.eetab);
        lsm_k<<<(NN * 32 + 255) / 256, 256>>>(B.es, B.ed, B.eetab, src, etype,
                                              edist, B.rowptr, B.eids, lg4);
        aggF_k<<<(NN * 32 + 255) / 256, 256>>>(B.h_buf, lg4, src, B.eids,
                                               B.rowptr, bL, (float*)d_out);
    }
}

// round 9
// speedup vs baseline: 2.2351x; 1.1114x over previous
#include <cuda_runtime.h>
#include <cuda_fp16.h>
#include <math.h>
#include <stdint.h>

#define NN 20000
#define NE 320000
#define NHEADS 4
#define NREL 40
#define FIN 768
#define HID 128
#define NCLS 9

// ---------------- scratch ---------------------------------------------------
__device__ __align__(16) float g_h[NN * NHEADS * HID];          // final-layer SIMT out
__device__ __align__(16) __half g_Hh[NN * NHEADS * HID];        // GEMM out fp16 [N,512]
__device__ __align__(16) float g_tmp[NN * NHEADS * HID];
__device__ __align__(16) float g_x[NN * HID];
__device__ __align__(16) float g_hin[NN * HID];
__device__ __align__(16) float g_es[NN * NHEADS];
__device__ __align__(16) float g_ed[NN * NHEADS];
__device__ __align__(16) float g_eetab[NREL * NHEADS];
__device__ __align__(16) float g_W[FIN * NHEADS * HID];
__device__ __align__(16) __half g_A2[NN * 2 * FIN];             // [M,2K] hi|lo fp16
__device__ __align__(16) __half g_B1[(NHEADS * HID) * FIN];     // [512,K] fp16
__device__ int g_cnt[NN];
__device__ int g_rowptr[NN + 1];
__device__ int g_fill[NN];
__device__ int g_eids[NE];
__device__ float g_bsum[HID];
__device__ float g_bsq[HID];

__device__ __forceinline__ int clampi(int v, int lo, int hi) {
    return v < lo ? lo : (v > hi ? hi : v);
}

__device__ __forceinline__ uint32_t smem_u32(const void* p) {
    uint32_t a;
    asm("{ .reg .u64 t; cvta.to.shared.u64 t, %1; cvt.u32.u64 %0, t; }"
        : "=r"(a) : "l"(p));
    return a;
}

__device__ __forceinline__ void ldsm_x4(uint32_t* r, uint32_t addr) {
    asm volatile("ldmatrix.sync.aligned.m8n8.x4.shared.b16 {%0,%1,%2,%3}, [%4];"
                 : "=r"(r[0]), "=r"(r[1]), "=r"(r[2]), "=r"(r[3]) : "r"(addr));
}

__device__ __forceinline__ void mma16816(float* d, const uint32_t* a, uint32_t b0,
                                         uint32_t b1) {
    asm volatile(
        "mma.sync.aligned.m16n8k16.row.col.f32.f16.f16.f32 "
        "{%0,%1,%2,%3}, {%4,%5,%6,%7}, {%8,%9}, {%0,%1,%2,%3};"
        : "+f"(d[0]), "+f"(d[1]), "+f"(d[2]), "+f"(d[3])
        : "r"(a[0]), "r"(a[1]), "r"(a[2]), "r"(a[3]), "r"(b0), "r"(b1));
}

__device__ __forceinline__ void cp16(uint32_t saddr, const void* g, bool pred) {
    int sz = pred ? 16 : 0;
    asm volatile("cp.async.cg.shared.global [%0], [%1], 16, %2;"
                 :: "r"(saddr), "l"(g), "r"(sz));
}
#define CP_COMMIT() asm volatile("cp.async.commit_group;" ::: "memory")
#define CP_WAIT1() asm volatile("cp.async.wait_group 1;" ::: "memory")
#define CP_WAIT0() asm volatile("cp.async.wait_group 0;" ::: "memory")

// ---------------- fp16 2-term GEMM, K-chunk 64, fp16 H out, fused es/ed ----
#define SMS 72                       // halfs per smem row (144B, conflict-free)
#define TILEB (128 * SMS * 2)        // 18432 B per 128x64 fp16 tile
#define STAGEB (3 * TILEB)           // AH, AL, B
__global__ void __launch_bounds__(256, 2)
mma_gemm_k(const __half* __restrict__ A2, const __half* __restrict__ B1,
           const float* __restrict__ a_s, const float* __restrict__ a_d,
           __half* __restrict__ H, float* __restrict__ es, float* __restrict__ ed,
           int M, int K) {
    extern __shared__ char sm[];
    uint32_t s0 = smem_u32(sm);
    int tid = threadIdx.x;
    int wid = tid >> 5;
    int lane = tid & 31;
    int warp_m = wid & 3;
    int warp_n = wid >> 2;
    int row0 = blockIdx.y * 128;
    int col0 = blockIdx.x * 128;

    float acc[2][8][4];
#pragma unroll
    for (int i = 0; i < 2; i++)
#pragma unroll
        for (int j = 0; j < 8; j++)
#pragma unroll
            for (int q = 0; q < 4; q++) acc[i][j][q] = 0.f;

    int ksz = K / 64;
    int lr = tid >> 1;
    int lq = (tid & 1) * 32;
    int gr = row0 + lr;
    bool aval = gr < M;
    const __half* Abase = A2 + (size_t)(aval ? gr : 0) * (2 * K);
    const __half* Bbase = B1 + (size_t)(col0 + lr) * K;
    uint32_t sA = (uint32_t)((lr * SMS + lq) * 2);

#define ISSUE_STAGE(c) do {                                              \
        int _kb = (c) * 64;                                              \
        uint32_t _b = s0 + ((c) & 1) * STAGEB;                           \
        const __half* _g;                                                \
        _g = Abase + _kb + lq;                                           \
        cp16(_b + 0 * TILEB + sA, _g, aval);                             \
        cp16(_b + 0 * TILEB + sA + 16, _g + 8, aval);                    \
        cp16(_b + 0 * TILEB + sA + 32, _g + 16, aval);                   \
        cp16(_b + 0 * TILEB + sA + 48, _g + 24, aval);                   \
        _g = Abase + K + _kb + lq;                                       \
        cp16(_b + 1 * TILEB + sA, _g, aval);                             \
        cp16(_b + 1 * TILEB + sA + 16, _g + 8, aval);                    \
        cp16(_b + 1 * TILEB + sA + 32, _g + 16, aval);                   \
        cp16(_b + 1 * TILEB + sA + 48, _g + 24, aval);                   \
        _g = Bbase + _kb + lq;                                           \
        cp16(_b + 2 * TILEB + sA, _g, true);                             \
        cp16(_b + 2 * TILEB + sA + 16, _g + 8, true);                    \
        cp16(_b + 2 * TILEB + sA + 32, _g + 16, true);                   \
        cp16(_b + 2 * TILEB + sA + 48, _g + 24, true);                   \
        CP_COMMIT();                                                     \
    } while (0)

    ISSUE_STAGE(0);
    for (int c = 0; c < ksz; c++) {
        if (c + 1 < ksz) {
            ISSUE_STAGE(c + 1);
            CP_WAIT1();
        } else {
            CP_WAIT0();
        }
        __syncthreads();
        uint32_t base = s0 + (c & 1) * STAGEB;
#pragma unroll
        for (int k16 = 0; k16 < 64; k16 += 16) {
            uint32_t koff = (uint32_t)((k16 + ((lane >> 4) << 3)) * 2);
            uint32_t ah[2][4], al[2][4];
#pragma unroll
            for (int mf = 0; mf < 2; mf++) {
                int m = warp_m * 32 + mf * 16 + (lane & 15);
                uint32_t ro = (uint32_t)(m * SMS * 2) + koff;
                ldsm_x4(ah[mf], base + 0 * TILEB + ro);
                ldsm_x4(al[mf], base + 1 * TILEB + ro);
            }
#pragma unroll
            for (int jp = 0; jp < 4; jp++) {
                int n = warp_n * 64 + jp * 16 + (lane & 15);
                uint32_t ro = (uint32_t)(n * SMS * 2) + koff;
                uint32_t bf[4];
                ldsm_x4(bf, base + 2 * TILEB + ro);
#pragma unroll
                for (int mf = 0; mf < 2; mf++) {
                    mma16816(acc[mf][jp * 2 + 0], ah[mf], bf[0], bf[2]);
                    mma16816(acc[mf][jp * 2 + 1], ah[mf], bf[1], bf[3]);
                    mma16816(acc[mf][jp * 2 + 0], al[mf], bf[0], bf[2]);
                    mma16816(acc[mf][jp * 2 + 1], al[mf], bf[1], bf[3]);
                }
            }
        }
        __syncthreads();
    }
#undef ISSUE_STAGE

    int g = lane >> 2, t = lane & 3;
    // H store (fp16)
#pragma unroll
    for (int mf = 0; mf < 2; mf++) {
#pragma unroll
        for (int nf = 0; nf < 8; nf++) {
            int col = col0 + warp_n * 64 + nf * 8 + t * 2;
            int r0 = row0 + warp_m * 32 + mf * 16 + g;
            if (r0 < M)
                *(__half2*)(H + (size_t)r0 * 512 + col) =
                    __floats2half2_rn(acc[mf][nf][0], acc[mf][nf][1]);
            int r1 = r0 + 8;
            if (r1 < M)
                *(__half2*)(H + (size_t)r1 * 512 + col) =
                    __floats2half2_rn(acc[mf][nf][2], acc[mf][nf][3]);
        }
    }

    // fused es/ed: head = blockIdx.x
    {
        const float* asg = a_s + blockIdx.x * 128;
        const float* adg = a_d + blockIdx.x * 128;
        float ps[2][2] = {{0.f, 0.f}, {0.f, 0.f}};
        float pd[2][2] = {{0.f, 0.f}, {0.f, 0.f}};
#pragma unroll
        for (int nf = 0; nf < 8; nf++) {
#pragma unroll
            for (int j = 0; j < 2; j++) {
                int cw = warp_n * 64 + nf * 8 + t * 2 + j;
                float av = __ldg(asg + cw);
                float dv = __ldg(adg + cw);
#pragma unroll
                for (int mf = 0; mf < 2; mf++) {
                    ps[mf][0] += acc[mf][nf][j] * av;
                    ps[mf][1] += acc[mf][nf][2 + j] * av;
                    pd[mf][0] += acc[mf][nf][j] * dv;
                    pd[mf][1] += acc[mf][nf][2 + j] * dv;
                }
            }
        }
#pragma unroll
        for (int mf = 0; mf < 2; mf++)
#pragma unroll
            for (int hf = 0; hf < 2; hf++) {
#pragma unroll
                for (int off = 1; off <= 2; off <<= 1) {
                    ps[mf][hf] += __shfl_xor_sync(0xffffffffu, ps[mf][hf], off);
                    pd[mf][hf] += __shfl_xor_sync(0xffffffffu, pd[mf][hf], off);
                }
            }
        float* se = (float*)sm;
        float* sd = se + 256;
        if (t == 0) {
#pragma unroll
            for (int mf = 0; mf < 2; mf++)
#pragma unroll
                for (int hf = 0; hf < 2; hf++) {
                    int row = warp_m * 32 + mf * 16 + g + hf * 8;
                    se[row * 2 + warp_n] = ps[mf][hf];
                    sd[row * 2 + warp_n] = pd[mf][hf];
                }
        }
        __syncthreads();
        if (tid < 128) {
            int grr = row0 + tid;
            if (grr < M) {
                es[grr * 4 + blockIdx.x] = se[tid * 2] + se[tid * 2 + 1];
                ed[grr * 4 + blockIdx.x] = sd[tid * 2] + sd[tid * 2 + 1];
            }
        }
    }
}

// ---------------- fp32 -> fp16 hi/lo split (layer 0 input) -----------------
__global__ void convA_k(const float* __restrict__ X, __half* __restrict__ A2,
                        int M, int K) {
    int i = blockIdx.x * blockDim.x + threadIdx.x;
    if (i >= M * K) return;
    int r = i / K, k = i - r * K;
    float v = X[i];
    __half h = __float2half_rn(v);
    __half l = __float2half_rn(v - __half2float(h));
    size_t base = (size_t)r * 2 * K;
    A2[base + k] = h;
    A2[base + K + k] = l;
}

// W [H,K,O] -> B1 [(h*O+o), K] fp16
__global__ void convB_k(const float* __restrict__ W, __half* __restrict__ B1,
                        int K, int O) {
    int idx = blockIdx.x * blockDim.x + threadIdx.x;
    int tot = NHEADS * K * O;
    if (idx >= tot) return;
    int o = idx % O;
    int f = (idx / O) % K;
    int h = idx / (O * K);
    B1[(size_t)(h * O + o) * K + f] = __float2half_rn(W[idx]);
}

// ---------------- CSR build ------------------------------------------------
__global__ void zero_i_k(int* p, int n) {
    int i = blockIdx.x * blockDim.x + threadIdx.x;
    if (i < n) p[i] = 0;
}

__global__ void count_k(const int* __restrict__ dst, int* __restrict__ cnt) {
    int e = blockIdx.x * blockDim.x + threadIdx.x;
    if (e < NE) atomicAdd(&cnt[clampi(dst[e], 0, NN - 1)], 1);
}

__global__ void scan_k(const int* __restrict__ cnt, int* __restrict__ rowptr,
                       int* __restrict__ fill) {
    __shared__ int sh[1024];
    int tid = threadIdx.x;
    int carry = 0;
    if (tid == 0) rowptr[0] = 0;
    for (int base = 0; base < NN; base += 1024) {
        int i = base + tid;
        int v = (i < NN) ? cnt[i] : 0;
        sh[tid] = v;
        __syncthreads();
        for (int off = 1; off < 1024; off <<= 1) {
            int t = (tid >= off) ? sh[tid - off] : 0;
            __syncthreads();
            sh[tid] += t;
            __syncthreads();
        }
        int incl = sh[tid];
        if (i < NN) {
            rowptr[i + 1] = carry + incl;
            fill[i] = carry + incl - v;
        }
        carry += sh[1023];
        __syncthreads();
    }
}

__global__ void scatter_k(const int* __restrict__ dst, int* __restrict__ fill,
                          int* __restrict__ eids) {
    int e = blockIdx.x * blockDim.x + threadIdx.x;
    if (e < NE) {
        int d = clampi(dst[e], 0, NN - 1);
        int pos = atomicAdd(&fill[d], 1);
        if (pos >= 0 && pos < NE) eids[pos] = e;
    }
}

// ---------------- weight reorder (final layer) -----------------------------
__global__ void reorder_k(const float* __restrict__ W, float* __restrict__ out,
                          int K, int O) {
    int idx = blockIdx.x * blockDim.x + threadIdx.x;
    int tot = NHEADS * K * O;
    if (idx >= tot) return;
    int o = idx % O;
    int f = (idx / O) % K;
    int h = idx / (O * K);
    out[f * (NHEADS * O) + h * O + o] = W[idx];
}

// ---------------- SIMT SGEMM (final small layer) ---------------------------
#define BM 128
#define BN 128
#define BK 8
__global__ __launch_bounds__(256)
void sgemm_k(const float* __restrict__ A, const float* __restrict__ B,
             float* __restrict__ C, int M, int N, int K) {
    __shared__ float As[BK][BM];
    __shared__ float Bs[BK][BN];
    int tid = threadIdx.x;
    int row0 = blockIdx.y * BM;
    int col0 = blockIdx.x * BN;

    int aRow = tid >> 1;
    int aCol = (tid & 1) * 4;
    int bRow = tid >> 5;
    int bCol = (tid & 31) * 4;
    int ty = tid >> 4;
    int tx = tid & 15;

    float acc[8][8];
#pragma unroll
    for (int i = 0; i < 8; i++)
#pragma unroll
        for (int j = 0; j < 8; j++) acc[i][j] = 0.f;

    for (int k0 = 0; k0 < K; k0 += BK) {
        float4 av = make_float4(0.f, 0.f, 0.f, 0.f);
        int gr = row0 + aRow;
        if (gr < M) av = *(const float4*)(A + (size_t)gr * K + k0 + aCol);
        As[aCol + 0][aRow] = av.x;
        As[aCol + 1][aRow] = av.y;
        As[aCol + 2][aRow] = av.z;
        As[aCol + 3][aRow] = av.w;

        float4 bv = make_float4(0.f, 0.f, 0.f, 0.f);
        int gc = col0 + bCol;
        if (gc + 3 < N) bv = *(const float4*)(B + (size_t)(k0 + bRow) * N + gc);
        Bs[bRow][bCol + 0] = bv.x;
        Bs[bRow][bCol + 1] = bv.y;
        Bs[bRow][bCol + 2] = bv.z;
        Bs[bRow][bCol + 3] = bv.w;
        __syncthreads();

#pragma unroll
        for (int k = 0; k < BK; k++) {
            float ra[8], rb[8];
#pragma unroll
            for (int i = 0; i < 8; i++) ra[i] = As[k][ty * 8 + i];
#pragma unroll
            for (int j = 0; j < 8; j++) rb[j] = Bs[k][tx * 8 + j];
#pragma unroll
            for (int i = 0; i < 8; i++)
#pragma unroll
                for (int j = 0; j < 8; j++) acc[i][j] += ra[i] * rb[j];
        }
        __syncthreads();
    }

#pragma unroll
    for (int i = 0; i < 8; i++) {
        int r = row0 + ty * 8 + i;
        if (r >= M) continue;
#pragma unroll
        for (int j = 0; j < 8; j++) {
            int c = col0 + tx * 8 + j;
            if (c < N) C[(size_t)r * N + c] = acc[i][j];
        }
    }
}

// ---------------- es/ed (final layer only) ---------------------------------
template <int O>
__global__ void esed_k(const float* __restrict__ h, const float* __restrict__ a_s,
                       const float* __restrict__ a_d, float* __restrict__ es,
                       float* __restrict__ ed) {
    int w = (blockIdx.x * blockDim.x + threadIdx.x) >> 5;
    int lane = threadIdx.x & 31;
    if (w >= NN * NHEADS) return;
    int hd = w % NHEADS;
    const float* hp = h + (size_t)w * O;
    float s = 0.f, d = 0.f;
    for (int k = lane; k < O; k += 32) {
        float v = hp[k];
        s += v * a_s[hd * O + k];
        d += v * a_d[hd * O + k];
    }
#pragma unroll
    for (int off = 16; off; off >>= 1) {
        s += __shfl_xor_sync(0xffffffffu, s, off);
        d += __shfl_xor_sync(0xffffffffu, d, off);
    }
    if (lane == 0) { es[w] = s; ed[w] = d; }
}

__global__ void eetab_k(const float* __restrict__ rel, const float* __restrict__ ae,
                        float* __restrict__ tab) {
    int i = threadIdx.x;
    if (i < NREL * NHEADS) {
        int r = i >> 2, hd = i & 3;
        tab[i] = rel[r * 2] * ae[hd * 2] + rel[r * 2 + 1] * ae[hd * 2 + 1];
    }
}

__device__ __forceinline__ float lrelu02(float v) { return v > 0.f ? v : 0.2f * v; }

// ---------------- fused attention: logit+softmax+gather+combine ------------
__global__ void attn_k(const __half* __restrict__ H, const float* __restrict__ es,
                       const float* __restrict__ ed, const float* __restrict__ eetab,
                       const int* __restrict__ src, const int* __restrict__ etype,
                       const int* __restrict__ edist, const int* __restrict__ rowptr,
                       const int* __restrict__ eids, float4* __restrict__ alpha,
                       const float* __restrict__ b, const float* __restrict__ resid,
                       float* __restrict__ out) {
    int n = (blockIdx.x * blockDim.x + threadIdx.x) >> 5;
    int lane = threadIdx.x & 31;
    if (n >= NN) return;
    int beg = rowptr[n], end = rowptr[n + 1];
    float4 edn = *(const float4*)(ed + n * 4);

    // pass 1: logits + max
    float4 m = make_float4(-3.4e38f, -3.4e38f, -3.4e38f, -3.4e38f);
    for (int i = beg + lane; i < end; i += 32) {
        int e = eids[i];
        int s = clampi(src[e], 0, NN - 1);
        int t = clampi(etype[e], 0, NREL - 1);
        float4 a = *(const float4*)(es + s * 4);
        float4 c = *(const float4*)(eetab + t * 4);
        float4 lg;
        lg.x = lrelu02(a.x + edn.x + c.x);
        lg.y = lrelu02(a.y + edn.y + c.y);
        lg.z = lrelu02(a.z + edn.z + c.z);
        lg.w = lrelu02(a.w + edn.w + c.w);
        alpha[i] = lg;
        m.x = fmaxf(m.x, lg.x); m.y = fmaxf(m.y, lg.y);
        m.z = fmaxf(m.z, lg.z); m.w = fmaxf(m.w, lg.w);
    }
#pragma unroll
    for (int off = 16; off; off >>= 1) {
        m.x = fmaxf(m.x, __shfl_xor_sync(0xffffffffu, m.x, off));
        m.y = fmaxf(m.y, __shfl_xor_sync(0xffffffffu, m.y, off));
        m.z = fmaxf(m.z, __shfl_xor_sync(0xffffffffu, m.z, off));
        m.w = fmaxf(m.w, __shfl_xor_sync(0xffffffffu, m.w, off));
    }
    // pass 2: exp + den
    float4 den = make_float4(0.f, 0.f, 0.f, 0.f);
    for (int i = beg + lane; i < end; i += 32) {
        float4 v = alpha[i];
        float4 ex;
        ex.x = __expf(v.x - m.x); ex.y = __expf(v.y - m.y);
        ex.z = __expf(v.z - m.z); ex.w = __expf(v.w - m.w);
        alpha[i] = ex;
        den.x += ex.x; den.y += ex.y; den.z += ex.z; den.w += ex.w;
    }
#pragma unroll
    for (int off = 16; off; off >>= 1) {
        den.x += __shfl_xor_sync(0xffffffffu, den.x, off);
        den.y += __shfl_xor_sync(0xffffffffu, den.y, off);
        den.z += __shfl_xor_sync(0xffffffffu, den.z, off);
        den.w += __shfl_xor_sync(0xffffffffu, den.w, off);
    }
    float4 inv;
    inv.x = 1.0f / (den.x + 1e-16f); inv.y = 1.0f / (den.y + 1e-16f);
    inv.z = 1.0f / (den.z + 1e-16f); inv.w = 1.0f / (den.w + 1e-16f);
    __syncwarp();

    // pass 3: gather (half2 coalesced) + head-mean + bias + residual
    float2 accA[NHEADS], accB[NHEADS];
#pragma unroll
    for (int q = 0; q < NHEADS; q++) {
        accA[q] = make_float2(0.f, 0.f);
        accB[q] = make_float2(0.f, 0.f);
    }
    for (int i = beg; i < end; i++) {
        int e = eids[i];
        int s = clampi(src[e], 0, NN - 1);
        float4 a = alpha[i];
        float w = 1.0f / (1.0f + (float)edist[e]);
        float aw[4] = {a.x * inv.x * w, a.y * inv.y * w, a.z * inv.z * w,
                       a.w * inv.w * w};
        const __half2* hs2 = (const __half2*)(H + (size_t)s * 512);
#pragma unroll
        for (int q = 0; q < NHEADS; q++) {
            float2 fa = __half22float2(hs2[q * 64 + lane]);
            float2 fb = __half22float2(hs2[q * 64 + 32 + lane]);
            accA[q].x += aw[q] * fa.x; accA[q].y += aw[q] * fa.y;
            accB[q].x += aw[q] * fb.x; accB[q].y += aw[q] * fb.y;
        }
    }
    // element (lane, A) -> cols 2l,2l+1 ; (lane, B) -> cols 64+2l, 64+2l+1
    {
        int oA = 2 * lane, oB = 64 + 2 * lane;
        float2 bA = *(const float2*)(b + oA);
        float2 bB = *(const float2*)(b + oB);
        float2 vA, vB;
        vA.x = 0.25f * (accA[0].x + accA[1].x + accA[2].x + accA[3].x) + bA.x;
        vA.y = 0.25f * (accA[0].y + accA[1].y + accA[2].y + accA[3].y) + bA.y;
        vB.x = 0.25f * (accB[0].x + accB[1].x + accB[2].x + accB[3].x) + bB.x;
        vB.y = 0.25f * (accB[0].y + accB[1].y + accB[2].y + accB[3].y) + bB.y;
        if (resid) {
            float2 rA = *(const float2*)(resid + (size_t)n * 128 + oA);
            float2 rB = *(const float2*)(resid + (size_t)n * 128 + oB);
            vA.x += rA.x; vA.y += rA.y; vB.x += rB.x; vB.y += rB.y;
        }
        *(float2*)(out + (size_t)n * 128 + oA) = vA;
        *(float2*)(out + (size_t)n * 128 + oB) = vB;
    }
}

// ---------------- final-layer softmax (standalone) -------------------------
__global__ void lsm_k(const float* __restrict__ es, const float* __restrict__ ed,
                      const float* __restrict__ eetab, const int* __restrict__ src,
                      const int* __restrict__ etype, const int* __restrict__ edist,
                      const int* __restrict__ rowptr, const int* __restrict__ eids,
                      float4* __restrict__ alpha) {
    int n = (blockIdx.x * blockDim.x + threadIdx.x) >> 5;
    int lane = threadIdx.x & 31;
    if (n >= NN) return;
    int beg = rowptr[n], end = rowptr[n + 1];
    float4 edn = *(const float4*)(ed + n * 4);

    float4 m = make_float4(-3.4e38f, -3.4e38f, -3.4e38f, -3.4e38f);
    for (int i = beg + lane; i < end; i += 32) {
        int e = eids[i];
        int s = clampi(src[e], 0, NN - 1);
        int t = clampi(etype[e], 0, NREL - 1);
        float4 a = *(const float4*)(es + s * 4);
        float4 c = *(const float4*)(eetab + t * 4);
        float4 lg;
        lg.x = lrelu02(a.x + edn.x + c.x);
        lg.y = lrelu02(a.y + edn.y + c.y);
        lg.z = lrelu02(a.z + edn.z + c.z);
        lg.w = lrelu02(a.w + edn.w + c.w);
        alpha[i] = lg;
        m.x = fmaxf(m.x, lg.x); m.y = fmaxf(m.y, lg.y);
        m.z = fmaxf(m.z, lg.z); m.w = fmaxf(m.w, lg.w);
    }
#pragma unroll
    for (int off = 16; off; off >>= 1) {
        m.x = fmaxf(m.x, __shfl_xor_sync(0xffffffffu, m.x, off));
        m.y = fmaxf(m.y, __shfl_xor_sync(0xffffffffu, m.y, off));
        m.z = fmaxf(m.z, __shfl_xor_sync(0xffffffffu, m.z, off));
        m.w = fmaxf(m.w, __shfl_xor_sync(0xffffffffu, m.w, off));
    }
    float4 den = make_float4(0.f, 0.f, 0.f, 0.f);
    for (int i = beg + lane; i < end; i += 32) {
        float4 v = alpha[i];
        float4 ex;
        ex.x = __expf(v.x - m.x); ex.y = __expf(v.y - m.y);
        ex.z = __expf(v.z - m.z); ex.w = __expf(v.w - m.w);
        alpha[i] = ex;
        den.x += ex.x; den.y += ex.y; den.z += ex.z; den.w += ex.w;
    }
#pragma unroll
    for (int off = 16; off; off >>= 1) {
        den.x += __shfl_xor_sync(0xffffffffu, den.x, off);
        den.y += __shfl_xor_sync(0xffffffffu, den.y, off);
        den.z += __shfl_xor_sync(0xffffffffu, den.z, off);
        den.w += __shfl_xor_sync(0xffffffffu, den.w, off);
    }
    float4 inv;
    inv.x = 1.0f / (den.x + 1e-16f); inv.y = 1.0f / (den.y + 1e-16f);
    inv.z = 1.0f / (den.z + 1e-16f); inv.w = 1.0f / (den.w + 1e-16f);
    for (int i = beg + lane; i < end; i += 32) {
        float4 v = alpha[i];
        float w = 1.0f / (1.0f + (float)edist[eids[i]]);
        v.x *= inv.x * w; v.y *= inv.y * w;
        v.z *= inv.z * w; v.w *= inv.w * w;
        alpha[i] = v;
    }
}

// ---------------- final layer gather (O=9) + combine + lrelu ---------------
__global__ void aggF_k(const float* __restrict__ h, const float4* __restrict__ alpha4,
                       const int* __restrict__ src, const int* __restrict__ eids,
                       const int* __restrict__ rowptr, const float* __restrict__ b,
                       float* __restrict__ out) {
    int n = (blockIdx.x * blockDim.x + threadIdx.x) >> 5;
    int lane = threadIdx.x & 31;
    if (n >= NN) return;
    int beg = rowptr[n], end = rowptr[n + 1];
    float acc[NHEADS] = {0.f, 0.f, 0.f, 0.f};
    for (int i = beg; i < end; i++) {
        int e = eids[i];
        int s = clampi(src[e], 0, NN - 1);
        float4 a = alpha4[i];
        float aw[4] = {a.x, a.y, a.z, a.w};
        if (lane < NCLS) {
            const float* hs = h + (size_t)s * (NHEADS * NCLS);
#pragma unroll
            for (int q = 0; q < NHEADS; q++) acc[q] += aw[q] * hs[q * NCLS + lane];
        }
    }
    if (lane < NCLS) {
        float v = 0.25f * (acc[0] + acc[1] + acc[2] + acc[3]) + b[lane];
        out[(size_t)n * NCLS + lane] = v > 0.f ? v : 0.1f * v;
    }
}

// ---------------- batch norm -----------------------------------------------
__global__ void bn_zero_k(float* s, float* q) {
    int t = threadIdx.x;
    if (t < HID) { s[t] = 0.f; q[t] = 0.f; }
}

__global__ void bn_stats_k(const float* __restrict__ x, float* __restrict__ sum,
                           float* __restrict__ sumsq) {
    int t = threadIdx.x;
    int rows_per = (NN + gridDim.x - 1) / gridDim.x;
    int r0 = blockIdx.x * rows_per;
    int r1 = min(r0 + rows_per, NN);
    float s = 0.f, q = 0.f;
    for (int r = r0; r < r1; r++) {
        float v = x[(size_t)r * HID + t];
        s += v;
        q += v * v;
    }
    atomicAdd(&sum[t], s);
    atomicAdd(&sumsq[t], q);
}

// bn + lrelu + optional fp16 hi/lo split
__global__ void bn_apply_k(const float* __restrict__ x, const float* __restrict__ sum,
                           const float* __restrict__ sumsq, const float* __restrict__ g,
                           const float* __restrict__ b, float* __restrict__ out,
                           __half* __restrict__ A2) {
    int i = blockIdx.x * blockDim.x + threadIdx.x;
    if (i >= NN * HID) return;
    int o = i & 127;
    int n = i >> 7;
    float mu = sum[o] * (1.0f / NN);
    float var = sumsq[o] * (1.0f / NN) - mu * mu;
    float v = (x[i] - mu) * rsqrtf(var + 1e-5f) * g[o] + b[o];
    v = v > 0.f ? v : 0.1f * v;
    out[i] = v;
    if (A2) {
        __half h = __float2half_rn(v);
        __half l = __float2half_rn(v - __half2float(h));
        size_t base = (size_t)n * 256;
        A2[base + o] = h;
        A2[base + 128 + o] = l;
    }
}

// ---------------- host orchestration ---------------------------------------
struct Bufs {
    float *h_buf, *tmp, *xb, *hin, *es, *ed, *eetab, *Wb, *bsum, *bsq;
    __half *Hh, *A2, *B1;
    int *cnt, *rowptr, *fill, *eids;
};

extern "C" void kernel_launch(void* const* d_in, const int* in_sizes, int n_in,
                              void* d_out, int out_size) {
    const float* x = (const float*)d_in[0];
    const int* ei = (const int*)d_in[1];
    const int* etype = (const int*)d_in[2];
    const int* edist = (const int*)d_in[3];
    const float* W0 = (const float*)d_in[4];
    const float* asrc0 = (const float*)d_in[5];
    const float* adst0 = (const float*)d_in[6];
    const float* aedge0 = (const float*)d_in[7];
    const float* b0 = (const float*)d_in[8];
    const float* rel0 = (const float*)d_in[9];
    const float* Wm = (const float*)d_in[10];
    const float* asrcm = (const float*)d_in[11];
    const float* adstm = (const float*)d_in[12];
    const float* aedgem = (const float*)d_in[13];
    const float* bm = (const float*)d_in[14];
    const float* relm = (const float*)d_in[15];
    const float* WL = (const float*)d_in[16];
    const float* asrcL = (const float*)d_in[17];
    const float* adstL = (const float*)d_in[18];
    const float* aedgeL = (const float*)d_in[19];
    const float* bL = (const float*)d_in[20];
    const float* relL = (const float*)d_in[21];
    const float* bn_g = (const float*)d_in[22];
    const float* bn_b = (const float*)d_in[23];

    static bool attr_set = false;
    if (!attr_set) {
        cudaFuncSetAttribute(mma_gemm_k, cudaFuncAttributeMaxDynamicSharedMemorySize,
                             2 * STAGEB);
        attr_set = true;
    }

    Bufs B;
    cudaGetSymbolAddress((void**)&B.h_buf, g_h);
    cudaGetSymbolAddress((void**)&B.Hh, g_Hh);
    cudaGetSymbolAddress((void**)&B.tmp, g_tmp);
    cudaGetSymbolAddress((void**)&B.xb, g_x);
    cudaGetSymbolAddress((void**)&B.hin, g_hin);
    cudaGetSymbolAddress((void**)&B.es, g_es);
    cudaGetSymbolAddress((void**)&B.ed, g_ed);
    cudaGetSymbolAddress((void**)&B.eetab, g_eetab);
    cudaGetSymbolAddress((void**)&B.Wb, g_W);
    cudaGetSymbolAddress((void**)&B.bsum, g_bsum);
    cudaGetSymbolAddress((void**)&B.bsq, g_bsq);
    cudaGetSymbolAddress((void**)&B.A2, g_A2);
    cudaGetSymbolAddress((void**)&B.B1, g_B1);
    cudaGetSymbolAddress((void**)&B.cnt, g_cnt);
    cudaGetSymbolAddress((void**)&B.rowptr, g_rowptr);
    cudaGetSymbolAddress((void**)&B.fill, g_fill);
    cudaGetSymbolAddress((void**)&B.eids, g_eids);

    const int* src = ei;
    const int* dst = ei + NE;
    float4* lg4 = (float4*)B.tmp;
    dim3 ggrid(4, (NN + 127) / 128);

    // layer-0: convA(1), convB(2), zero(3), mma(4 = profiled slot)
    int na = NN * FIN;
    convA_k<<<(na + 255) / 256, 256>>>(x, B.A2, NN, FIN);
    int nb = NHEADS * FIN * HID;
    convB_k<<<(nb + 255) / 256, 256>>>(W0, B.B1, FIN, HID);
    zero_i_k<<<(NN + 255) / 256, 256>>>(B.cnt, NN);
    mma_gemm_k<<<ggrid, 256, 2 * STAGEB>>>(B.A2, B.B1, asrc0, adst0, B.Hh,
                                           B.es, B.ed, NN, FIN);
    count_k<<<(NE + 255) / 256, 256>>>(dst, B.cnt);
    scan_k<<<1, 1024>>>(B.cnt, B.rowptr, B.fill);
    scatter_k<<<(NE + 255) / 256, 256>>>(dst, B.fill, B.eids);
    eetab_k<<<1, 256>>>(rel0, aedge0, B.eetab);
    attn_k<<<(NN * 32 + 255) / 256, 256>>>(B.Hh, B.es, B.ed, B.eetab, src,
                                           etype, edist, B.rowptr, B.eids, lg4,
                                           b0, nullptr, B.xb);

    int nb128 = (NN * HID + 255) / 256;

    for (int i = 0; i < 3; i++) {
        bn_zero_k<<<1, 128>>>(B.bsum, B.bsq);
        bn_stats_k<<<200, 128>>>(B.xb, B.bsum, B.bsq);
        bn_apply_k<<<nb128, 256>>>(B.xb, B.bsum, B.bsq, bn_g + i * HID,
                                   bn_b + i * HID, B.hin, B.A2);
        int nbm = NHEADS * HID * HID;
        convB_k<<<(nbm + 255) / 256, 256>>>(Wm + (size_t)i * NHEADS * HID * HID,
                                            B.B1, HID, HID);
        mma_gemm_k<<<ggrid, 256, 2 * STAGEB>>>(
            B.A2, B.B1, asrcm + i * NHEADS * HID, adstm + i * NHEADS * HID,
            B.Hh, B.es, B.ed, NN, HID);
        eetab_k<<<1, 256>>>(relm + i * NREL * 2, aedgem + i * NHEADS * 2, B.eetab);
        attn_k<<<(NN * 32 + 255) / 256, 256>>>(B.Hh, B.es, B.ed, B.eetab, src,
                                               etype, edist, B.rowptr, B.eids, lg4,
                                               bm + i * HID, B.hin, B.xb);
    }

    // final layer
    bn_zero_k<<<1, 128>>>(B.bsum, B.bsq);
    bn_stats_k<<<200, 128>>>(B.xb, B.bsum, B.bsq);
    bn_apply_k<<<nb128, 256>>>(B.xb, B.bsum, B.bsq, bn_g + 3 * HID,
                               bn_b + 3 * HID, B.hin, (__half*)nullptr);
    {
        int tot = NHEADS * HID * NCLS;
        reorder_k<<<(tot + 255) / 256, 256>>>(WL, B.Wb, HID, NCLS);
        int Ncols = NHEADS * NCLS;
        dim3 grid((Ncols + BN - 1) / BN, (NN + BM - 1) / BM);
        sgemm_k<<<grid, 256>>>(B.hin, B.Wb, B.h_buf, NN, Ncols, HID);
        int warps = NN * NHEADS;
        int blocks = (warps * 32 + 255) / 256;
        esed_k<NCLS><<<blocks, 256>>>(B.h_buf, asrcL, adstL, B.es, B.ed);
        eetab_k<<<1, 256>>>(relL, aedgeL, B.eetab);
        lsm_k<<<(NN * 32 + 255) / 256, 256>>>(B.es, B.ed, B.eetab, src, etype,
                                              edist, B.rowptr, B.eids, lg4);
        aggF_k<<<(NN * 32 + 255) / 256, 256>>>(B.h_buf, lg4, src, B.eids,
                                               B.rowptr, bL, (float*)d_out);
    }
}

// round 10
// speedup vs baseline: 2.3250x; 1.0402x over previous
#include <cuda_runtime.h>
#include <cuda_fp16.h>
#include <math.h>
#include <stdint.h>

#define NN 20000
#define NE 320000
#define NHEADS 4
#define NREL 40
#define FIN 768
#define HID 128
#define NCLS 9

// ---------------- scratch ---------------------------------------------------
__device__ __align__(16) float g_h[NN * NHEADS * HID];          // final-layer SIMT out
__device__ __align__(16) __half g_Hh[NN * NHEADS * HID];        // GEMM out fp16 [N,512]
__device__ __align__(16) float g_tmp[NN * NHEADS * HID];
__device__ __align__(16) float g_x[NN * HID];
__device__ __align__(16) float g_hin[NN * HID];
__device__ __align__(16) float g_es[NN * NHEADS];
__device__ __align__(16) float g_ed[NN * NHEADS];
__device__ __align__(16) float g_W[FIN * NHEADS * HID];
__device__ __align__(16) __half g_A2[NN * 2 * FIN];             // [M,2K] hi|lo fp16
__device__ __align__(16) __half g_B1[(NHEADS * HID) * FIN];     // [512,K] fp16
__device__ int g_cnt[NN];
__device__ int g_rowptr[NN + 1];
__device__ int g_fill[NN];
__device__ int g_eids[NE];
__device__ float g_bsum[4 * HID];
__device__ float g_bsq[4 * HID];

__device__ __forceinline__ int clampi(int v, int lo, int hi) {
    return v < lo ? lo : (v > hi ? hi : v);
}

__device__ __forceinline__ uint32_t smem_u32(const void* p) {
    uint32_t a;
    asm("{ .reg .u64 t; cvta.to.shared.u64 t, %1; cvt.u32.u64 %0, t; }"
        : "=r"(a) : "l"(p));
    return a;
}

__device__ __forceinline__ void ldsm_x4(uint32_t* r, uint32_t addr) {
    asm volatile("ldmatrix.sync.aligned.m8n8.x4.shared.b16 {%0,%1,%2,%3}, [%4];"
                 : "=r"(r[0]), "=r"(r[1]), "=r"(r[2]), "=r"(r[3]) : "r"(addr));
}

__device__ __forceinline__ void mma16816(float* d, const uint32_t* a, uint32_t b0,
                                         uint32_t b1) {
    asm volatile(
        "mma.sync.aligned.m16n8k16.row.col.f32.f16.f16.f32 "
        "{%0,%1,%2,%3}, {%4,%5,%6,%7}, {%8,%9}, {%0,%1,%2,%3};"
        : "+f"(d[0]), "+f"(d[1]), "+f"(d[2]), "+f"(d[3])
        : "r"(a[0]), "r"(a[1]), "r"(a[2]), "r"(a[3]), "r"(b0), "r"(b1));
}

__device__ __forceinline__ void cp16(uint32_t saddr, const void* g, bool pred) {
    int sz = pred ? 16 : 0;
    asm volatile("cp.async.cg.shared.global [%0], [%1], 16, %2;"
                 :: "r"(saddr), "l"(g), "r"(sz));
}
#define CP_COMMIT() asm volatile("cp.async.commit_group;" ::: "memory")
#define CP_WAIT2() asm volatile("cp.async.wait_group 2;" ::: "memory")
#define CP_WAIT1() asm volatile("cp.async.wait_group 1;" ::: "memory")
#define CP_WAIT0() asm volatile("cp.async.wait_group 0;" ::: "memory")

// ---------------- fp16 2-term GEMM, K-chunk 32, 3-stage, fp16 H, es/ed -----
#define SMS 40
#define TILEB 10240                 // bytes per 128x32 fp16 tile
#define STAGEB (3 * TILEB)          // AH, AL, B
#define NSTAGE 3
__global__ void __launch_bounds__(256, 2)
mma_gemm_k(const __half* __restrict__ A2, const __half* __restrict__ B1,
           const float* __restrict__ a_s, const float* __restrict__ a_d,
           __half* __restrict__ H, float* __restrict__ es, float* __restrict__ ed,
           int M, int K) {
    extern __shared__ char sm[];
    uint32_t s0 = smem_u32(sm);
    int tid = threadIdx.x;
    int wid = tid >> 5;
    int lane = tid & 31;
    int warp_m = wid & 3;
    int warp_n = wid >> 2;
    int row0 = blockIdx.y * 128;
    int col0 = blockIdx.x * 128;

    float acc[2][8][4];
#pragma unroll
    for (int i = 0; i < 2; i++)
#pragma unroll
        for (int j = 0; j < 8; j++)
#pragma unroll
            for (int q = 0; q < 4; q++) acc[i][j][q] = 0.f;

    int ksz = K / 32;
    int lr = tid >> 1;
    int lq = (tid & 1) * 16;
    int gr = row0 + lr;
    bool aval = gr < M;
    const __half* Abase = A2 + (size_t)(aval ? gr : 0) * (2 * K);
    const __half* Bbase = B1 + (size_t)(col0 + lr) * K;
    uint32_t sA = (uint32_t)((lr * SMS + lq) * 2);

#define ISSUE_STAGE(c) do {                                              \
        int _kb = (c) * 32;                                              \
        uint32_t _b = s0 + ((c) % NSTAGE) * STAGEB;                      \
        const __half* _g;                                                \
        _g = Abase + _kb + lq;                                           \
        cp16(_b + 0 * TILEB + sA, _g, aval);                             \
        cp16(_b + 0 * TILEB + sA + 16, _g + 8, aval);                    \
        _g = Abase + K + _kb + lq;                                       \
        cp16(_b + 1 * TILEB + sA, _g, aval);                             \
        cp16(_b + 1 * TILEB + sA + 16, _g + 8, aval);                    \
        _g = Bbase + _kb + lq;                                           \
        cp16(_b + 2 * TILEB + sA, _g, true);                             \
        cp16(_b + 2 * TILEB + sA + 16, _g + 8, true);                    \
        CP_COMMIT();                                                     \
    } while (0)

    ISSUE_STAGE(0);
    if (ksz > 1) ISSUE_STAGE(1);
    for (int c = 0; c < ksz; c++) {
        if (c + 2 < ksz) {
            ISSUE_STAGE(c + 2);
            CP_WAIT2();
        } else if (c + 1 < ksz) {
            CP_WAIT1();
        } else {
            CP_WAIT0();
        }
        __syncthreads();
        uint32_t base = s0 + (c % NSTAGE) * STAGEB;
#pragma unroll
        for (int k16 = 0; k16 < 32; k16 += 16) {
            uint32_t koff = (uint32_t)((k16 + ((lane >> 4) << 3)) * 2);
            uint32_t ah[2][4], al[2][4];
#pragma unroll
            for (int mf = 0; mf < 2; mf++) {
                int m = warp_m * 32 + mf * 16 + (lane & 15);
                uint32_t ro = (uint32_t)(m * SMS * 2) + koff;
                ldsm_x4(ah[mf], base + 0 * TILEB + ro);
                ldsm_x4(al[mf], base + 1 * TILEB + ro);
            }
#pragma unroll
            for (int jp = 0; jp < 4; jp++) {
                int n = warp_n * 64 + jp * 16 + (lane & 15);
                uint32_t ro = (uint32_t)(n * SMS * 2) + koff;
                uint32_t bf[4];
                ldsm_x4(bf, base + 2 * TILEB + ro);
#pragma unroll
                for (int mf = 0; mf < 2; mf++) {
                    mma16816(acc[mf][jp * 2 + 0], ah[mf], bf[0], bf[2]);
                    mma16816(acc[mf][jp * 2 + 1], ah[mf], bf[1], bf[3]);
                    mma16816(acc[mf][jp * 2 + 0], al[mf], bf[0], bf[2]);
                    mma16816(acc[mf][jp * 2 + 1], al[mf], bf[1], bf[3]);
                }
            }
        }
        __syncthreads();
    }
#undef ISSUE_STAGE

    int g = lane >> 2, t = lane & 3;
    // H store (fp16)
#pragma unroll
    for (int mf = 0; mf < 2; mf++) {
#pragma unroll
        for (int nf = 0; nf < 8; nf++) {
            int col = col0 + warp_n * 64 + nf * 8 + t * 2;
            int r0 = row0 + warp_m * 32 + mf * 16 + g;
            if (r0 < M)
                *(__half2*)(H + (size_t)r0 * 512 + col) =
                    __floats2half2_rn(acc[mf][nf][0], acc[mf][nf][1]);
            int r1 = r0 + 8;
            if (r1 < M)
                *(__half2*)(H + (size_t)r1 * 512 + col) =
                    __floats2half2_rn(acc[mf][nf][2], acc[mf][nf][3]);
        }
    }

    // fused es/ed: head = blockIdx.x
    {
        const float* asg = a_s + blockIdx.x * 128;
        const float* adg = a_d + blockIdx.x * 128;
        float ps[2][2] = {{0.f, 0.f}, {0.f, 0.f}};
        float pd[2][2] = {{0.f, 0.f}, {0.f, 0.f}};
#pragma unroll
        for (int nf = 0; nf < 8; nf++) {
#pragma unroll
            for (int j = 0; j < 2; j++) {
                int cw = warp_n * 64 + nf * 8 + t * 2 + j;
                float av = __ldg(asg + cw);
                float dv = __ldg(adg + cw);
#pragma unroll
                for (int mf = 0; mf < 2; mf++) {
                    ps[mf][0] += acc[mf][nf][j] * av;
                    ps[mf][1] += acc[mf][nf][2 + j] * av;
                    pd[mf][0] += acc[mf][nf][j] * dv;
                    pd[mf][1] += acc[mf][nf][2 + j] * dv;
                }
            }
        }
#pragma unroll
        for (int mf = 0; mf < 2; mf++)
#pragma unroll
            for (int hf = 0; hf < 2; hf++) {
#pragma unroll
                for (int off = 1; off <= 2; off <<= 1) {
                    ps[mf][hf] += __shfl_xor_sync(0xffffffffu, ps[mf][hf], off);
                    pd[mf][hf] += __shfl_xor_sync(0xffffffffu, pd[mf][hf], off);
                }
            }
        float* se = (float*)sm;
        float* sd = se + 256;
        if (t == 0) {
#pragma unroll
            for (int mf = 0; mf < 2; mf++)
#pragma unroll
                for (int hf = 0; hf < 2; hf++) {
                    int row = warp_m * 32 + mf * 16 + g + hf * 8;
                    se[row * 2 + warp_n] = ps[mf][hf];
                    sd[row * 2 + warp_n] = pd[mf][hf];
                }
        }
        __syncthreads();
        if (tid < 128) {
            int grr = row0 + tid;
            if (grr < M) {
                es[grr * 4 + blockIdx.x] = se[tid * 2] + se[tid * 2 + 1];
                ed[grr * 4 + blockIdx.x] = sd[tid * 2] + sd[tid * 2 + 1];
            }
        }
    }
}

// ---------------- fp32 -> fp16 hi/lo split (layer 0 input) -----------------
__global__ void convA_k(const float* __restrict__ X, __half* __restrict__ A2,
                        int M, int K) {
    int i = blockIdx.x * blockDim.x + threadIdx.x;
    if (i >= M * K) return;
    int r = i / K, k = i - r * K;
    float v = X[i];
    __half h = __float2half_rn(v);
    __half l = __float2half_rn(v - __half2float(h));
    size_t base = (size_t)r * 2 * K;
    A2[base + k] = h;
    A2[base + K + k] = l;
}

// W [H,K,O] -> B1 [(h*O+o), K] fp16
__global__ void convB_k(const float* __restrict__ W, __half* __restrict__ B1,
                        int K, int O) {
    int idx = blockIdx.x * blockDim.x + threadIdx.x;
    int tot = NHEADS * K * O;
    if (idx >= tot) return;
    int o = idx % O;
    int f = (idx / O) % K;
    int h = idx / (O * K);
    B1[(size_t)(h * O + o) * K + f] = __float2half_rn(W[idx]);
}

// ---------------- init: zero cnt + all bn stat buffers ---------------------
__global__ void init_zero_k(int* cnt, float* bsum, float* bsq) {
    int i = blockIdx.x * blockDim.x + threadIdx.x;
    if (i < NN) cnt[i] = 0;
    if (i < 4 * HID) { bsum[i] = 0.f; bsq[i] = 0.f; }
}

__global__ void count_k(const int* __restrict__ dst, int* __restrict__ cnt) {
    int e = blockIdx.x * blockDim.x + threadIdx.x;
    if (e < NE) atomicAdd(&cnt[clampi(dst[e], 0, NN - 1)], 1);
}

__global__ void scan_k(const int* __restrict__ cnt, int* __restrict__ rowptr,
                       int* __restrict__ fill) {
    __shared__ int sh[1024];
    int tid = threadIdx.x;
    int carry = 0;
    if (tid == 0) rowptr[0] = 0;
    for (int base = 0; base < NN; base += 1024) {
        int i = base + tid;
        int v = (i < NN) ? cnt[i] : 0;
        sh[tid] = v;
        __syncthreads();
        for (int off = 1; off < 1024; off <<= 1) {
            int t = (tid >= off) ? sh[tid - off] : 0;
            __syncthreads();
            sh[tid] += t;
            __syncthreads();
        }
        int incl = sh[tid];
        if (i < NN) {
            rowptr[i + 1] = carry + incl;
            fill[i] = carry + incl - v;
        }
        carry += sh[1023];
        __syncthreads();
    }
}

__global__ void scatter_k(const int* __restrict__ dst, int* __restrict__ fill,
                          int* __restrict__ eids) {
    int e = blockIdx.x * blockDim.x + threadIdx.x;
    if (e < NE) {
        int d = clampi(dst[e], 0, NN - 1);
        int pos = atomicAdd(&fill[d], 1);
        if (pos >= 0 && pos < NE) eids[pos] = e;
    }
}

// ---------------- weight reorder (final layer) -----------------------------
__global__ void reorder_k(const float* __restrict__ W, float* __restrict__ out,
                          int K, int O) {
    int idx = blockIdx.x * blockDim.x + threadIdx.x;
    int tot = NHEADS * K * O;
    if (idx >= tot) return;
    int o = idx % O;
    int f = (idx / O) % K;
    int h = idx / (O * K);
    out[f * (NHEADS * O) + h * O + o] = W[idx];
}

// ---------------- SIMT SGEMM (final small layer) ---------------------------
#define BM 128
#define BN 128
#define BK 8
__global__ __launch_bounds__(256)
void sgemm_k(const float* __restrict__ A, const float* __restrict__ B,
             float* __restrict__ C, int M, int N, int K) {
    __shared__ float As[BK][BM];
    __shared__ float Bs[BK][BN];
    int tid = threadIdx.x;
    int row0 = blockIdx.y * BM;
    int col0 = blockIdx.x * BN;

    int aRow = tid >> 1;
    int aCol = (tid & 1) * 4;
    int bRow = tid >> 5;
    int bCol = (tid & 31) * 4;
    int ty = tid >> 4;
    int tx = tid & 15;

    float acc[8][8];
#pragma unroll
    for (int i = 0; i < 8; i++)
#pragma unroll
        for (int j = 0; j < 8; j++) acc[i][j] = 0.f;

    for (int k0 = 0; k0 < K; k0 += BK) {
        float4 av = make_float4(0.f, 0.f, 0.f, 0.f);
        int gr = row0 + aRow;
        if (gr < M) av = *(const float4*)(A + (size_t)gr * K + k0 + aCol);
        As[aCol + 0][aRow] = av.x;
        As[aCol + 1][aRow] = av.y;
        As[aCol + 2][aRow] = av.z;
        As[aCol + 3][aRow] = av.w;

        float4 bv = make_float4(0.f, 0.f, 0.f, 0.f);
        int gc = col0 + bCol;
        if (gc + 3 < N) bv = *(const float4*)(B + (size_t)(k0 + bRow) * N + gc);
        Bs[bRow][bCol + 0] = bv.x;
        Bs[bRow][bCol + 1] = bv.y;
        Bs[bRow][bCol + 2] = bv.z;
        Bs[bRow][bCol + 3] = bv.w;
        __syncthreads();

#pragma unroll
        for (int k = 0; k < BK; k++) {
            float ra[8], rb[8];
#pragma unroll
            for (int i = 0; i < 8; i++) ra[i] = As[k][ty * 8 + i];
#pragma unroll
            for (int j = 0; j < 8; j++) rb[j] = Bs[k][tx * 8 + j];
#pragma unroll
            for (int i = 0; i < 8; i++)
#pragma unroll
                for (int j = 0; j < 8; j++) acc[i][j] += ra[i] * rb[j];
        }
        __syncthreads();
    }

#pragma unroll
    for (int i = 0; i < 8; i++) {
        int r = row0 + ty * 8 + i;
        if (r >= M) continue;
#pragma unroll
        for (int j = 0; j < 8; j++) {
            int c = col0 + tx * 8 + j;
            if (c < N) C[(size_t)r * N + c] = acc[i][j];
        }
    }
}

// ---------------- es/ed (final layer only) ---------------------------------
template <int O>
__global__ void esed_k(const float* __restrict__ h, const float* __restrict__ a_s,
                       const float* __restrict__ a_d, float* __restrict__ es,
                       float* __restrict__ ed) {
    int w = (blockIdx.x * blockDim.x + threadIdx.x) >> 5;
    int lane = threadIdx.x & 31;
    if (w >= NN * NHEADS) return;
    int hd = w % NHEADS;
    const float* hp = h + (size_t)w * O;
    float s = 0.f, d = 0.f;
    for (int k = lane; k < O; k += 32) {
        float v = hp[k];
        s += v * a_s[hd * O + k];
        d += v * a_d[hd * O + k];
    }
#pragma unroll
    for (int off = 16; off; off >>= 1) {
        s += __shfl_xor_sync(0xffffffffu, s, off);
        d += __shfl_xor_sync(0xffffffffu, d, off);
    }
    if (lane == 0) { es[w] = s; ed[w] = d; }
}

__device__ __forceinline__ float lrelu02(float v) { return v > 0.f ? v : 0.2f * v; }

// ---------------- fused attention (eetab in smem, logit+softmax+gather) ----
__global__ void attn_k(const __half* __restrict__ H, const float* __restrict__ es,
                       const float* __restrict__ ed, const float* __restrict__ rel,
                       const float* __restrict__ ae, const int* __restrict__ src,
                       const int* __restrict__ etype, const int* __restrict__ edist,
                       const int* __restrict__ rowptr, const int* __restrict__ eids,
                       float4* __restrict__ alpha, const float* __restrict__ b,
                       const float* __restrict__ resid, float* __restrict__ out) {
    __shared__ __align__(16) float eetab[NREL * NHEADS];
    int tid = threadIdx.x;
    if (tid < NREL * NHEADS) {
        int r = tid >> 2, hd = tid & 3;
        eetab[tid] = rel[r * 2] * ae[hd * 2] + rel[r * 2 + 1] * ae[hd * 2 + 1];
    }
    __syncthreads();

    int n = (blockIdx.x * blockDim.x + tid) >> 5;
    int lane = tid & 31;
    if (n >= NN) return;
    int beg = rowptr[n], end = rowptr[n + 1];
    float4 edn = *(const float4*)(ed + n * 4);

    // pass 1: logits + max
    float4 m = make_float4(-3.4e38f, -3.4e38f, -3.4e38f, -3.4e38f);
    for (int i = beg + lane; i < end; i += 32) {
        int e = eids[i];
        int s = clampi(src[e], 0, NN - 1);
        int t = clampi(etype[e], 0, NREL - 1);
        float4 a = *(const float4*)(es + s * 4);
        float4 c = *(const float4*)(eetab + t * 4);
        float4 lg;
        lg.x = lrelu02(a.x + edn.x + c.x);
        lg.y = lrelu02(a.y + edn.y + c.y);
        lg.z = lrelu02(a.z + edn.z + c.z);
        lg.w = lrelu02(a.w + edn.w + c.w);
        alpha[i] = lg;
        m.x = fmaxf(m.x, lg.x); m.y = fmaxf(m.y, lg.y);
        m.z = fmaxf(m.z, lg.z); m.w = fmaxf(m.w, lg.w);
    }
#pragma unroll
    for (int off = 16; off; off >>= 1) {
        m.x = fmaxf(m.x, __shfl_xor_sync(0xffffffffu, m.x, off));
        m.y = fmaxf(m.y, __shfl_xor_sync(0xffffffffu, m.y, off));
        m.z = fmaxf(m.z, __shfl_xor_sync(0xffffffffu, m.z, off));
        m.w = fmaxf(m.w, __shfl_xor_sync(0xffffffffu, m.w, off));
    }
    // pass 2: exp + den
    float4 den = make_float4(0.f, 0.f, 0.f, 0.f);
    for (int i = beg + lane; i < end; i += 32) {
        float4 v = alpha[i];
        float4 ex;
        ex.x = __expf(v.x - m.x); ex.y = __expf(v.y - m.y);
        ex.z = __expf(v.z - m.z); ex.w = __expf(v.w - m.w);
        alpha[i] = ex;
        den.x += ex.x; den.y += ex.y; den.z += ex.z; den.w += ex.w;
    }
#pragma unroll
    for (int off = 16; off; off >>= 1) {
        den.x += __shfl_xor_sync(0xffffffffu, den.x, off);
        den.y += __shfl_xor_sync(0xffffffffu, den.y, off);
        den.z += __shfl_xor_sync(0xffffffffu, den.z, off);
        den.w += __shfl_xor_sync(0xffffffffu, den.w, off);
    }
    float4 inv;
    inv.x = 1.0f / (den.x + 1e-16f); inv.y = 1.0f / (den.y + 1e-16f);
    inv.z = 1.0f / (den.z + 1e-16f); inv.w = 1.0f / (den.w + 1e-16f);
    __syncwarp();

    // pass 3: gather (half2 coalesced) + head-mean + bias + residual
    float2 accA[NHEADS], accB[NHEADS];
#pragma unroll
    for (int q = 0; q < NHEADS; q++) {
        accA[q] = make_float2(0.f, 0.f);
        accB[q] = make_float2(0.f, 0.f);
    }
    for (int i = beg; i < end; i++) {
        int e = eids[i];
        int s = clampi(src[e], 0, NN - 1);
        float4 a = alpha[i];
        float w = 1.0f / (1.0f + (float)edist[e]);
        float aw[4] = {a.x * inv.x * w, a.y * inv.y * w, a.z * inv.z * w,
                       a.w * inv.w * w};
        const __half2* hs2 = (const __half2*)(H + (size_t)s * 512);
#pragma unroll
        for (int q = 0; q < NHEADS; q++) {
            float2 fa = __half22float2(hs2[q * 64 + lane]);
            float2 fb = __half22float2(hs2[q * 64 + 32 + lane]);
            accA[q].x += aw[q] * fa.x; accA[q].y += aw[q] * fa.y;
            accB[q].x += aw[q] * fb.x; accB[q].y += aw[q] * fb.y;
        }
    }
    {
        int oA = 2 * lane, oB = 64 + 2 * lane;
        float2 bA = *(const float2*)(b + oA);
        float2 bB = *(const float2*)(b + oB);
        float2 vA, vB;
        vA.x = 0.25f * (accA[0].x + accA[1].x + accA[2].x + accA[3].x) + bA.x;
        vA.y = 0.25f * (accA[0].y + accA[1].y + accA[2].y + accA[3].y) + bA.y;
        vB.x = 0.25f * (accB[0].x + accB[1].x + accB[2].x + accB[3].x) + bB.x;
        vB.y = 0.25f * (accB[0].y + accB[1].y + accB[2].y + accB[3].y) + bB.y;
        if (resid) {
            float2 rA = *(const float2*)(resid + (size_t)n * 128 + oA);
            float2 rB = *(const float2*)(resid + (size_t)n * 128 + oB);
            vA.x += rA.x; vA.y += rA.y; vB.x += rB.x; vB.y += rB.y;
        }
        *(float2*)(out + (size_t)n * 128 + oA) = vA;
        *(float2*)(out + (size_t)n * 128 + oB) = vB;
    }
}

// ---------------- final-layer softmax (standalone, eetab in smem) ----------
__global__ void lsm_k(const float* __restrict__ es, const float* __restrict__ ed,
                      const float* __restrict__ rel, const float* __restrict__ ae,
                      const int* __restrict__ src, const int* __restrict__ etype,
                      const int* __restrict__ edist, const int* __restrict__ rowptr,
                      const int* __restrict__ eids, float4* __restrict__ alpha) {
    __shared__ __align__(16) float eetab[NREL * NHEADS];
    int tid = threadIdx.x;
    if (tid < NREL * NHEADS) {
        int r = tid >> 2, hd = tid & 3;
        eetab[tid] = rel[r * 2] * ae[hd * 2] + rel[r * 2 + 1] * ae[hd * 2 + 1];
    }
    __syncthreads();

    int n = (blockIdx.x * blockDim.x + tid) >> 5;
    int lane = tid & 31;
    if (n >= NN) return;
    int beg = rowptr[n], end = rowptr[n + 1];
    float4 edn = *(const float4*)(ed + n * 4);

    float4 m = make_float4(-3.4e38f, -3.4e38f, -3.4e38f, -3.4e38f);
    for (int i = beg + lane; i < end; i += 32) {
        int e = eids[i];
        int s = clampi(src[e], 0, NN - 1);
        int t = clampi(etype[e], 0, NREL - 1);
        float4 a = *(const float4*)(es + s * 4);
        float4 c = *(const float4*)(eetab + t * 4);
        float4 lg;
        lg.x = lrelu02(a.x + edn.x + c.x);
        lg.y = lrelu02(a.y + edn.y + c.y);
        lg.z = lrelu02(a.z + edn.z + c.z);
        lg.w = lrelu02(a.w + edn.w + c.w);
        alpha[i] = lg;
        m.x = fmaxf(m.x, lg.x); m.y = fmaxf(m.y, lg.y);
        m.z = fmaxf(m.z, lg.z); m.w = fmaxf(m.w, lg.w);
    }
#pragma unroll
    for (int off = 16; off; off >>= 1) {
        m.x = fmaxf(m.x, __shfl_xor_sync(0xffffffffu, m.x, off));
        m.y = fmaxf(m.y, __shfl_xor_sync(0xffffffffu, m.y, off));
        m.z = fmaxf(m.z, __shfl_xor_sync(0xffffffffu, m.z, off));
        m.w = fmaxf(m.w, __shfl_xor_sync(0xffffffffu, m.w, off));
    }
    float4 den = make_float4(0.f, 0.f, 0.f, 0.f);
    for (int i = beg + lane; i < end; i += 32) {
        float4 v = alpha[i];
        float4 ex;
        ex.x = __expf(v.x - m.x); ex.y = __expf(v.y - m.y);
        ex.z = __expf(v.z - m.z); ex.w = __expf(v.w - m.w);
        alpha[i] = ex;
        den.x += ex.x; den.y += ex.y; den.z += ex.z; den.w += ex.w;
    }
#pragma unroll
    for (int off = 16; off; off >>= 1) {
        den.x += __shfl_xor_sync(0xffffffffu, den.x, off);
        den.y += __shfl_xor_sync(0xffffffffu, den.y, off);
        den.z += __shfl_xor_sync(0xffffffffu, den.z, off);
        den.w += __shfl_xor_sync(0xffffffffu, den.w, off);
    }
    float4 inv;
    inv.x = 1.0f / (den.x + 1e-16f); inv.y = 1.0f / (den.y + 1e-16f);
    inv.z = 1.0f / (den.z + 1e-16f); inv.w = 1.0f / (den.w + 1e-16f);
    for (int i = beg + lane; i < end; i += 32) {
        float4 v = alpha[i];
        float w = 1.0f / (1.0f + (float)edist[eids[i]]);
        v.x *= inv.x * w; v.y *= inv.y * w;
        v.z *= inv.z * w; v.w *= inv.w * w;
        alpha[i] = v;
    }
}

// ---------------- final layer gather (O=9) + combine + lrelu ---------------
__global__ void aggF_k(const float* __restrict__ h, const float4* __restrict__ alpha4,
                       const int* __restrict__ src, const int* __restrict__ eids,
                       const int* __restrict__ rowptr, const float* __restrict__ b,
                       float* __restrict__ out) {
    int n = (blockIdx.x * blockDim.x + threadIdx.x) >> 5;
    int lane = threadIdx.x & 31;
    if (n >= NN) return;
    int beg = rowptr[n], end = rowptr[n + 1];
    float acc[NHEADS] = {0.f, 0.f, 0.f, 0.f};
    for (int i = beg; i < end; i++) {
        int e = eids[i];
        int s = clampi(src[e], 0, NN - 1);
        float4 a = alpha4[i];
        float aw[4] = {a.x, a.y, a.z, a.w};
        if (lane < NCLS) {
            const float* hs = h + (size_t)s * (NHEADS * NCLS);
#pragma unroll
            for (int q = 0; q < NHEADS; q++) acc[q] += aw[q] * hs[q * NCLS + lane];
        }
    }
    if (lane < NCLS) {
        float v = 0.25f * (acc[0] + acc[1] + acc[2] + acc[3]) + b[lane];
        out[(size_t)n * NCLS + lane] = v > 0.f ? v : 0.1f * v;
    }
}

// ---------------- batch norm -----------------------------------------------
__global__ void bn_stats_k(const float* __restrict__ x, float* __restrict__ sum,
                           float* __restrict__ sumsq) {
    int t = threadIdx.x;
    int rows_per = (NN + gridDim.x - 1) / gridDim.x;
    int r0 = blockIdx.x * rows_per;
    int r1 = min(r0 + rows_per, NN);
    float s = 0.f, q = 0.f;
    for (int r = r0; r < r1; r++) {
        float v = x[(size_t)r * HID + t];
        s += v;
        q += v * v;
    }
    atomicAdd(&sum[t], s);
    atomicAdd(&sumsq[t], q);
}

// bn + lrelu + optional fp16 hi/lo split
__global__ void bn_apply_k(const float* __restrict__ x, const float* __restrict__ sum,
                           const float* __restrict__ sumsq, const float* __restrict__ g,
                           const float* __restrict__ b, float* __restrict__ out,
                           __half* __restrict__ A2) {
    int i = blockIdx.x * blockDim.x + threadIdx.x;
    if (i >= NN * HID) return;
    int o = i & 127;
    int n = i >> 7;
    float mu = sum[o] * (1.0f / NN);
    float var = sumsq[o] * (1.0f / NN) - mu * mu;
    float v = (x[i] - mu) * rsqrtf(var + 1e-5f) * g[o] + b[o];
    v = v > 0.f ? v : 0.1f * v;
    out[i] = v;
    if (A2) {
        __half h = __float2half_rn(v);
        __half l = __float2half_rn(v - __half2float(h));
        size_t base = (size_t)n * 256;
        A2[base + o] = h;
        A2[base + 128 + o] = l;
    }
}

// ---------------- host orchestration ---------------------------------------
struct Bufs {
    float *h_buf, *tmp, *xb, *hin, *es, *ed, *Wb, *bsum, *bsq;
    __half *Hh, *A2, *B1;
    int *cnt, *rowptr, *fill, *eids;
};

extern "C" void kernel_launch(void* const* d_in, const int* in_sizes, int n_in,
                              void* d_out, int out_size) {
    const float* x = (const float*)d_in[0];
    const int* ei = (const int*)d_in[1];
    const int* etype = (const int*)d_in[2];
    const int* edist = (const int*)d_in[3];
    const float* W0 = (const float*)d_in[4];
    const float* asrc0 = (const float*)d_in[5];
    const float* adst0 = (const float*)d_in[6];
    const float* aedge0 = (const float*)d_in[7];
    const float* b0 = (const float*)d_in[8];
    const float* rel0 = (const float*)d_in[9];
    const float* Wm = (const float*)d_in[10];
    const float* asrcm = (const float*)d_in[11];
    const float* adstm = (const float*)d_in[12];
    const float* aedgem = (const float*)d_in[13];
    const float* bm = (const float*)d_in[14];
    const float* relm = (const float*)d_in[15];
    const float* WL = (const float*)d_in[16];
    const float* asrcL = (const float*)d_in[17];
    const float* adstL = (const float*)d_in[18];
    const float* aedgeL = (const float*)d_in[19];
    const float* bL = (const float*)d_in[20];
    const float* relL = (const float*)d_in[21];
    const float* bn_g = (const float*)d_in[22];
    const float* bn_b = (const float*)d_in[23];

    static bool attr_set = false;
    if (!attr_set) {
        cudaFuncSetAttribute(mma_gemm_k, cudaFuncAttributeMaxDynamicSharedMemorySize,
                             NSTAGE * STAGEB);
        attr_set = true;
    }

    Bufs B;
    cudaGetSymbolAddress((void**)&B.h_buf, g_h);
    cudaGetSymbolAddress((void**)&B.Hh, g_Hh);
    cudaGetSymbolAddress((void**)&B.tmp, g_tmp);
    cudaGetSymbolAddress((void**)&B.xb, g_x);
    cudaGetSymbolAddress((void**)&B.hin, g_hin);
    cudaGetSymbolAddress((void**)&B.es, g_es);
    cudaGetSymbolAddress((void**)&B.ed, g_ed);
    cudaGetSymbolAddress((void**)&B.Wb, g_W);
    cudaGetSymbolAddress((void**)&B.bsum, g_bsum);
    cudaGetSymbolAddress((void**)&B.bsq, g_bsq);
    cudaGetSymbolAddress((void**)&B.A2, g_A2);
    cudaGetSymbolAddress((void**)&B.B1, g_B1);
    cudaGetSymbolAddress((void**)&B.cnt, g_cnt);
    cudaGetSymbolAddress((void**)&B.rowptr, g_rowptr);
    cudaGetSymbolAddress((void**)&B.fill, g_fill);
    cudaGetSymbolAddress((void**)&B.eids, g_eids);

    const int* src = ei;
    const int* dst = ei + NE;
    float4* lg4 = (float4*)B.tmp;
    dim3 ggrid(4, (NN + 127) / 128);
    int attn_blocks = (NN * 32 + 255) / 256;

    // layer-0: convA(1), convB(2), init(3), mma(4 = profiled slot)
    int na = NN * FIN;
    convA_k<<<(na + 255) / 256, 256>>>(x, B.A2, NN, FIN);
    int nb = NHEADS * FIN * HID;
    convB_k<<<(nb + 255) / 256, 256>>>(W0, B.B1, FIN, HID);
    init_zero_k<<<(NN + 255) / 256, 256>>>(B.cnt, B.bsum, B.bsq);
    mma_gemm_k<<<ggrid, 256, NSTAGE * STAGEB>>>(B.A2, B.B1, asrc0, adst0, B.Hh,
                                                B.es, B.ed, NN, FIN);
    count_k<<<(NE + 255) / 256, 256>>>(dst, B.cnt);
    scan_k<<<1, 1024>>>(B.cnt, B.rowptr, B.fill);
    scatter_k<<<(NE + 255) / 256, 256>>>(dst, B.fill, B.eids);
    attn_k<<<attn_blocks, 256>>>(B.Hh, B.es, B.ed, rel0, aedge0, src, etype,
                                 edist, B.rowptr, B.eids, lg4, b0, nullptr, B.xb);

    int nb128 = (NN * HID + 255) / 256;

    for (int i = 0; i < 3; i++) {
        bn_stats_k<<<200, 128>>>(B.xb, B.bsum + i * HID, B.bsq + i * HID);
        bn_apply_k<<<nb128, 256>>>(B.xb, B.bsum + i * HID, B.bsq + i * HID,
                                   bn_g + i * HID, bn_b + i * HID, B.hin, B.A2);
        int nbm = NHEADS * HID * HID;
        convB_k<<<(nbm + 255) / 256, 256>>>(Wm + (size_t)i * NHEADS * HID * HID,
                                            B.B1, HID, HID);
        mma_gemm_k<<<ggrid, 256, NSTAGE * STAGEB>>>(
            B.A2, B.B1, asrcm + i * NHEADS * HID, adstm + i * NHEADS * HID,
            B.Hh, B.es, B.ed, NN, HID);
        attn_k<<<attn_blocks, 256>>>(B.Hh, B.es, B.ed, relm + i * NREL * 2,
                                     aedgem + i * NHEADS * 2, src, etype, edist,
                                     B.rowptr, B.eids, lg4, bm + i * HID, B.hin,
                                     B.xb);
    }

    // final layer
    bn_stats_k<<<200, 128>>>(B.xb, B.bsum + 3 * HID, B.bsq + 3 * HID);
    bn_apply_k<<<nb128, 256>>>(B.xb, B.bsum + 3 * HID, B.bsq + 3 * HID,
                               bn_g + 3 * HID, bn_b + 3 * HID, B.hin,
                               (__half*)nullptr);
    {
        int tot = NHEADS * HID * NCLS;
        reorder_k<<<(tot + 255) / 256, 256>>>(WL, B.Wb, HID, NCLS);
        int Ncols = NHEADS * NCLS;
        dim3 grid((Ncols + BN - 1) / BN, (NN + BM - 1) / BM);
        sgemm_k<<<grid, 256>>>(B.hin, B.Wb, B.h_buf, NN, Ncols, HID);
        int warps = NN * NHEADS;
        int blocks = (warps * 32 + 255) / 256;
        esed_k<NCLS><<<blocks, 256>>>(B.h_buf, asrcL, adstL, B.es, B.ed);
        lsm_k<<<attn_blocks, 256>>>(B.es, B.ed, relL, aedgeL, src, etype, edist,
                                    B.rowptr, B.eids, lg4);
        aggF_k<<<attn_blocks, 256>>>(B.h_buf, lg4, src, B.eids, B.rowptr, bL,
                                     (float*)d_out);
    }
}